// round 1
// baseline (speedup 1.0000x reference)
#include <cuda_runtime.h>
#include <math.h>

// Problem constants
#define BB 16
#define SS 256
#define DD 1024
#define HP 16
#define DK 64
#define HC 8
#define SK 32
#define EPSV 1e-6f

// ---------------- scratch buffers (static device memory; no allocation) ----------------
__device__ float g_xp[BB*SS*DD];          // LN_p output            [B,S,D]
__device__ float g_qkv[3*BB*SS*DD];       // pos qkv                [3,B,S,D]
__device__ float g_xp2[BB*SS*DD];         // pos attn out           [B,S,D]
__device__ float g_xt[BB*DD*SS];          // LN_c out, transposed   [B,D,S]
__device__ float g_qkvc[3*BB*DD*SS];      // channel qkv            [3,B,D,S]
__device__ float g_xcatt[BB*DD*SS];       // channel attn out       [B,D,S]
__device__ float g_proj[BB*DD*SS];        // final proj (pre-transpose) [B,D,S]

// ---------------- LayerNorm over channels (ddof=1, eps added to std) ----------------
__global__ void __launch_bounds__(256) ln_p_kernel(const float* __restrict__ x,
                                                   const float* __restrict__ ap,
                                                   const float* __restrict__ bp,
                                                   float* __restrict__ xp)
{
    long row = blockIdx.x;                 // b*S+s, 4096 rows
    const float* xr = x + row * DD;
    int tid = threadIdx.x;
    float s = 0.f, s2 = 0.f;
    #pragma unroll
    for (int i = tid; i < DD; i += 256) { float v = xr[i]; s += v; s2 += v*v; }
    __shared__ float rs[8], rs2[8];
    #pragma unroll
    for (int o = 16; o; o >>= 1) { s += __shfl_xor_sync(~0u, s, o); s2 += __shfl_xor_sync(~0u, s2, o); }
    if ((tid & 31) == 0) { rs[tid>>5] = s; rs2[tid>>5] = s2; }
    __syncthreads();
    s = 0.f; s2 = 0.f;
    #pragma unroll
    for (int w = 0; w < 8; w++) { s += rs[w]; s2 += rs2[w]; }
    float mean = s * (1.f / DD);
    float var  = (s2 - s * mean) * (1.f / (DD - 1));
    float inv  = 1.f / (sqrtf(var) + EPSV);
    #pragma unroll
    for (int i = tid; i < DD; i += 256) {
        float v = xr[i];
        xp[row * DD + i] = ap[i] * (v - mean) * inv + bp[i];
    }
}

// ---------------- generic batched SGEMM: C = A*B + bias, row-major ----------------
// BM=BN=128, BK=8, 256 threads, 8x8 per thread
__global__ void __launch_bounds__(256) sgemm128(const float* __restrict__ A,
                                                const float* __restrict__ Bm,
                                                const float* __restrict__ bias,
                                                float* __restrict__ C,
                                                int M, int N, int K,
                                                long aBatch, long bBatch, long biasBatch, long cBatch)
{
    int bz = blockIdx.z;
    A    += (long)bz * aBatch;
    Bm   += (long)bz * bBatch;
    bias += (long)bz * biasBatch;
    C    += (long)bz * cBatch;

    __shared__ float As[8][128];
    __shared__ float Bs[8][128];
    int tid = threadIdx.x;
    int row0 = blockIdx.y * 128, col0 = blockIdx.x * 128;
    int tx = tid & 15, ty = tid >> 4;

    float acc[8][8];
    #pragma unroll
    for (int i = 0; i < 8; i++)
        #pragma unroll
        for (int j = 0; j < 8; j++) acc[i][j] = 0.f;

    int aRow  = tid >> 1;            // 0..127
    int aK4   = (tid & 1) * 4;       // 0 or 4
    int bRow  = tid >> 5;            // 0..7
    int bCol4 = (tid & 31) * 4;

    for (int k0 = 0; k0 < K; k0 += 8) {
        float4 a4 = *(const float4*)&A[(long)(row0 + aRow) * K + k0 + aK4];
        float4 b4 = *(const float4*)&Bm[(long)(k0 + bRow) * N + col0 + bCol4];
        As[aK4+0][aRow] = a4.x; As[aK4+1][aRow] = a4.y;
        As[aK4+2][aRow] = a4.z; As[aK4+3][aRow] = a4.w;
        *(float4*)&Bs[bRow][bCol4] = b4;
        __syncthreads();
        #pragma unroll
        for (int kk = 0; kk < 8; kk++) {
            float4 a0 = *(const float4*)&As[kk][ty*8];
            float4 a1 = *(const float4*)&As[kk][ty*8+4];
            float4 b0 = *(const float4*)&Bs[kk][tx*8];
            float4 b1 = *(const float4*)&Bs[kk][tx*8+4];
            float av[8] = {a0.x,a0.y,a0.z,a0.w,a1.x,a1.y,a1.z,a1.w};
            float bv[8] = {b0.x,b0.y,b0.z,b0.w,b1.x,b1.y,b1.z,b1.w};
            #pragma unroll
            for (int i = 0; i < 8; i++)
                #pragma unroll
                for (int j = 0; j < 8; j++) acc[i][j] += av[i]*bv[j];
        }
        __syncthreads();
    }
    #pragma unroll
    for (int i = 0; i < 8; i++) {
        long r = row0 + ty*8 + i;
        int c0 = col0 + tx*8;
        float4 o0 = make_float4(acc[i][0]+bias[c0+0], acc[i][1]+bias[c0+1],
                                acc[i][2]+bias[c0+2], acc[i][3]+bias[c0+3]);
        float4 o1 = make_float4(acc[i][4]+bias[c0+4], acc[i][5]+bias[c0+5],
                                acc[i][6]+bias[c0+6], acc[i][7]+bias[c0+7]);
        *(float4*)&C[r * N + c0]     = o0;
        *(float4*)&C[r * N + c0 + 4] = o1;
    }
}

// ---------------- positional attention: one block per (b,h), K/V fully in smem ----------------
// smem layout (floats): Ks[256*65], Vs[256*65], qs[256], sc[1024], red[32], red2[32], redpv[1024]
#define POS_SMEM_FLOATS (256*65*2 + 256 + 1024 + 32 + 32 + 1024)
__global__ void __launch_bounds__(256) pos_attn(const float* __restrict__ qkv,
                                                float* __restrict__ out)
{
    int bh = blockIdx.x; int b = bh >> 4, h = bh & 15;
    extern __shared__ float sm[];
    float* Ks   = sm;
    float* Vs   = Ks + 256*65;
    float* qs   = Vs + 256*65;
    float* sc   = qs + 256;
    float* red  = sc + 1024;
    float* red2 = red + 32;
    float* redpv= red2 + 32;
    int tid = threadIdx.x;
    int lane = tid & 31, w = tid >> 5;

    const float* Qg = qkv + ((long)b * SS) * DD + h * DK;
    const float* Kg = Qg + (long)BB*SS*DD;
    const float* Vg = Qg + 2L*BB*SS*DD;

    for (int idx = tid; idx < 256*64; idx += 256) {
        int s = idx >> 6, dk = idx & 63;
        Ks[s*65+dk] = Kg[(long)s * DD + dk];
        Vs[s*65+dk] = Vg[(long)s * DD + dk];
    }
    __syncthreads();

    for (int t0 = 0; t0 < SS; t0 += 4) {
        {
            int i = tid >> 6, dk = tid & 63;
            qs[tid] = Qg[(long)(t0 + i) * DD + dk];
        }
        __syncthreads();
        float a0=0.f, a1=0.f, a2=0.f, a3=0.f;
        #pragma unroll 8
        for (int dk = 0; dk < 64; dk++) {
            float kv = Ks[tid*65+dk];
            a0 += kv * qs[dk];
            a1 += kv * qs[64+dk];
            a2 += kv * qs[128+dk];
            a3 += kv * qs[192+dk];
        }
        a0 *= 0.125f; a1 *= 0.125f; a2 *= 0.125f; a3 *= 0.125f;
        float m0=a0,m1=a1,m2=a2,m3=a3;
        #pragma unroll
        for (int o = 16; o; o >>= 1) {
            m0 = fmaxf(m0, __shfl_xor_sync(~0u,m0,o));
            m1 = fmaxf(m1, __shfl_xor_sync(~0u,m1,o));
            m2 = fmaxf(m2, __shfl_xor_sync(~0u,m2,o));
            m3 = fmaxf(m3, __shfl_xor_sync(~0u,m3,o));
        }
        if (lane == 0) { red[w]=m0; red[8+w]=m1; red[16+w]=m2; red[24+w]=m3; }
        __syncthreads();
        float mm0=red[0],mm1=red[8],mm2=red[16],mm3=red[24];
        #pragma unroll
        for (int ww = 1; ww < 8; ww++) {
            mm0=fmaxf(mm0,red[ww]); mm1=fmaxf(mm1,red[8+ww]);
            mm2=fmaxf(mm2,red[16+ww]); mm3=fmaxf(mm3,red[24+ww]);
        }
        float p0=__expf(a0-mm0), p1=__expf(a1-mm1), p2=__expf(a2-mm2), p3=__expf(a3-mm3);
        sc[tid]=p0; sc[256+tid]=p1; sc[512+tid]=p2; sc[768+tid]=p3;
        float s0=p0,s1=p1,s2=p2,s3=p3;
        #pragma unroll
        for (int o = 16; o; o >>= 1) {
            s0 += __shfl_xor_sync(~0u,s0,o); s1 += __shfl_xor_sync(~0u,s1,o);
            s2 += __shfl_xor_sync(~0u,s2,o); s3 += __shfl_xor_sync(~0u,s3,o);
        }
        if (lane == 0) { red2[w]=s0; red2[8+w]=s1; red2[16+w]=s2; red2[24+w]=s3; }
        __syncthreads();
        float l0=0.f,l1=0.f,l2=0.f,l3=0.f;
        #pragma unroll
        for (int ww = 0; ww < 8; ww++) {
            l0+=red2[ww]; l1+=red2[8+ww]; l2+=red2[16+ww]; l3+=red2[24+ww];
        }
        // PV: thread (g, dk) sums s in [g*64, g*64+64)
        int g = tid >> 6, dk = tid & 63;
        float pv0=0.f,pv1=0.f,pv2=0.f,pv3=0.f;
        int sB = g * 64;
        #pragma unroll 8
        for (int s = sB; s < sB + 64; s++) {
            float v = Vs[s*65+dk];
            pv0 += sc[s]*v; pv1 += sc[256+s]*v; pv2 += sc[512+s]*v; pv3 += sc[768+s]*v;
        }
        redpv[(0*4+g)*64+dk]=pv0; redpv[(1*4+g)*64+dk]=pv1;
        redpv[(2*4+g)*64+dk]=pv2; redpv[(3*4+g)*64+dk]=pv3;
        __syncthreads();
        {
            int i = tid >> 6, dk2 = tid & 63;
            float r = redpv[(i*4+0)*64+dk2] + redpv[(i*4+1)*64+dk2]
                    + redpv[(i*4+2)*64+dk2] + redpv[(i*4+3)*64+dk2];
            float li = (i==0)?l0:((i==1)?l1:((i==2)?l2:l3));
            out[((long)(b*SS) + t0 + i) * DD + h*DK + dk2] = r / li;
        }
        __syncthreads();
    }
}

// ---------------- LayerNorm over sequence + transpose to [B,D,S] ----------------
__global__ void __launch_bounds__(256) ln_c_kernel(const float* __restrict__ xin,
                                                   const float* __restrict__ ac,
                                                   const float* __restrict__ bc,
                                                   float* __restrict__ xt)
{
    int b = blockIdx.y;
    int d = blockIdx.x * 256 + threadIdx.x;
    const float* base = xin + (long)b * SS * DD + d;
    float s = 0.f, s2 = 0.f;
    #pragma unroll 4
    for (int si = 0; si < SS; si++) { float v = base[(long)si * DD]; s += v; s2 += v*v; }
    float mean = s * (1.f / SS);
    float var  = (s2 - s * mean) * (1.f / (SS - 1));
    float inv  = 1.f / (sqrtf(var) + EPSV);
    float* dst = xt + ((long)b * DD + d) * SS;
    #pragma unroll 4
    for (int si = 0; si < SS; si++) {
        float v = base[(long)si * DD];
        dst[si] = ac[si] * (v - mean) * inv + bc[si];
    }
}

// ---------------- channel attention: flash-style, block = (tchunk, b*HC+h) ----------------
// TC=128 query tokens per block, s-tiles of 128 over 1024 tokens, head dim 32
#define CH_SMEM_FLOATS (32*132*2 + 128*36 + 128*132 + 128*3 + 256)
__global__ void __launch_bounds__(256) chan_attn(const float* __restrict__ qkvc,
                                                 float* __restrict__ xcatt)
{
    int tc = blockIdx.x;              // 0..7
    int bh = blockIdx.y; int b = bh >> 3, h = bh & 7;
    extern __shared__ float sm[];
    float* Qst  = sm;                 // [32][132] transposed, pre-scaled
    float* Kst  = Qst + 32*132;       // [32][132] transposed
    float* Vs   = Kst + 32*132;       // [128][36]
    float* Ps   = Vs + 128*36;        // [128][132]
    float* m_sh = Ps + 128*132;       // [128]
    float* l_sh = m_sh + 128;
    float* al_sh= l_sh + 128;
    float* redl = al_sh + 128;        // [256]
    int tid = threadIdx.x;
    int ty = tid >> 4, tx = tid & 15;          // scores: rows ty*8.., cols tx*8..
    int pg = tid >> 3, pskg = tid & 7;         // PV: t rows pg*4.., sk cols pskg*4..

    const float scale = 0.1767766952966369f;   // 1/sqrt(32)
    const long qBase = ((long)b * DD) * SS + (long)h * SK;
    const long nStride = (long)BB * DD * SS;

    for (int idx = tid; idx < 128*32; idx += 256) {
        int r = idx >> 5, k = idx & 31;
        float v = qkvc[qBase + (long)(tc*128 + r) * SS + k];
        Qst[k*132 + r] = v * scale;
    }
    if (tid < 128) { m_sh[tid] = -1e30f; l_sh[tid] = 0.f; }

    float acc[4][4];
    #pragma unroll
    for (int i = 0; i < 4; i++)
        #pragma unroll
        for (int j = 0; j < 4; j++) acc[i][j] = 0.f;

    for (int st = 0; st < 8; st++) {
        __syncthreads();   // protect Kst/Vs/Ps reuse
        for (int idx = tid; idx < 128*32; idx += 256) {
            int r = idx >> 5, k = idx & 31;
            Kst[k*132 + r] = qkvc[qBase + nStride   + (long)(st*128 + r) * SS + k];
            Vs[r*36 + k]   = qkvc[qBase + 2*nStride + (long)(st*128 + r) * SS + k];
        }
        __syncthreads();
        // scores 8x8 per thread
        float s8[8][8];
        #pragma unroll
        for (int i = 0; i < 8; i++)
            #pragma unroll
            for (int j = 0; j < 8; j++) s8[i][j] = 0.f;
        #pragma unroll 4
        for (int k = 0; k < 32; k++) {
            float4 a0 = *(const float4*)(Qst + k*132 + ty*8);
            float4 a1 = *(const float4*)(Qst + k*132 + ty*8 + 4);
            float4 b0 = *(const float4*)(Kst + k*132 + tx*8);
            float4 b1 = *(const float4*)(Kst + k*132 + tx*8 + 4);
            float av[8] = {a0.x,a0.y,a0.z,a0.w,a1.x,a1.y,a1.z,a1.w};
            float bv[8] = {b0.x,b0.y,b0.z,b0.w,b1.x,b1.y,b1.z,b1.w};
            #pragma unroll
            for (int i = 0; i < 8; i++)
                #pragma unroll
                for (int j = 0; j < 8; j++) s8[i][j] += av[i]*bv[j];
        }
        #pragma unroll
        for (int i = 0; i < 8; i++) {
            *(float4*)(Ps + (ty*8+i)*132 + tx*8)     = make_float4(s8[i][0],s8[i][1],s8[i][2],s8[i][3]);
            *(float4*)(Ps + (ty*8+i)*132 + tx*8 + 4) = make_float4(s8[i][4],s8[i][5],s8[i][6],s8[i][7]);
        }
        __syncthreads();
        // row max + alpha
        if (tid < 128) {
            float rm = -1e30f;
            #pragma unroll 8
            for (int s = 0; s < 128; s++) rm = fmaxf(rm, Ps[tid*132+s]);
            float mo = m_sh[tid];
            float mn = fmaxf(mo, rm);
            float al = __expf(mo - mn);
            m_sh[tid] = mn; al_sh[tid] = al; l_sh[tid] *= al;
        }
        __syncthreads();
        // exp + partial row sums (2 threads per row)
        {
            int r = tid >> 1, sOff = (tid & 1) * 64;
            float mn = m_sh[r];
            float ssum = 0.f;
            #pragma unroll 8
            for (int s = sOff; s < sOff + 64; s++) {
                float p = __expf(Ps[r*132+s] - mn);
                Ps[r*132+s] = p;
                ssum += p;
            }
            redl[tid] = ssum;
        }
        __syncthreads();
        if (tid < 128) l_sh[tid] += redl[2*tid] + redl[2*tid+1];
        // rescale accumulators
        #pragma unroll
        for (int i = 0; i < 4; i++) {
            float al = al_sh[pg*4+i];
            #pragma unroll
            for (int j = 0; j < 4; j++) acc[i][j] *= al;
        }
        // PV accumulate
        #pragma unroll 4
        for (int s = 0; s < 128; s++) {
            float4 v4 = *(const float4*)(Vs + s*36 + pskg*4);
            float p0 = Ps[(pg*4+0)*132+s];
            float p1 = Ps[(pg*4+1)*132+s];
            float p2 = Ps[(pg*4+2)*132+s];
            float p3 = Ps[(pg*4+3)*132+s];
            acc[0][0]+=p0*v4.x; acc[0][1]+=p0*v4.y; acc[0][2]+=p0*v4.z; acc[0][3]+=p0*v4.w;
            acc[1][0]+=p1*v4.x; acc[1][1]+=p1*v4.y; acc[1][2]+=p1*v4.z; acc[1][3]+=p1*v4.w;
            acc[2][0]+=p2*v4.x; acc[2][1]+=p2*v4.y; acc[2][2]+=p2*v4.z; acc[2][3]+=p2*v4.w;
            acc[3][0]+=p3*v4.x; acc[3][1]+=p3*v4.y; acc[3][2]+=p3*v4.z; acc[3][3]+=p3*v4.w;
        }
    }
    __syncthreads();
    #pragma unroll
    for (int i = 0; i < 4; i++) {
        float inv = 1.f / l_sh[pg*4+i];
        float4 o = make_float4(acc[i][0]*inv, acc[i][1]*inv, acc[i][2]*inv, acc[i][3]*inv);
        *(float4*)&xcatt[((long)b*DD + tc*128 + pg*4 + i) * SS + h*SK + pskg*4] = o;
    }
}

// ---------------- final transpose [B,D,S] -> [B,S,D] ----------------
__global__ void transpose_out(const float* __restrict__ in, float* __restrict__ out)
{
    __shared__ float tile[32][33];
    int b = blockIdx.z;
    int d0 = blockIdx.x * 32, s0 = blockIdx.y * 32;
    int tx = threadIdx.x, ty = threadIdx.y;
    #pragma unroll
    for (int k = 0; k < 32; k += 8)
        tile[ty+k][tx] = in[((long)b*DD + d0+ty+k) * SS + s0 + tx];
    __syncthreads();
    #pragma unroll
    for (int k = 0; k < 32; k += 8)
        out[((long)b*SS + s0+ty+k) * DD + d0 + tx] = tile[tx][ty+k];
}

// ---------------- launch ----------------
extern "C" void kernel_launch(void* const* d_in, const int* in_sizes, int n_in,
                              void* d_out, int out_size)
{
    const float* x   = (const float*)d_in[0];
    const float* Wp  = (const float*)d_in[1];
    const float* bp  = (const float*)d_in[2];
    const float* Wc  = (const float*)d_in[3];
    const float* bc  = (const float*)d_in[4];
    const float* ap  = (const float*)d_in[5];
    const float* bpp = (const float*)d_in[6];
    const float* ac  = (const float*)d_in[7];
    const float* bcc = (const float*)d_in[8];
    float* out = (float*)d_out;

    void *p_xp, *p_qkv, *p_xp2, *p_xt, *p_qkvc, *p_xcatt, *p_proj;
    cudaGetSymbolAddress(&p_xp, g_xp);
    cudaGetSymbolAddress(&p_qkv, g_qkv);
    cudaGetSymbolAddress(&p_xp2, g_xp2);
    cudaGetSymbolAddress(&p_xt, g_xt);
    cudaGetSymbolAddress(&p_qkvc, g_qkvc);
    cudaGetSymbolAddress(&p_xcatt, g_xcatt);
    cudaGetSymbolAddress(&p_proj, g_proj);
    float* xp    = (float*)p_xp;
    float* qkv   = (float*)p_qkv;
    float* xp2   = (float*)p_xp2;
    float* xt    = (float*)p_xt;
    float* qkvc  = (float*)p_qkvc;
    float* xcatt = (float*)p_xcatt;
    float* proj  = (float*)p_proj;

    size_t posSmem = POS_SMEM_FLOATS * sizeof(float);
    size_t chSmem  = CH_SMEM_FLOATS * sizeof(float);
    cudaFuncSetAttribute((const void*)pos_attn,  cudaFuncAttributeMaxDynamicSharedMemorySize, (int)posSmem);
    cudaFuncSetAttribute((const void*)chan_attn, cudaFuncAttributeMaxDynamicSharedMemorySize, (int)chSmem);

    // 1. LayerNorm over D
    ln_p_kernel<<<BB*SS, 256>>>(x, ap, bpp, xp);

    // 2. positional qkv: [4096,1024] x [1024,1024] batched over 3
    sgemm128<<<dim3(DD/128, (BB*SS)/128, 3), 256>>>(
        xp, Wp, bp, qkv, BB*SS, DD, DD,
        0L, (long)DD*DD, (long)DD, (long)BB*SS*DD);

    // 3. positional attention
    pos_attn<<<BB*HP, 256, posSmem>>>(qkv, xp2);

    // 4. LayerNorm over S + transpose to [B,D,S]
    ln_c_kernel<<<dim3(DD/256, BB), 256>>>(xp2, ac, bcc, xt);

    // 5. channel qkv: [16384,256] x [256,256] batched over 3
    sgemm128<<<dim3(SS/128, (BB*DD)/128, 3), 256>>>(
        xt, Wc, bc, qkvc, BB*DD, SS, SS,
        0L, (long)SS*SS, (long)SS, (long)BB*DD*SS);

    // 6. channel attention (flash)
    chan_attn<<<dim3(8, BB*HC), 256, chSmem>>>(qkvc, xcatt);

    // 7. output projection with Wc[3], bc[3]
    sgemm128<<<dim3(SS/128, (BB*DD)/128, 1), 256>>>(
        xcatt, Wc + 3L*SS*SS, bc + 3L*SS, proj, BB*DD, SS, SS,
        0L, 0L, 0L, 0L);

    // 8. transpose [B,D,S] -> [B,S,D]
    transpose_out<<<dim3(DD/32, SS/32, BB), dim3(32, 8)>>>(proj, out);
}

// round 2
// speedup vs baseline: 1.4630x; 1.4630x over previous
#include <cuda_runtime.h>
#include <math.h>
#include <stdint.h>

// Problem constants
#define BB 16
#define SS 256
#define DD 1024
#define HP 16
#define DK 64
#define HC 8
#define SK 32
#define EPSV 1e-6f

// ---------------- scratch buffers (static device memory; no allocation) ----------------
__device__ float g_xp[BB*SS*DD];          // LN_p output (tf32-rounded) [B,S,D]
__device__ float g_qkv[3*BB*SS*DD];       // pos qkv                [3,B,S,D]
__device__ float g_xp2[BB*SS*DD];         // pos attn out           [B,S,D]
__device__ float g_xt[BB*DD*SS];          // LN_c out, transposed (tf32-rounded) [B,D,S]
__device__ float g_qkvc[3*BB*DD*SS];      // channel qkv            [3,B,D,S]
__device__ float g_xcatt[BB*DD*SS];       // channel attn out (tf32-rounded) [B,D,S]
__device__ float g_proj[BB*DD*SS];        // final proj (pre-transpose) [B,D,S]
__device__ float g_Wp32[3*DD*DD];         // tf32-rounded Wp
__device__ float g_Wc32[4*SS*SS];         // tf32-rounded Wc

// ---------------- helpers ----------------
__device__ __forceinline__ float rtf32(float x) {
    unsigned u;
    asm("cvt.rna.tf32.f32 %0, %1;" : "=r"(u) : "f"(x));
    return __uint_as_float(u);
}

__device__ __forceinline__ void cp_async16(uint32_t smem, const void* g) {
    asm volatile("cp.async.cg.shared.global [%0], [%1], 16;" :: "r"(smem), "l"(g));
}

__device__ __forceinline__ void mma_tf32(float* c, const unsigned* a, const unsigned* b) {
    asm volatile("mma.sync.aligned.m16n8k8.row.col.f32.tf32.tf32.f32 "
        "{%0,%1,%2,%3}, {%4,%5,%6,%7}, {%8,%9}, {%0,%1,%2,%3};"
        : "+f"(c[0]), "+f"(c[1]), "+f"(c[2]), "+f"(c[3])
        : "r"(a[0]), "r"(a[1]), "r"(a[2]), "r"(a[3]), "r"(b[0]), "r"(b[1]));
}

// ---------------- tf32 rounding kernel for weights ----------------
__global__ void __launch_bounds__(256) round_tf32_kernel(const float* __restrict__ in,
                                                         float* __restrict__ out, int n4)
{
    int i = blockIdx.x * 256 + threadIdx.x;
    if (i < n4) {
        float4 v = ((const float4*)in)[i];
        v.x = rtf32(v.x); v.y = rtf32(v.y); v.z = rtf32(v.z); v.w = rtf32(v.w);
        ((float4*)out)[i] = v;
    }
}

// ---------------- LayerNorm over channels (ddof=1, eps added to std) ----------------
__global__ void __launch_bounds__(256) ln_p_kernel(const float* __restrict__ x,
                                                   const float* __restrict__ ap,
                                                   const float* __restrict__ bp,
                                                   float* __restrict__ xp)
{
    long row = blockIdx.x;                 // b*S+s, 4096 rows
    const float* xr = x + row * DD;
    int tid = threadIdx.x;
    float s = 0.f, s2 = 0.f;
    #pragma unroll
    for (int i = tid; i < DD; i += 256) { float v = xr[i]; s += v; s2 += v*v; }
    __shared__ float rs[8], rs2[8];
    #pragma unroll
    for (int o = 16; o; o >>= 1) { s += __shfl_xor_sync(~0u, s, o); s2 += __shfl_xor_sync(~0u, s2, o); }
    if ((tid & 31) == 0) { rs[tid>>5] = s; rs2[tid>>5] = s2; }
    __syncthreads();
    s = 0.f; s2 = 0.f;
    #pragma unroll
    for (int w = 0; w < 8; w++) { s += rs[w]; s2 += rs2[w]; }
    float mean = s * (1.f / DD);
    float var  = (s2 - s * mean) * (1.f / (DD - 1));
    float inv  = 1.f / (sqrtf(var) + EPSV);
    #pragma unroll
    for (int i = tid; i < DD; i += 256) {
        float v = xr[i];
        xp[row * DD + i] = rtf32(ap[i] * (v - mean) * inv + bp[i]);
    }
}

// ---------------- tf32 tensor-core GEMM: C = A*B + bias, row-major ----------------
// BM=128, BN=128, BK=16, 256 threads (8 warps), warp tile 32x64 via m16n8k8
__global__ void __launch_bounds__(256, 2) gemm_tf32(const float* __restrict__ A,
                                                    const float* __restrict__ Bm,
                                                    const float* __restrict__ bias,
                                                    float* __restrict__ C,
                                                    int M, int N, int K,
                                                    long aB, long bB, long biasB, long cB)
{
    int bz = blockIdx.z;
    A    += (long)bz * aB;
    Bm   += (long)bz * bB;
    bias += (long)bz * biasB;
    C    += (long)bz * cB;

    __shared__ float As[2][128*20];   // [row][k] stride 20 (conflict-free frags, f4-aligned)
    __shared__ float Bs[2][16*136];   // [k][n]  stride 136 (conflict-free frags, f4-aligned)

    int tid  = threadIdx.x;
    int warp = tid >> 5, lane = tid & 31;
    int wm = warp & 3, wn = warp >> 2;
    long row0 = (long)blockIdx.y * 128;
    int  col0 = blockIdx.x * 128;

    // load mapping: A tile 128x16 (512 f4), B tile 16x128 (512 f4): 2 f4 each
    int aRow0 = tid >> 2,        aCol = (tid & 3) * 4;
    int aRow1 = (tid + 256) >> 2;
    int bRow0 = tid >> 5,        bCol = (tid & 31) * 4;
    int bRow1 = (tid + 256) >> 5;

    float acc[2][8][4];
    #pragma unroll
    for (int mi = 0; mi < 2; mi++)
        #pragma unroll
        for (int ni = 0; ni < 8; ni++)
            #pragma unroll
            for (int r = 0; r < 4; r++) acc[mi][ni][r] = 0.f;

    #define LOAD_TILE(buf, k0) do { \
        cp_async16((uint32_t)__cvta_generic_to_shared(&As[buf][aRow0*20 + aCol]), \
                   &A[(row0 + aRow0) * K + (k0) + aCol]); \
        cp_async16((uint32_t)__cvta_generic_to_shared(&As[buf][aRow1*20 + aCol]), \
                   &A[(row0 + aRow1) * K + (k0) + aCol]); \
        cp_async16((uint32_t)__cvta_generic_to_shared(&Bs[buf][bRow0*136 + bCol]), \
                   &Bm[(long)((k0) + bRow0) * N + col0 + bCol]); \
        cp_async16((uint32_t)__cvta_generic_to_shared(&Bs[buf][bRow1*136 + bCol]), \
                   &Bm[(long)((k0) + bRow1) * N + col0 + bCol]); \
        asm volatile("cp.async.commit_group;"); \
    } while (0)

    int KT = K >> 4;
    LOAD_TILE(0, 0);

    for (int kt = 0; kt < KT; kt++) {
        int buf = kt & 1;
        if (kt + 1 < KT) {
            LOAD_TILE(buf ^ 1, (kt + 1) << 4);
            asm volatile("cp.async.wait_group 1;" ::: "memory");
        } else {
            asm volatile("cp.async.wait_group 0;" ::: "memory");
        }
        __syncthreads();

        #pragma unroll
        for (int ks = 0; ks < 2; ks++) {
            int kb = ks * 8;
            unsigned a[2][4], b[8][2];
            #pragma unroll
            for (int mi = 0; mi < 2; mi++) {
                int r = wm * 32 + mi * 16 + (lane >> 2);
                int c = kb + (lane & 3);
                a[mi][0] = __float_as_uint(As[buf][r * 20 + c]);
                a[mi][1] = __float_as_uint(As[buf][(r + 8) * 20 + c]);
                a[mi][2] = __float_as_uint(As[buf][r * 20 + c + 4]);
                a[mi][3] = __float_as_uint(As[buf][(r + 8) * 20 + c + 4]);
            }
            #pragma unroll
            for (int ni = 0; ni < 8; ni++) {
                int n = wn * 64 + ni * 8 + (lane >> 2);
                int kr = kb + (lane & 3);
                b[ni][0] = __float_as_uint(Bs[buf][kr * 136 + n]);
                b[ni][1] = __float_as_uint(Bs[buf][(kr + 4) * 136 + n]);
            }
            #pragma unroll
            for (int mi = 0; mi < 2; mi++)
                #pragma unroll
                for (int ni = 0; ni < 8; ni++)
                    mma_tf32(acc[mi][ni], a[mi], b[ni]);
        }
        __syncthreads();
    }

    // epilogue
    #pragma unroll
    for (int mi = 0; mi < 2; mi++) {
        #pragma unroll
        for (int ni = 0; ni < 8; ni++) {
            long r = row0 + wm * 32 + mi * 16 + (lane >> 2);
            int  c = col0 + wn * 64 + ni * 8 + 2 * (lane & 3);
            float b0 = bias[c], b1 = bias[c + 1];
            float2 v0 = make_float2(acc[mi][ni][0] + b0, acc[mi][ni][1] + b1);
            float2 v1 = make_float2(acc[mi][ni][2] + b0, acc[mi][ni][3] + b1);
            *(float2*)&C[r * N + c]       = v0;
            *(float2*)&C[(r + 8) * N + c] = v1;
        }
    }
    #undef LOAD_TILE
}

// ---------------- positional attention: one block per (b,h), K/V fully in smem ----------------
#define POS_SMEM_FLOATS (256*65*2 + 256 + 1024 + 32 + 32 + 1024)
__global__ void __launch_bounds__(256) pos_attn(const float* __restrict__ qkv,
                                                float* __restrict__ out)
{
    int bh = blockIdx.x; int b = bh >> 4, h = bh & 15;
    extern __shared__ float sm[];
    float* Ks   = sm;
    float* Vs   = Ks + 256*65;
    float* qs   = Vs + 256*65;
    float* sc   = qs + 256;
    float* red  = sc + 1024;
    float* red2 = red + 32;
    float* redpv= red2 + 32;
    int tid = threadIdx.x;
    int lane = tid & 31, w = tid >> 5;

    const float* Qg = qkv + ((long)b * SS) * DD + h * DK;
    const float* Kg = Qg + (long)BB*SS*DD;
    const float* Vg = Qg + 2L*BB*SS*DD;

    for (int idx = tid; idx < 256*64; idx += 256) {
        int s = idx >> 6, dk = idx & 63;
        Ks[s*65+dk] = Kg[(long)s * DD + dk];
        Vs[s*65+dk] = Vg[(long)s * DD + dk];
    }
    __syncthreads();

    for (int t0 = 0; t0 < SS; t0 += 4) {
        {
            int i = tid >> 6, dk = tid & 63;
            qs[tid] = Qg[(long)(t0 + i) * DD + dk];
        }
        __syncthreads();
        float a0=0.f, a1=0.f, a2=0.f, a3=0.f;
        #pragma unroll 8
        for (int dk = 0; dk < 64; dk++) {
            float kv = Ks[tid*65+dk];
            a0 += kv * qs[dk];
            a1 += kv * qs[64+dk];
            a2 += kv * qs[128+dk];
            a3 += kv * qs[192+dk];
        }
        a0 *= 0.125f; a1 *= 0.125f; a2 *= 0.125f; a3 *= 0.125f;
        float m0=a0,m1=a1,m2=a2,m3=a3;
        #pragma unroll
        for (int o = 16; o; o >>= 1) {
            m0 = fmaxf(m0, __shfl_xor_sync(~0u,m0,o));
            m1 = fmaxf(m1, __shfl_xor_sync(~0u,m1,o));
            m2 = fmaxf(m2, __shfl_xor_sync(~0u,m2,o));
            m3 = fmaxf(m3, __shfl_xor_sync(~0u,m3,o));
        }
        if (lane == 0) { red[w]=m0; red[8+w]=m1; red[16+w]=m2; red[24+w]=m3; }
        __syncthreads();
        float mm0=red[0],mm1=red[8],mm2=red[16],mm3=red[24];
        #pragma unroll
        for (int ww = 1; ww < 8; ww++) {
            mm0=fmaxf(mm0,red[ww]); mm1=fmaxf(mm1,red[8+ww]);
            mm2=fmaxf(mm2,red[16+ww]); mm3=fmaxf(mm3,red[24+ww]);
        }
        float p0=__expf(a0-mm0), p1=__expf(a1-mm1), p2=__expf(a2-mm2), p3=__expf(a3-mm3);
        sc[tid]=p0; sc[256+tid]=p1; sc[512+tid]=p2; sc[768+tid]=p3;
        float s0=p0,s1=p1,s2=p2,s3=p3;
        #pragma unroll
        for (int o = 16; o; o >>= 1) {
            s0 += __shfl_xor_sync(~0u,s0,o); s1 += __shfl_xor_sync(~0u,s1,o);
            s2 += __shfl_xor_sync(~0u,s2,o); s3 += __shfl_xor_sync(~0u,s3,o);
        }
        if (lane == 0) { red2[w]=s0; red2[8+w]=s1; red2[16+w]=s2; red2[24+w]=s3; }
        __syncthreads();
        float l0=0.f,l1=0.f,l2=0.f,l3=0.f;
        #pragma unroll
        for (int ww = 0; ww < 8; ww++) {
            l0+=red2[ww]; l1+=red2[8+ww]; l2+=red2[16+ww]; l3+=red2[24+ww];
        }
        int g = tid >> 6, dk = tid & 63;
        float pv0=0.f,pv1=0.f,pv2=0.f,pv3=0.f;
        int sB = g * 64;
        #pragma unroll 8
        for (int s = sB; s < sB + 64; s++) {
            float v = Vs[s*65+dk];
            pv0 += sc[s]*v; pv1 += sc[256+s]*v; pv2 += sc[512+s]*v; pv3 += sc[768+s]*v;
        }
        redpv[(0*4+g)*64+dk]=pv0; redpv[(1*4+g)*64+dk]=pv1;
        redpv[(2*4+g)*64+dk]=pv2; redpv[(3*4+g)*64+dk]=pv3;
        __syncthreads();
        {
            int i = tid >> 6, dk2 = tid & 63;
            float r = redpv[(i*4+0)*64+dk2] + redpv[(i*4+1)*64+dk2]
                    + redpv[(i*4+2)*64+dk2] + redpv[(i*4+3)*64+dk2];
            float li = (i==0)?l0:((i==1)?l1:((i==2)?l2:l3));
            out[((long)(b*SS) + t0 + i) * DD + h*DK + dk2] = r / li;
        }
        __syncthreads();
    }
}

// ---------------- LayerNorm over sequence + transpose to [B,D,S], tiled ----------------
__global__ void __launch_bounds__(256) ln_c_kernel(const float* __restrict__ xin,
                                                   const float* __restrict__ ac,
                                                   const float* __restrict__ bcv,
                                                   float* __restrict__ xt)
{
    __shared__ float tile[32][257];
    __shared__ float red[8][32], red2[8][32];
    __shared__ float s_mean[32], s_inv[32];
    int b = blockIdx.y, d0 = blockIdx.x * 32;
    int tid = threadIdx.x, lane = tid & 31, w = tid >> 5;
    const float* base = xin + (long)b * SS * DD + d0;
    #pragma unroll 4
    for (int i = 0; i < 32; i++) {
        int s = w * 32 + i;
        tile[lane][s] = base[(long)s * DD + lane];
    }
    __syncthreads();
    {
        int d = tid & 31, ch = tid >> 5;
        float s1 = 0.f, s2 = 0.f;
        #pragma unroll
        for (int j = 0; j < 32; j++) {
            float v = tile[d][ch * 32 + j]; s1 += v; s2 += v * v;
        }
        red[ch][d] = s1; red2[ch][d] = s2;
    }
    __syncthreads();
    if (tid < 32) {
        float s1 = 0.f, s2 = 0.f;
        #pragma unroll
        for (int ch = 0; ch < 8; ch++) { s1 += red[ch][tid]; s2 += red2[ch][tid]; }
        float mean = s1 * (1.f / SS);
        float var  = (s2 - s1 * mean) * (1.f / (SS - 1));
        s_mean[tid] = mean;
        s_inv[tid]  = 1.f / (sqrtf(var) + EPSV);
    }
    __syncthreads();
    {
        int d = tid >> 3, s0 = (tid & 7) * 32;
        float mean = s_mean[d], inv = s_inv[d];
        float* dst = xt + ((long)b * DD + d0 + d) * SS;
        #pragma unroll
        for (int j = 0; j < 32; j += 4) {
            int s = s0 + j;
            float4 o;
            o.x = rtf32(ac[s+0] * (tile[d][s+0] - mean) * inv + bcv[s+0]);
            o.y = rtf32(ac[s+1] * (tile[d][s+1] - mean) * inv + bcv[s+1]);
            o.z = rtf32(ac[s+2] * (tile[d][s+2] - mean) * inv + bcv[s+2]);
            o.w = rtf32(ac[s+3] * (tile[d][s+3] - mean) * inv + bcv[s+3]);
            *(float4*)&dst[s] = o;
        }
    }
}

// ---------------- channel attention: flash-style, block = (tchunk, b*HC+h) ----------------
#define CH_SMEM_FLOATS (32*132*2 + 128*36 + 128*132 + 128*3 + 256)
__global__ void __launch_bounds__(256) chan_attn(const float* __restrict__ qkvc,
                                                 float* __restrict__ xcatt)
{
    int tc = blockIdx.x;              // 0..7
    int bh = blockIdx.y; int b = bh >> 3, h = bh & 7;
    extern __shared__ float sm[];
    float* Qst  = sm;                 // [32][132] transposed, pre-scaled
    float* Kst  = Qst + 32*132;       // [32][132] transposed
    float* Vs   = Kst + 32*132;       // [128][36]
    float* Ps   = Vs + 128*36;        // [128][132]
    float* m_sh = Ps + 128*132;       // [128]
    float* l_sh = m_sh + 128;
    float* al_sh= l_sh + 128;
    float* redl = al_sh + 128;        // [256]
    int tid = threadIdx.x;
    int ty = tid >> 4, tx = tid & 15;
    int pg = tid >> 3, pskg = tid & 7;

    const float scale = 0.1767766952966369f;   // 1/sqrt(32)
    const long qBase = ((long)b * DD) * SS + (long)h * SK;
    const long nStride = (long)BB * DD * SS;

    for (int idx = tid; idx < 128*32; idx += 256) {
        int r = idx >> 5, k = idx & 31;
        float v = qkvc[qBase + (long)(tc*128 + r) * SS + k];
        Qst[k*132 + r] = v * scale;
    }
    if (tid < 128) { m_sh[tid] = -1e30f; l_sh[tid] = 0.f; }

    float acc[4][4];
    #pragma unroll
    for (int i = 0; i < 4; i++)
        #pragma unroll
        for (int j = 0; j < 4; j++) acc[i][j] = 0.f;

    for (int st = 0; st < 8; st++) {
        __syncthreads();
        for (int idx = tid; idx < 128*32; idx += 256) {
            int r = idx >> 5, k = idx & 31;
            Kst[k*132 + r] = qkvc[qBase + nStride   + (long)(st*128 + r) * SS + k];
            Vs[r*36 + k]   = qkvc[qBase + 2*nStride + (long)(st*128 + r) * SS + k];
        }
        __syncthreads();
        float s8[8][8];
        #pragma unroll
        for (int i = 0; i < 8; i++)
            #pragma unroll
            for (int j = 0; j < 8; j++) s8[i][j] = 0.f;
        #pragma unroll 4
        for (int k = 0; k < 32; k++) {
            float4 a0 = *(const float4*)(Qst + k*132 + ty*8);
            float4 a1 = *(const float4*)(Qst + k*132 + ty*8 + 4);
            float4 b0 = *(const float4*)(Kst + k*132 + tx*8);
            float4 b1 = *(const float4*)(Kst + k*132 + tx*8 + 4);
            float av[8] = {a0.x,a0.y,a0.z,a0.w,a1.x,a1.y,a1.z,a1.w};
            float bv[8] = {b0.x,b0.y,b0.z,b0.w,b1.x,b1.y,b1.z,b1.w};
            #pragma unroll
            for (int i = 0; i < 8; i++)
                #pragma unroll
                for (int j = 0; j < 8; j++) s8[i][j] += av[i]*bv[j];
        }
        #pragma unroll
        for (int i = 0; i < 8; i++) {
            *(float4*)(Ps + (ty*8+i)*132 + tx*8)     = make_float4(s8[i][0],s8[i][1],s8[i][2],s8[i][3]);
            *(float4*)(Ps + (ty*8+i)*132 + tx*8 + 4) = make_float4(s8[i][4],s8[i][5],s8[i][6],s8[i][7]);
        }
        __syncthreads();
        if (tid < 128) {
            float rm = -1e30f;
            #pragma unroll 8
            for (int s = 0; s < 128; s++) rm = fmaxf(rm, Ps[tid*132+s]);
            float mo = m_sh[tid];
            float mn = fmaxf(mo, rm);
            float al = __expf(mo - mn);
            m_sh[tid] = mn; al_sh[tid] = al; l_sh[tid] *= al;
        }
        __syncthreads();
        {
            int r = tid >> 1, sOff = (tid & 1) * 64;
            float mn = m_sh[r];
            float ssum = 0.f;
            #pragma unroll 8
            for (int s = sOff; s < sOff + 64; s++) {
                float p = __expf(Ps[r*132+s] - mn);
                Ps[r*132+s] = p;
                ssum += p;
            }
            redl[tid] = ssum;
        }
        __syncthreads();
        if (tid < 128) l_sh[tid] += redl[2*tid] + redl[2*tid+1];
        #pragma unroll
        for (int i = 0; i < 4; i++) {
            float al = al_sh[pg*4+i];
            #pragma unroll
            for (int j = 0; j < 4; j++) acc[i][j] *= al;
        }
        #pragma unroll 4
        for (int s = 0; s < 128; s++) {
            float4 v4 = *(const float4*)(Vs + s*36 + pskg*4);
            float p0 = Ps[(pg*4+0)*132+s];
            float p1 = Ps[(pg*4+1)*132+s];
            float p2 = Ps[(pg*4+2)*132+s];
            float p3 = Ps[(pg*4+3)*132+s];
            acc[0][0]+=p0*v4.x; acc[0][1]+=p0*v4.y; acc[0][2]+=p0*v4.z; acc[0][3]+=p0*v4.w;
            acc[1][0]+=p1*v4.x; acc[1][1]+=p1*v4.y; acc[1][2]+=p1*v4.z; acc[1][3]+=p1*v4.w;
            acc[2][0]+=p2*v4.x; acc[2][1]+=p2*v4.y; acc[2][2]+=p2*v4.z; acc[2][3]+=p2*v4.w;
            acc[3][0]+=p3*v4.x; acc[3][1]+=p3*v4.y; acc[3][2]+=p3*v4.z; acc[3][3]+=p3*v4.w;
        }
    }
    __syncthreads();
    #pragma unroll
    for (int i = 0; i < 4; i++) {
        float inv = 1.f / l_sh[pg*4+i];
        float4 o = make_float4(rtf32(acc[i][0]*inv), rtf32(acc[i][1]*inv),
                               rtf32(acc[i][2]*inv), rtf32(acc[i][3]*inv));
        *(float4*)&xcatt[((long)b*DD + tc*128 + pg*4 + i) * SS + h*SK + pskg*4] = o;
    }
}

// ---------------- final transpose [B,D,S] -> [B,S,D] ----------------
__global__ void transpose_out(const float* __restrict__ in, float* __restrict__ out)
{
    __shared__ float tile[32][33];
    int b = blockIdx.z;
    int d0 = blockIdx.x * 32, s0 = blockIdx.y * 32;
    int tx = threadIdx.x, ty = threadIdx.y;
    #pragma unroll
    for (int k = 0; k < 32; k += 8)
        tile[ty+k][tx] = in[((long)b*DD + d0+ty+k) * SS + s0 + tx];
    __syncthreads();
    #pragma unroll
    for (int k = 0; k < 32; k += 8)
        out[((long)b*SS + s0+ty+k) * DD + d0 + tx] = tile[tx][ty+k];
}

// ---------------- launch ----------------
extern "C" void kernel_launch(void* const* d_in, const int* in_sizes, int n_in,
                              void* d_out, int out_size)
{
    const float* x   = (const float*)d_in[0];
    const float* Wp  = (const float*)d_in[1];
    const float* bp  = (const float*)d_in[2];
    const float* Wc  = (const float*)d_in[3];
    const float* bc  = (const float*)d_in[4];
    const float* ap  = (const float*)d_in[5];
    const float* bpp = (const float*)d_in[6];
    const float* ac  = (const float*)d_in[7];
    const float* bcc = (const float*)d_in[8];
    float* out = (float*)d_out;

    void *p_xp, *p_qkv, *p_xp2, *p_xt, *p_qkvc, *p_xcatt, *p_proj, *p_wp, *p_wc;
    cudaGetSymbolAddress(&p_xp, g_xp);
    cudaGetSymbolAddress(&p_qkv, g_qkv);
    cudaGetSymbolAddress(&p_xp2, g_xp2);
    cudaGetSymbolAddress(&p_xt, g_xt);
    cudaGetSymbolAddress(&p_qkvc, g_qkvc);
    cudaGetSymbolAddress(&p_xcatt, g_xcatt);
    cudaGetSymbolAddress(&p_proj, g_proj);
    cudaGetSymbolAddress(&p_wp, g_Wp32);
    cudaGetSymbolAddress(&p_wc, g_Wc32);
    float* xp    = (float*)p_xp;
    float* qkv   = (float*)p_qkv;
    float* xp2   = (float*)p_xp2;
    float* xt    = (float*)p_xt;
    float* qkvc  = (float*)p_qkvc;
    float* xcatt = (float*)p_xcatt;
    float* proj  = (float*)p_proj;
    float* Wp32  = (float*)p_wp;
    float* Wc32  = (float*)p_wc;

    size_t posSmem = POS_SMEM_FLOATS * sizeof(float);
    size_t chSmem  = CH_SMEM_FLOATS * sizeof(float);
    cudaFuncSetAttribute((const void*)pos_attn,  cudaFuncAttributeMaxDynamicSharedMemorySize, (int)posSmem);
    cudaFuncSetAttribute((const void*)chan_attn, cudaFuncAttributeMaxDynamicSharedMemorySize, (int)chSmem);

    // 0. round weights to tf32-representable fp32
    round_tf32_kernel<<<(3*DD*DD/4 + 255)/256, 256>>>(Wp, Wp32, 3*DD*DD/4);
    round_tf32_kernel<<<(4*SS*SS/4 + 255)/256, 256>>>(Wc, Wc32, 4*SS*SS/4);

    // 1. LayerNorm over D (tf32-rounded output)
    ln_p_kernel<<<BB*SS, 256>>>(x, ap, bpp, xp);

    // 2. positional qkv: [4096,1024] x [1024,1024] batched over 3 (tensor cores)
    gemm_tf32<<<dim3(DD/128, (BB*SS)/128, 3), 256>>>(
        xp, Wp32, bp, qkv, BB*SS, DD, DD,
        0L, (long)DD*DD, (long)DD, (long)BB*SS*DD);

    // 3. positional attention
    pos_attn<<<BB*HP, 256, posSmem>>>(qkv, xp2);

    // 4. LayerNorm over S + transpose to [B,D,S] (tf32-rounded output)
    ln_c_kernel<<<dim3(DD/32, BB), 256>>>(xp2, ac, bcc, xt);

    // 5. channel qkv: [16384,256] x [256,256] batched over 3 (tensor cores)
    gemm_tf32<<<dim3(SS/128, (BB*DD)/128, 3), 256>>>(
        xt, Wc32, bc, qkvc, BB*DD, SS, SS,
        0L, (long)SS*SS, (long)SS, (long)BB*DD*SS);

    // 6. channel attention (flash)
    chan_attn<<<dim3(8, BB*HC), 256, chSmem>>>(qkvc, xcatt);

    // 7. output projection with Wc[3], bc[3] (tensor cores)
    gemm_tf32<<<dim3(SS/128, (BB*DD)/128, 1), 256>>>(
        xcatt, Wc32 + 3L*SS*SS, bc + 3L*SS, proj, BB*DD, SS, SS,
        0L, 0L, 0L, 0L);

    // 8. transpose [B,D,S] -> [B,S,D]
    transpose_out<<<dim3(DD/32, SS/32, BB), dim3(32, 8)>>>(proj, out);
}

// round 3
// speedup vs baseline: 2.7695x; 1.8930x over previous
#include <cuda_runtime.h>
#include <math.h>
#include <stdint.h>

// Problem constants
#define BB 16
#define SS 256
#define DD 1024
#define HP 16
#define DK 64
#define HC 8
#define SK 32
#define EPSV 1e-6f

// ---------------- scratch buffers (static device memory; no allocation) ----------------
__device__ float g_xp[BB*SS*DD];          // LN_p output (full fp32) [B,S,D]
__device__ float g_qkv[3*BB*SS*DD];       // pos qkv                [3,B,S,D]
__device__ float g_xp2[BB*SS*DD];         // pos attn out           [B,S,D]
__device__ float g_xt[BB*DD*SS];          // LN_c out, transposed   [B,D,S]
__device__ float g_qkvc[3*BB*DD*SS];      // channel qkv            [3,B,D,S]
__device__ float g_xcatt[BB*DD*SS];       // channel attn out       [B,D,S]
__device__ float g_proj[BB*DD*SS];        // final proj (pre-transpose) [B,D,S]
__device__ float g_Wp32[3*DD*DD];         // tf32-rounded Wp
__device__ float g_Wc32[4*SS*SS];         // tf32-rounded Wc

// ---------------- helpers ----------------
__device__ __forceinline__ float rtf32(float x) {
    unsigned u;
    asm("cvt.rna.tf32.f32 %0, %1;" : "=r"(u) : "f"(x));
    return __uint_as_float(u);
}

__device__ __forceinline__ void cp_async16(uint32_t smem, const void* g) {
    asm volatile("cp.async.cg.shared.global [%0], [%1], 16;" :: "r"(smem), "l"(g));
}

__device__ __forceinline__ void mma_tf32(float* c, const unsigned* a, const unsigned* b) {
    asm volatile("mma.sync.aligned.m16n8k8.row.col.f32.tf32.tf32.f32 "
        "{%0,%1,%2,%3}, {%4,%5,%6,%7}, {%8,%9}, {%0,%1,%2,%3};"
        : "+f"(c[0]), "+f"(c[1]), "+f"(c[2]), "+f"(c[3])
        : "r"(a[0]), "r"(a[1]), "r"(a[2]), "r"(a[3]), "r"(b[0]), "r"(b[1]));
}

__device__ __forceinline__ void mma_tf32_f(float* c, const float* a, const unsigned* b) {
    asm volatile("mma.sync.aligned.m16n8k8.row.col.f32.tf32.tf32.f32 "
        "{%0,%1,%2,%3}, {%4,%5,%6,%7}, {%8,%9}, {%0,%1,%2,%3};"
        : "+f"(c[0]), "+f"(c[1]), "+f"(c[2]), "+f"(c[3])
        : "r"(__float_as_uint(a[0])), "r"(__float_as_uint(a[1])),
          "r"(__float_as_uint(a[2])), "r"(__float_as_uint(a[3])),
          "r"(b[0]), "r"(b[1]));
}

// ---------------- tf32 rounding kernel for weights ----------------
__global__ void __launch_bounds__(256) round_tf32_kernel(const float* __restrict__ in,
                                                         float* __restrict__ out, int n4)
{
    int i = blockIdx.x * 256 + threadIdx.x;
    if (i < n4) {
        float4 v = ((const float4*)in)[i];
        v.x = rtf32(v.x); v.y = rtf32(v.y); v.z = rtf32(v.z); v.w = rtf32(v.w);
        ((float4*)out)[i] = v;
    }
}

// ---------------- LayerNorm over channels (ddof=1, eps added to std) ----------------
__global__ void __launch_bounds__(256) ln_p_kernel(const float* __restrict__ x,
                                                   const float* __restrict__ ap,
                                                   const float* __restrict__ bp,
                                                   float* __restrict__ xp)
{
    long row = blockIdx.x;                 // b*S+s, 4096 rows
    const float* xr = x + row * DD;
    int tid = threadIdx.x;
    float s = 0.f, s2 = 0.f;
    #pragma unroll
    for (int i = tid; i < DD; i += 256) { float v = xr[i]; s += v; s2 += v*v; }
    __shared__ float rs[8], rs2[8];
    #pragma unroll
    for (int o = 16; o; o >>= 1) { s += __shfl_xor_sync(~0u, s, o); s2 += __shfl_xor_sync(~0u, s2, o); }
    if ((tid & 31) == 0) { rs[tid>>5] = s; rs2[tid>>5] = s2; }
    __syncthreads();
    s = 0.f; s2 = 0.f;
    #pragma unroll
    for (int w = 0; w < 8; w++) { s += rs[w]; s2 += rs2[w]; }
    float mean = s * (1.f / DD);
    float var  = (s2 - s * mean) * (1.f / (DD - 1));
    float inv  = 1.f / (sqrtf(var) + EPSV);
    #pragma unroll
    for (int i = tid; i < DD; i += 256) {
        float v = xr[i];
        xp[row * DD + i] = ap[i] * (v - mean) * inv + bp[i];
    }
}

// ---------------- tf32 tensor-core GEMM with split-A compensation ----------------
// C = A*B + bias; A kept fp32, split into tf32 hi + lo per fragment (2 MMAs).
// BM=128, BN=128, BK=16, 256 threads (8 warps), warp tile 32x64 via m16n8k8
__global__ void __launch_bounds__(256, 2) gemm_tf32(const float* __restrict__ A,
                                                    const float* __restrict__ Bm,
                                                    const float* __restrict__ bias,
                                                    float* __restrict__ C,
                                                    int M, int N, int K,
                                                    long aB, long bB, long biasB, long cB)
{
    int bz = blockIdx.z;
    A    += (long)bz * aB;
    Bm   += (long)bz * bB;
    bias += (long)bz * biasB;
    C    += (long)bz * cB;

    __shared__ float As[2][128*20];
    __shared__ float Bs[2][16*136];

    int tid  = threadIdx.x;
    int warp = tid >> 5, lane = tid & 31;
    int wm = warp & 3, wn = warp >> 2;
    long row0 = (long)blockIdx.y * 128;
    int  col0 = blockIdx.x * 128;

    int aRow0 = tid >> 2,        aCol = (tid & 3) * 4;
    int aRow1 = (tid + 256) >> 2;
    int bRow0 = tid >> 5,        bCol = (tid & 31) * 4;
    int bRow1 = (tid + 256) >> 5;

    float acc[2][8][4];
    #pragma unroll
    for (int mi = 0; mi < 2; mi++)
        #pragma unroll
        for (int ni = 0; ni < 8; ni++)
            #pragma unroll
            for (int r = 0; r < 4; r++) acc[mi][ni][r] = 0.f;

    #define LOAD_TILE(buf, k0) do { \
        cp_async16((uint32_t)__cvta_generic_to_shared(&As[buf][aRow0*20 + aCol]), \
                   &A[(row0 + aRow0) * K + (k0) + aCol]); \
        cp_async16((uint32_t)__cvta_generic_to_shared(&As[buf][aRow1*20 + aCol]), \
                   &A[(row0 + aRow1) * K + (k0) + aCol]); \
        cp_async16((uint32_t)__cvta_generic_to_shared(&Bs[buf][bRow0*136 + bCol]), \
                   &Bm[(long)((k0) + bRow0) * N + col0 + bCol]); \
        cp_async16((uint32_t)__cvta_generic_to_shared(&Bs[buf][bRow1*136 + bCol]), \
                   &Bm[(long)((k0) + bRow1) * N + col0 + bCol]); \
        asm volatile("cp.async.commit_group;"); \
    } while (0)

    int KT = K >> 4;
    LOAD_TILE(0, 0);

    for (int kt = 0; kt < KT; kt++) {
        int buf = kt & 1;
        if (kt + 1 < KT) {
            LOAD_TILE(buf ^ 1, (kt + 1) << 4);
            asm volatile("cp.async.wait_group 1;" ::: "memory");
        } else {
            asm volatile("cp.async.wait_group 0;" ::: "memory");
        }
        __syncthreads();

        #pragma unroll
        for (int ks = 0; ks < 2; ks++) {
            int kb = ks * 8;
            unsigned ahi[2][4], alo[2][4];
            #pragma unroll
            for (int mi = 0; mi < 2; mi++) {
                int r = wm * 32 + mi * 16 + (lane >> 2);
                int c = kb + (lane & 3);
                float v0 = As[buf][r * 20 + c];
                float v1 = As[buf][(r + 8) * 20 + c];
                float v2 = As[buf][r * 20 + c + 4];
                float v3 = As[buf][(r + 8) * 20 + c + 4];
                float h0 = rtf32(v0), h1 = rtf32(v1), h2 = rtf32(v2), h3 = rtf32(v3);
                ahi[mi][0] = __float_as_uint(h0); alo[mi][0] = __float_as_uint(v0 - h0);
                ahi[mi][1] = __float_as_uint(h1); alo[mi][1] = __float_as_uint(v1 - h1);
                ahi[mi][2] = __float_as_uint(h2); alo[mi][2] = __float_as_uint(v2 - h2);
                ahi[mi][3] = __float_as_uint(h3); alo[mi][3] = __float_as_uint(v3 - h3);
            }
            #pragma unroll
            for (int ni = 0; ni < 8; ni++) {
                int n = wn * 64 + ni * 8 + (lane >> 2);
                int kr = kb + (lane & 3);
                unsigned b[2];
                b[0] = __float_as_uint(Bs[buf][kr * 136 + n]);
                b[1] = __float_as_uint(Bs[buf][(kr + 4) * 136 + n]);
                mma_tf32(acc[0][ni], alo[0], b);
                mma_tf32(acc[0][ni], ahi[0], b);
                mma_tf32(acc[1][ni], alo[1], b);
                mma_tf32(acc[1][ni], ahi[1], b);
            }
        }
        __syncthreads();
    }

    #pragma unroll
    for (int mi = 0; mi < 2; mi++) {
        #pragma unroll
        for (int ni = 0; ni < 8; ni++) {
            long r = row0 + wm * 32 + mi * 16 + (lane >> 2);
            int  c = col0 + wn * 64 + ni * 8 + 2 * (lane & 3);
            float b0 = bias[c], b1 = bias[c + 1];
            float2 v0 = make_float2(acc[mi][ni][0] + b0, acc[mi][ni][1] + b1);
            float2 v1 = make_float2(acc[mi][ni][2] + b0, acc[mi][ni][3] + b1);
            *(float2*)&C[r * N + c]       = v0;
            *(float2*)&C[(r + 8) * N + c] = v1;
        }
    }
    #undef LOAD_TILE
}

// ---------------- positional attention via tensor cores ----------------
// Block: 8 warps, 128 queries; full S=256 keys, exact single-pass softmax.
// grid (2, B*HP). smem: Q[128][68], K[256][68], V[256][68] (pad 68 = conflict-free frags)
#define PA_SMEM_BYTES ((128 + 256 + 256) * 68 * 4)
__global__ void __launch_bounds__(256) pos_attn_mma(const float* __restrict__ qkv,
                                                    float* __restrict__ out)
{
    extern __shared__ float sm[];
    float* Qs = sm;              // [128][68]
    float* Ks = Qs + 128 * 68;   // [256][68]
    float* Vs = Ks + 256 * 68;   // [256][68]
    int tid = threadIdx.x, lane = tid & 31, w = tid >> 5;
    int qt = blockIdx.x, bh = blockIdx.y;
    int b = bh >> 4, h = bh & 15;

    const float* Qg = qkv + ((long)b * SS + qt * 128) * DD + h * DK;
    const float* Kg = qkv + (long)BB*SS*DD + (long)b * SS * DD + h * DK;
    const float* Vg = Kg + (long)BB*SS*DD;

    // load Q (scaled by 1/8, rna-rounded), K, V (rna-rounded)
    for (int idx = tid; idx < 128 * 16; idx += 256) {
        int r = idx >> 4, c = (idx & 15) * 4;
        float4 v = *(const float4*)&Qg[(long)r * DD + c];
        v.x = rtf32(v.x * 0.125f); v.y = rtf32(v.y * 0.125f);
        v.z = rtf32(v.z * 0.125f); v.w = rtf32(v.w * 0.125f);
        *(float4*)&Qs[r * 68 + c] = v;
    }
    for (int idx = tid; idx < 256 * 16; idx += 256) {
        int r = idx >> 4, c = (idx & 15) * 4;
        float4 kv = *(const float4*)&Kg[(long)r * DD + c];
        kv.x = rtf32(kv.x); kv.y = rtf32(kv.y); kv.z = rtf32(kv.z); kv.w = rtf32(kv.w);
        *(float4*)&Ks[r * 68 + c] = kv;
        float4 vv = *(const float4*)&Vg[(long)r * DD + c];
        vv.x = rtf32(vv.x); vv.y = rtf32(vv.y); vv.z = rtf32(vv.z); vv.w = rtf32(vv.w);
        *(float4*)&Vs[r * 68 + c] = vv;
    }
    __syncthreads();

    int g = lane >> 2, tig = lane & 3;

    // Q a-frags (8 k-steps over DK=64)
    unsigned qa[8][4];
    #pragma unroll
    for (int ks = 0; ks < 8; ks++) {
        const float* qb = Qs + (w * 16 + g) * 68 + ks * 8 + tig;
        qa[ks][0] = __float_as_uint(qb[0]);
        qa[ks][1] = __float_as_uint(qb[8 * 68]);
        qa[ks][2] = __float_as_uint(qb[4]);
        qa[ks][3] = __float_as_uint(qb[8 * 68 + 4]);
    }

    // scores: 16 rows x 256 cols per warp
    float sc[32][4];
    #pragma unroll
    for (int nf = 0; nf < 32; nf++) {
        sc[nf][0] = sc[nf][1] = sc[nf][2] = sc[nf][3] = 0.f;
        #pragma unroll
        for (int ks = 0; ks < 8; ks++) {
            unsigned bb[2];
            bb[0] = __float_as_uint(Ks[(nf * 8 + g) * 68 + ks * 8 + tig]);
            bb[1] = __float_as_uint(Ks[(nf * 8 + g) * 68 + ks * 8 + tig + 4]);
            mma_tf32(sc[nf], qa[ks], bb);
        }
    }

    // softmax (rows g and g+8)
    float mx0 = -1e30f, mx1 = -1e30f;
    #pragma unroll
    for (int nf = 0; nf < 32; nf++) {
        mx0 = fmaxf(mx0, fmaxf(sc[nf][0], sc[nf][1]));
        mx1 = fmaxf(mx1, fmaxf(sc[nf][2], sc[nf][3]));
    }
    mx0 = fmaxf(mx0, __shfl_xor_sync(~0u, mx0, 1));
    mx0 = fmaxf(mx0, __shfl_xor_sync(~0u, mx0, 2));
    mx1 = fmaxf(mx1, __shfl_xor_sync(~0u, mx1, 1));
    mx1 = fmaxf(mx1, __shfl_xor_sync(~0u, mx1, 2));
    float sum0 = 0.f, sum1 = 0.f;
    #pragma unroll
    for (int nf = 0; nf < 32; nf++) {
        float p0 = __expf(sc[nf][0] - mx0), p1 = __expf(sc[nf][1] - mx0);
        float p2 = __expf(sc[nf][2] - mx1), p3 = __expf(sc[nf][3] - mx1);
        sum0 += p0 + p1; sum1 += p2 + p3;
        sc[nf][0] = rtf32(p0); sc[nf][1] = rtf32(p1);
        sc[nf][2] = rtf32(p2); sc[nf][3] = rtf32(p3);
    }
    sum0 += __shfl_xor_sync(~0u, sum0, 1); sum0 += __shfl_xor_sync(~0u, sum0, 2);
    sum1 += __shfl_xor_sync(~0u, sum1, 1); sum1 += __shfl_xor_sync(~0u, sum1, 2);

    // convert P c-frags -> a-frags (in place)
    int srcA = (lane & 28) | (tig >> 1);
    int srcB = srcA + 2;
    bool odd = tig & 1;
    #pragma unroll
    for (int f = 0; f < 32; f++) {
        float t0 = __shfl_sync(~0u, sc[f][0], srcA);
        float t1 = __shfl_sync(~0u, sc[f][1], srcA);
        float t2 = __shfl_sync(~0u, sc[f][2], srcA);
        float t3 = __shfl_sync(~0u, sc[f][3], srcA);
        float u0 = __shfl_sync(~0u, sc[f][0], srcB);
        float u1 = __shfl_sync(~0u, sc[f][1], srcB);
        float u2 = __shfl_sync(~0u, sc[f][2], srcB);
        float u3 = __shfl_sync(~0u, sc[f][3], srcB);
        sc[f][0] = odd ? t1 : t0;
        sc[f][1] = odd ? t3 : t2;
        sc[f][2] = odd ? u1 : u0;
        sc[f][3] = odd ? u3 : u2;
    }

    // PV: O[16][64] per warp
    float o[8][4];
    #pragma unroll
    for (int nf = 0; nf < 8; nf++) { o[nf][0]=o[nf][1]=o[nf][2]=o[nf][3]=0.f; }
    #pragma unroll
    for (int nf = 0; nf < 8; nf++) {
        #pragma unroll
        for (int ks = 0; ks < 32; ks++) {
            unsigned bb[2];
            bb[0] = __float_as_uint(Vs[(ks * 8 + tig) * 68 + nf * 8 + g]);
            bb[1] = __float_as_uint(Vs[(ks * 8 + tig + 4) * 68 + nf * 8 + g]);
            mma_tf32_f(o[nf], sc[ks], bb);
        }
    }

    float inv0 = 1.f / sum0, inv1 = 1.f / sum1;
    long orow0 = ((long)b * SS + qt * 128 + w * 16 + g) * DD + h * DK;
    long orow1 = orow0 + 8L * DD;
    #pragma unroll
    for (int nf = 0; nf < 8; nf++) {
        int c = nf * 8 + 2 * tig;
        *(float2*)&out[orow0 + c] = make_float2(o[nf][0] * inv0, o[nf][1] * inv0);
        *(float2*)&out[orow1 + c] = make_float2(o[nf][2] * inv1, o[nf][3] * inv1);
    }
}

// ---------------- LayerNorm over sequence + transpose to [B,D,S], tiled ----------------
__global__ void __launch_bounds__(256) ln_c_kernel(const float* __restrict__ xin,
                                                   const float* __restrict__ ac,
                                                   const float* __restrict__ bcv,
                                                   float* __restrict__ xt)
{
    __shared__ float tile[32][257];
    __shared__ float red[8][32], red2[8][32];
    __shared__ float s_mean[32], s_inv[32];
    int b = blockIdx.y, d0 = blockIdx.x * 32;
    int tid = threadIdx.x, lane = tid & 31, w = tid >> 5;
    const float* base = xin + (long)b * SS * DD + d0;
    #pragma unroll 4
    for (int i = 0; i < 32; i++) {
        int s = w * 32 + i;
        tile[lane][s] = base[(long)s * DD + lane];
    }
    __syncthreads();
    {
        int d = tid & 31, ch = tid >> 5;
        float s1 = 0.f, s2 = 0.f;
        #pragma unroll
        for (int j = 0; j < 32; j++) {
            float v = tile[d][ch * 32 + j]; s1 += v; s2 += v * v;
        }
        red[ch][d] = s1; red2[ch][d] = s2;
    }
    __syncthreads();
    if (tid < 32) {
        float s1 = 0.f, s2 = 0.f;
        #pragma unroll
        for (int ch = 0; ch < 8; ch++) { s1 += red[ch][tid]; s2 += red2[ch][tid]; }
        float mean = s1 * (1.f / SS);
        float var  = (s2 - s1 * mean) * (1.f / (SS - 1));
        s_mean[tid] = mean;
        s_inv[tid]  = 1.f / (sqrtf(var) + EPSV);
    }
    __syncthreads();
    {
        int d = tid >> 3, s0 = (tid & 7) * 32;
        float mean = s_mean[d], inv = s_inv[d];
        float* dst = xt + ((long)b * DD + d0 + d) * SS;
        #pragma unroll
        for (int j = 0; j < 32; j += 4) {
            int s = s0 + j;
            float4 o;
            o.x = ac[s+0] * (tile[d][s+0] - mean) * inv + bcv[s+0];
            o.y = ac[s+1] * (tile[d][s+1] - mean) * inv + bcv[s+1];
            o.z = ac[s+2] * (tile[d][s+2] - mean) * inv + bcv[s+2];
            o.w = ac[s+3] * (tile[d][s+3] - mean) * inv + bcv[s+3];
            *(float4*)&dst[s] = o;
        }
    }
}

// ---------------- channel attention via tensor cores (flash, online softmax) ----------------
// Block: 8 warps, 128 query-channels; key tiles of 128 over 1024; dk=32.
// grid (8, B*HC). smem: Q[128][36], K[128][36], V[128][36]
#define CA_SMEM_BYTES ((128 + 128 + 128) * 36 * 4)
__global__ void __launch_bounds__(256) chan_attn_mma(const float* __restrict__ qkvc,
                                                     float* __restrict__ xcatt)
{
    extern __shared__ float sm[];
    float* Qs = sm;              // [128][36]
    float* Ks = Qs + 128 * 36;
    float* Vs = Ks + 128 * 36;
    int tid = threadIdx.x, lane = tid & 31, w = tid >> 5;
    int qt = blockIdx.x, bh = blockIdx.y;
    int b = bh >> 3, h = bh & 7;
    const float scale = 0.1767766952966369f;   // 1/sqrt(32)

    const long qBase = (long)b * DD * SS + h * SK;
    const long nStride = (long)BB * DD * SS;

    // load Q (scaled, rounded)
    for (int idx = tid; idx < 128 * 8; idx += 256) {
        int r = idx >> 3, c = (idx & 7) * 4;
        float4 v = *(const float4*)&qkvc[qBase + (long)(qt * 128 + r) * SS + c];
        v.x = rtf32(v.x * scale); v.y = rtf32(v.y * scale);
        v.z = rtf32(v.z * scale); v.w = rtf32(v.w * scale);
        *(float4*)&Qs[r * 36 + c] = v;
    }
    __syncthreads();

    int g = lane >> 2, tig = lane & 3;

    unsigned qa[4][4];
    #pragma unroll
    for (int ks = 0; ks < 4; ks++) {
        const float* qb = Qs + (w * 16 + g) * 36 + ks * 8 + tig;
        qa[ks][0] = __float_as_uint(qb[0]);
        qa[ks][1] = __float_as_uint(qb[8 * 36]);
        qa[ks][2] = __float_as_uint(qb[4]);
        qa[ks][3] = __float_as_uint(qb[8 * 36 + 4]);
    }

    float m0 = -1e30f, m1 = -1e30f, l0 = 0.f, l1 = 0.f;
    float o[4][4];
    #pragma unroll
    for (int nf = 0; nf < 4; nf++) { o[nf][0]=o[nf][1]=o[nf][2]=o[nf][3]=0.f; }

    int srcA = (lane & 28) | (tig >> 1);
    int srcB = srcA + 2;
    bool odd = tig & 1;

    for (int st = 0; st < 8; st++) {
        __syncthreads();
        for (int idx = tid; idx < 128 * 8; idx += 256) {
            int r = idx >> 3, c = (idx & 7) * 4;
            float4 kv = *(const float4*)&qkvc[qBase + nStride + (long)(st * 128 + r) * SS + c];
            kv.x = rtf32(kv.x); kv.y = rtf32(kv.y); kv.z = rtf32(kv.z); kv.w = rtf32(kv.w);
            *(float4*)&Ks[r * 36 + c] = kv;
            float4 vv = *(const float4*)&qkvc[qBase + 2 * nStride + (long)(st * 128 + r) * SS + c];
            vv.x = rtf32(vv.x); vv.y = rtf32(vv.y); vv.z = rtf32(vv.z); vv.w = rtf32(vv.w);
            *(float4*)&Vs[r * 36 + c] = vv;
        }
        __syncthreads();

        // scores 16x128 per warp
        float sc[16][4];
        #pragma unroll
        for (int nf = 0; nf < 16; nf++) {
            sc[nf][0] = sc[nf][1] = sc[nf][2] = sc[nf][3] = 0.f;
            #pragma unroll
            for (int ks = 0; ks < 4; ks++) {
                unsigned bb[2];
                bb[0] = __float_as_uint(Ks[(nf * 8 + g) * 36 + ks * 8 + tig]);
                bb[1] = __float_as_uint(Ks[(nf * 8 + g) * 36 + ks * 8 + tig + 4]);
                mma_tf32(sc[nf], qa[ks], bb);
            }
        }
        // online softmax
        float tm0 = -1e30f, tm1 = -1e30f;
        #pragma unroll
        for (int nf = 0; nf < 16; nf++) {
            tm0 = fmaxf(tm0, fmaxf(sc[nf][0], sc[nf][1]));
            tm1 = fmaxf(tm1, fmaxf(sc[nf][2], sc[nf][3]));
        }
        tm0 = fmaxf(tm0, __shfl_xor_sync(~0u, tm0, 1));
        tm0 = fmaxf(tm0, __shfl_xor_sync(~0u, tm0, 2));
        tm1 = fmaxf(tm1, __shfl_xor_sync(~0u, tm1, 1));
        tm1 = fmaxf(tm1, __shfl_xor_sync(~0u, tm1, 2));
        float nm0 = fmaxf(m0, tm0), nm1 = fmaxf(m1, tm1);
        float al0 = __expf(m0 - nm0), al1 = __expf(m1 - nm1);
        m0 = nm0; m1 = nm1;
        float ts0 = 0.f, ts1 = 0.f;
        #pragma unroll
        for (int nf = 0; nf < 16; nf++) {
            float p0 = __expf(sc[nf][0] - nm0), p1 = __expf(sc[nf][1] - nm0);
            float p2 = __expf(sc[nf][2] - nm1), p3 = __expf(sc[nf][3] - nm1);
            ts0 += p0 + p1; ts1 += p2 + p3;
            sc[nf][0] = rtf32(p0); sc[nf][1] = rtf32(p1);
            sc[nf][2] = rtf32(p2); sc[nf][3] = rtf32(p3);
        }
        ts0 += __shfl_xor_sync(~0u, ts0, 1); ts0 += __shfl_xor_sync(~0u, ts0, 2);
        ts1 += __shfl_xor_sync(~0u, ts1, 1); ts1 += __shfl_xor_sync(~0u, ts1, 2);
        l0 = l0 * al0 + ts0; l1 = l1 * al1 + ts1;
        #pragma unroll
        for (int nf = 0; nf < 4; nf++) {
            o[nf][0] *= al0; o[nf][1] *= al0;
            o[nf][2] *= al1; o[nf][3] *= al1;
        }
        // convert P -> a-frags (in place)
        #pragma unroll
        for (int f = 0; f < 16; f++) {
            float t0 = __shfl_sync(~0u, sc[f][0], srcA);
            float t1 = __shfl_sync(~0u, sc[f][1], srcA);
            float t2 = __shfl_sync(~0u, sc[f][2], srcA);
            float t3 = __shfl_sync(~0u, sc[f][3], srcA);
            float u0 = __shfl_sync(~0u, sc[f][0], srcB);
            float u1 = __shfl_sync(~0u, sc[f][1], srcB);
            float u2 = __shfl_sync(~0u, sc[f][2], srcB);
            float u3 = __shfl_sync(~0u, sc[f][3], srcB);
            sc[f][0] = odd ? t1 : t0;
            sc[f][1] = odd ? t3 : t2;
            sc[f][2] = odd ? u1 : u0;
            sc[f][3] = odd ? u3 : u2;
        }
        // PV
        #pragma unroll
        for (int nf = 0; nf < 4; nf++) {
            #pragma unroll
            for (int ks = 0; ks < 16; ks++) {
                unsigned bb[2];
                bb[0] = __float_as_uint(Vs[(ks * 8 + tig) * 36 + nf * 8 + g]);
                bb[1] = __float_as_uint(Vs[(ks * 8 + tig + 4) * 36 + nf * 8 + g]);
                mma_tf32_f(o[nf], sc[ks], bb);
            }
        }
    }

    float inv0 = 1.f / l0, inv1 = 1.f / l1;
    long orow0 = ((long)b * DD + qt * 128 + w * 16 + g) * SS + h * SK;
    long orow1 = orow0 + 8L * SS;
    #pragma unroll
    for (int nf = 0; nf < 4; nf++) {
        int c = nf * 8 + 2 * tig;
        *(float2*)&xcatt[orow0 + c] = make_float2(o[nf][0] * inv0, o[nf][1] * inv0);
        *(float2*)&xcatt[orow1 + c] = make_float2(o[nf][2] * inv1, o[nf][3] * inv1);
    }
}

// ---------------- final transpose [B,D,S] -> [B,S,D] ----------------
__global__ void transpose_out(const float* __restrict__ in, float* __restrict__ out)
{
    __shared__ float tile[32][33];
    int b = blockIdx.z;
    int d0 = blockIdx.x * 32, s0 = blockIdx.y * 32;
    int tx = threadIdx.x, ty = threadIdx.y;
    #pragma unroll
    for (int k = 0; k < 32; k += 8)
        tile[ty+k][tx] = in[((long)b*DD + d0+ty+k) * SS + s0 + tx];
    __syncthreads();
    #pragma unroll
    for (int k = 0; k < 32; k += 8)
        out[((long)b*SS + s0+ty+k) * DD + d0 + tx] = tile[tx][ty+k];
}

// ---------------- launch ----------------
extern "C" void kernel_launch(void* const* d_in, const int* in_sizes, int n_in,
                              void* d_out, int out_size)
{
    const float* x   = (const float*)d_in[0];
    const float* Wp  = (const float*)d_in[1];
    const float* bp  = (const float*)d_in[2];
    const float* Wc  = (const float*)d_in[3];
    const float* bc  = (const float*)d_in[4];
    const float* ap  = (const float*)d_in[5];
    const float* bpp = (const float*)d_in[6];
    const float* ac  = (const float*)d_in[7];
    const float* bcc = (const float*)d_in[8];
    float* out = (float*)d_out;

    void *p_xp, *p_qkv, *p_xp2, *p_xt, *p_qkvc, *p_xcatt, *p_proj, *p_wp, *p_wc;
    cudaGetSymbolAddress(&p_xp, g_xp);
    cudaGetSymbolAddress(&p_qkv, g_qkv);
    cudaGetSymbolAddress(&p_xp2, g_xp2);
    cudaGetSymbolAddress(&p_xt, g_xt);
    cudaGetSymbolAddress(&p_qkvc, g_qkvc);
    cudaGetSymbolAddress(&p_xcatt, g_xcatt);
    cudaGetSymbolAddress(&p_proj, g_proj);
    cudaGetSymbolAddress(&p_wp, g_Wp32);
    cudaGetSymbolAddress(&p_wc, g_Wc32);
    float* xp    = (float*)p_xp;
    float* qkv   = (float*)p_qkv;
    float* xp2   = (float*)p_xp2;
    float* xt    = (float*)p_xt;
    float* qkvc  = (float*)p_qkvc;
    float* xcatt = (float*)p_xcatt;
    float* proj  = (float*)p_proj;
    float* Wp32  = (float*)p_wp;
    float* Wc32  = (float*)p_wc;

    cudaFuncSetAttribute((const void*)pos_attn_mma,  cudaFuncAttributeMaxDynamicSharedMemorySize, PA_SMEM_BYTES);
    cudaFuncSetAttribute((const void*)chan_attn_mma, cudaFuncAttributeMaxDynamicSharedMemorySize, CA_SMEM_BYTES);

    // 0. round weights to tf32 (rna)
    round_tf32_kernel<<<(3*DD*DD/4 + 255)/256, 256>>>(Wp, Wp32, 3*DD*DD/4);
    round_tf32_kernel<<<(4*SS*SS/4 + 255)/256, 256>>>(Wc, Wc32, 4*SS*SS/4);

    // 1. LayerNorm over D
    ln_p_kernel<<<BB*SS, 256>>>(x, ap, bpp, xp);

    // 2. positional qkv (split-A compensated tf32)
    gemm_tf32<<<dim3(DD/128, (BB*SS)/128, 3), 256>>>(
        xp, Wp32, bp, qkv, BB*SS, DD, DD,
        0L, (long)DD*DD, (long)DD, (long)BB*SS*DD);

    // 3. positional attention (tensor cores)
    pos_attn_mma<<<dim3(2, BB*HP), 256, PA_SMEM_BYTES>>>(qkv, xp2);

    // 4. LayerNorm over S + transpose to [B,D,S]
    ln_c_kernel<<<dim3(DD/32, BB), 256>>>(xp2, ac, bcc, xt);

    // 5. channel qkv (split-A compensated tf32)
    gemm_tf32<<<dim3(SS/128, (BB*DD)/128, 3), 256>>>(
        xt, Wc32, bc, qkvc, BB*DD, SS, SS,
        0L, (long)SS*SS, (long)SS, (long)BB*DD*SS);

    // 6. channel attention (tensor cores, flash)
    chan_attn_mma<<<dim3(8, BB*HC), 256, CA_SMEM_BYTES>>>(qkvc, xcatt);

    // 7. output projection (split-A compensated tf32)
    gemm_tf32<<<dim3(SS/128, (BB*DD)/128, 1), 256>>>(
        xcatt, Wc32 + 3L*SS*SS, bc + 3L*SS, proj, BB*DD, SS, SS,
        0L, 0L, 0L, 0L);

    // 8. transpose [B,D,S] -> [B,S,D]
    transpose_out<<<dim3(DD/32, SS/32, BB), dim3(32, 8)>>>(proj, out);
}

// round 5
// speedup vs baseline: 3.0884x; 1.1151x over previous
#include <cuda_runtime.h>
#include <cuda_bf16.h>
#include <math.h>
#include <stdint.h>

// Problem constants
#define BB 16
#define SS 256
#define DD 1024
#define HP 16
#define DK 64
#define HC 8
#define SK 32
#define EPSV 1e-6f

// ---------------- scratch buffers (static device memory; no allocation) ----------------
__device__ float g_xp[BB*SS*DD];          // LN_p output (full fp32) [B,S,D]
__device__ float g_qkv[3*BB*SS*DD];       // pos qkv                [3,B,S,D]
__device__ float g_xp2[BB*SS*DD];         // pos attn out           [B,S,D]
__device__ float g_xt[BB*DD*SS];          // LN_c out, transposed   [B,D,S]
__device__ float g_qkvc[3*BB*DD*SS];      // channel qkv            [3,B,D,S]
__device__ float g_xcatt[BB*DD*SS];       // channel attn out       [B,D,S]
__device__ float g_proj[BB*DD*SS];        // final proj (pre-transpose) [B,D,S]
__device__ __nv_bfloat16 g_WpT_hi[3*DD*DD];  // Wp transposed [N][K], bf16 hi
__device__ __nv_bfloat16 g_WpT_lo[3*DD*DD];  // bf16 lo (residual)
__device__ __nv_bfloat16 g_WcT_hi[4*SS*SS];
__device__ __nv_bfloat16 g_WcT_lo[4*SS*SS];

// ---------------- helpers ----------------
__device__ __forceinline__ float rtf32(float x) {
    unsigned u;
    asm("cvt.rna.tf32.f32 %0, %1;" : "=r"(u) : "f"(x));
    return __uint_as_float(u);
}

__device__ __forceinline__ void cp_async16(uint32_t smem, const void* g) {
    asm volatile("cp.async.cg.shared.global [%0], [%1], 16;" :: "r"(smem), "l"(g));
}

__device__ __forceinline__ void mma_tf32(float* c, const unsigned* a, const unsigned* b) {
    asm volatile("mma.sync.aligned.m16n8k8.row.col.f32.tf32.tf32.f32 "
        "{%0,%1,%2,%3}, {%4,%5,%6,%7}, {%8,%9}, {%0,%1,%2,%3};"
        : "+f"(c[0]), "+f"(c[1]), "+f"(c[2]), "+f"(c[3])
        : "r"(a[0]), "r"(a[1]), "r"(a[2]), "r"(a[3]), "r"(b[0]), "r"(b[1]));
}

__device__ __forceinline__ void mma_tf32_f(float* c, const float* a, const unsigned* b) {
    asm volatile("mma.sync.aligned.m16n8k8.row.col.f32.tf32.tf32.f32 "
        "{%0,%1,%2,%3}, {%4,%5,%6,%7}, {%8,%9}, {%0,%1,%2,%3};"
        : "+f"(c[0]), "+f"(c[1]), "+f"(c[2]), "+f"(c[3])
        : "r"(__float_as_uint(a[0])), "r"(__float_as_uint(a[1])),
          "r"(__float_as_uint(a[2])), "r"(__float_as_uint(a[3])),
          "r"(b[0]), "r"(b[1]));
}

__device__ __forceinline__ void mma_bf16(float* c, const unsigned* a, const unsigned* b) {
    asm volatile("mma.sync.aligned.m16n8k16.row.col.f32.bf16.bf16.f32 "
        "{%0,%1,%2,%3}, {%4,%5,%6,%7}, {%8,%9}, {%0,%1,%2,%3};"
        : "+f"(c[0]), "+f"(c[1]), "+f"(c[2]), "+f"(c[3])
        : "r"(a[0]), "r"(a[1]), "r"(a[2]), "r"(a[3]), "r"(b[0]), "r"(b[1]));
}

// ---------------- weight transpose + bf16 hi/lo split ----------------
// W: [batch][K][N] row-major fp32 -> hi/lo: [batch][N][K] bf16
__global__ void __launch_bounds__(256) split_transpose(const float* __restrict__ W,
                                                       __nv_bfloat16* __restrict__ hi,
                                                       __nv_bfloat16* __restrict__ lo,
                                                       int K, int N)
{
    __shared__ float t[32][33];
    int bz = blockIdx.z;
    W  += (long)bz * K * N;
    hi += (long)bz * K * N;
    lo += (long)bz * K * N;
    int n0 = blockIdx.x * 32, k0 = blockIdx.y * 32;
    int tx = threadIdx.x & 31, ty = threadIdx.x >> 5;  // 32 x 8
    #pragma unroll
    for (int j = 0; j < 32; j += 8)
        t[ty + j][tx] = W[(long)(k0 + ty + j) * N + n0 + tx];
    __syncthreads();
    #pragma unroll
    for (int j = 0; j < 32; j += 8) {
        float v = t[tx][ty + j];
        __nv_bfloat16 h = __float2bfloat16(v);
        __nv_bfloat16 l = __float2bfloat16(v - __bfloat162float(h));
        long o = (long)(n0 + ty + j) * K + k0 + tx;
        hi[o] = h; lo[o] = l;
    }
}

// ---------------- LayerNorm over channels (ddof=1, eps added to std) ----------------
__global__ void __launch_bounds__(256) ln_p_kernel(const float* __restrict__ x,
                                                   const float* __restrict__ ap,
                                                   const float* __restrict__ bp,
                                                   float* __restrict__ xp)
{
    long row = blockIdx.x;
    const float* xr = x + row * DD;
    int tid = threadIdx.x;
    float s = 0.f, s2 = 0.f;
    #pragma unroll
    for (int i = tid; i < DD; i += 256) { float v = xr[i]; s += v; s2 += v*v; }
    __shared__ float rs[8], rs2[8];
    #pragma unroll
    for (int o = 16; o; o >>= 1) { s += __shfl_xor_sync(~0u, s, o); s2 += __shfl_xor_sync(~0u, s2, o); }
    if ((tid & 31) == 0) { rs[tid>>5] = s; rs2[tid>>5] = s2; }
    __syncthreads();
    s = 0.f; s2 = 0.f;
    #pragma unroll
    for (int w = 0; w < 8; w++) { s += rs[w]; s2 += rs2[w]; }
    float mean = s * (1.f / DD);
    float var  = (s2 - s * mean) * (1.f / (DD - 1));
    float inv  = 1.f / (sqrtf(var) + EPSV);
    #pragma unroll
    for (int i = tid; i < DD; i += 256) {
        float v = xr[i];
        xp[row * DD + i] = ap[i] * (v - mean) * inv + bp[i];
    }
}

// ---------------- bf16x3 error-compensated tensor GEMM ----------------
// C = A * B^T + bias. A [M][K] fp32 (split to bf16 hi/lo at load),
// Bh/Bl [N][K] bf16 K-major. BM=128 BN=128 BK=32, 256 threads, warp tile 32x64.
// smem tiles bf16 stride 40/row. 8 tiles x 10240 B = 81920 B.
#define GT_TILE 10240
#define GEMM_SMEM_BYTES (8 * GT_TILE)

__device__ __forceinline__ void gemm_load_chunk(
    char* smem, const float* __restrict__ A,
    const __nv_bfloat16* __restrict__ Bh, const __nv_bfloat16* __restrict__ Bl,
    long row0, int col0, int K, int k0, int buf, int tid)
{
    char* base = smem + buf * 4 * GT_TILE;
    __nv_bfloat16* aHi = (__nv_bfloat16*)base;
    __nv_bfloat16* aLo = (__nv_bfloat16*)(base + GT_TILE);
    char* bHi = base + 2 * GT_TILE;
    char* bLo = base + 3 * GT_TILE;
    // A: 128 rows x 32 cols fp32 -> hi/lo bf16
    #pragma unroll
    for (int i = 0; i < 4; i++) {
        int idx = tid + i * 256;
        int r = idx >> 3, c4 = (idx & 7) << 2;
        float4 v = *(const float4*)&A[(row0 + r) * (long)K + k0 + c4];
        __nv_bfloat162 h0 = __floats2bfloat162_rn(v.x, v.y);
        __nv_bfloat162 h1 = __floats2bfloat162_rn(v.z, v.w);
        float2 f0 = __bfloat1622float2(h0);
        float2 f1 = __bfloat1622float2(h1);
        __nv_bfloat162 l0 = __floats2bfloat162_rn(v.x - f0.x, v.y - f0.y);
        __nv_bfloat162 l1 = __floats2bfloat162_rn(v.z - f1.x, v.w - f1.y);
        int off = r * 40 + c4;
        *(__nv_bfloat162*)&aHi[off]     = h0;
        *(__nv_bfloat162*)&aHi[off + 2] = h1;
        *(__nv_bfloat162*)&aLo[off]     = l0;
        *(__nv_bfloat162*)&aLo[off + 2] = l1;
    }
    // B: 128 rows x 32 bf16, hi + lo, via cp.async 16B
    #pragma unroll
    for (int i = 0; i < 2; i++) {
        int idx = tid + i * 256;
        int r = idx >> 2, seg = (idx & 3) << 3;   // 8 bf16 = 16B
        uint32_t doff = (uint32_t)(r * 40 + seg) * 2;
        cp_async16((uint32_t)__cvta_generic_to_shared(bHi + doff),
                   &Bh[(long)(col0 + r) * K + k0 + seg]);
        cp_async16((uint32_t)__cvta_generic_to_shared(bLo + doff),
                   &Bl[(long)(col0 + r) * K + k0 + seg]);
    }
    asm volatile("cp.async.commit_group;");
}

__global__ void __launch_bounds__(256, 2) gemm_bf16(const float* __restrict__ A,
                                                    const __nv_bfloat16* __restrict__ Bh,
                                                    const __nv_bfloat16* __restrict__ Bl,
                                                    const float* __restrict__ bias,
                                                    float* __restrict__ C,
                                                    int K, int Ntot,
                                                    long aB, long bB, long biasB, long cB)
{
    extern __shared__ char smem[];
    int tid  = threadIdx.x;
    int warp = tid >> 5, lane = tid & 31;
    int wm = warp & 3, wn = warp >> 2;
    int g = lane >> 2, t = lane & 3;
    int bz = blockIdx.z;
    A    += (long)bz * aB;
    Bh   += (long)bz * bB;
    Bl   += (long)bz * bB;
    bias += (long)bz * biasB;
    C    += (long)bz * cB;
    long row0 = (long)blockIdx.y * 128;
    int  col0 = blockIdx.x * 128;

    float acc[2][8][4];
    #pragma unroll
    for (int mi = 0; mi < 2; mi++)
        #pragma unroll
        for (int ni = 0; ni < 8; ni++)
            #pragma unroll
            for (int r = 0; r < 4; r++) acc[mi][ni][r] = 0.f;

    int NC = K >> 5;
    gemm_load_chunk(smem, A, Bh, Bl, row0, col0, K, 0, 0, tid);
    asm volatile("cp.async.wait_group 0;" ::: "memory");
    __syncthreads();

    for (int c = 0; c < NC; c++) {
        int buf = c & 1;
        if (c + 1 < NC)
            gemm_load_chunk(smem, A, Bh, Bl, row0, col0, K, (c + 1) << 5, buf ^ 1, tid);

        char* base = smem + buf * 4 * GT_TILE;
        const __nv_bfloat16* aHi = (const __nv_bfloat16*)base;
        const __nv_bfloat16* aLo = (const __nv_bfloat16*)(base + GT_TILE);
        const __nv_bfloat16* bHi = (const __nv_bfloat16*)(base + 2 * GT_TILE);
        const __nv_bfloat16* bLo = (const __nv_bfloat16*)(base + 3 * GT_TILE);

        #pragma unroll
        for (int ks = 0; ks < 2; ks++) {
            int kb = ks * 16;
            unsigned ahi[2][4], alo[2][4];
            #pragma unroll
            for (int mi = 0; mi < 2; mi++) {
                int r = wm * 32 + mi * 16 + g;
                int c0i = kb + 2 * t;
                ahi[mi][0] = *(const unsigned*)&aHi[r * 40 + c0i];
                ahi[mi][1] = *(const unsigned*)&aHi[(r + 8) * 40 + c0i];
                ahi[mi][2] = *(const unsigned*)&aHi[r * 40 + c0i + 8];
                ahi[mi][3] = *(const unsigned*)&aHi[(r + 8) * 40 + c0i + 8];
                alo[mi][0] = *(const unsigned*)&aLo[r * 40 + c0i];
                alo[mi][1] = *(const unsigned*)&aLo[(r + 8) * 40 + c0i];
                alo[mi][2] = *(const unsigned*)&aLo[r * 40 + c0i + 8];
                alo[mi][3] = *(const unsigned*)&aLo[(r + 8) * 40 + c0i + 8];
            }
            #pragma unroll
            for (int ni = 0; ni < 8; ni++) {
                int n = wn * 64 + ni * 8 + g;
                int kk = kb + 2 * t;
                unsigned bh[2], bl[2];
                bh[0] = *(const unsigned*)&bHi[n * 40 + kk];
                bh[1] = *(const unsigned*)&bHi[n * 40 + kk + 8];
                bl[0] = *(const unsigned*)&bLo[n * 40 + kk];
                bl[1] = *(const unsigned*)&bLo[n * 40 + kk + 8];
                mma_bf16(acc[0][ni], ahi[0], bl);
                mma_bf16(acc[0][ni], alo[0], bh);
                mma_bf16(acc[0][ni], ahi[0], bh);
                mma_bf16(acc[1][ni], ahi[1], bl);
                mma_bf16(acc[1][ni], alo[1], bh);
                mma_bf16(acc[1][ni], ahi[1], bh);
            }
        }
        if (c + 1 < NC) {
            asm volatile("cp.async.wait_group 0;" ::: "memory");
            __syncthreads();
        }
    }

    // epilogue
    #pragma unroll
    for (int mi = 0; mi < 2; mi++) {
        #pragma unroll
        for (int ni = 0; ni < 8; ni++) {
            long r = row0 + wm * 32 + mi * 16 + g;
            int  cc = col0 + wn * 64 + ni * 8 + 2 * t;
            float b0 = bias[cc], b1 = bias[cc + 1];
            float2 v0 = make_float2(acc[mi][ni][0] + b0, acc[mi][ni][1] + b1);
            float2 v1 = make_float2(acc[mi][ni][2] + b0, acc[mi][ni][3] + b1);
            *(float2*)&C[r * Ntot + cc]       = v0;
            *(float2*)&C[(r + 8) * Ntot + cc] = v1;
        }
    }
}

// ---------------- positional attention via tensor cores ----------------
#define PA_SMEM_BYTES ((128 + 256 + 256) * 68 * 4)
__global__ void __launch_bounds__(256) pos_attn_mma(const float* __restrict__ qkv,
                                                    float* __restrict__ out)
{
    extern __shared__ float sm[];
    float* Qs = sm;              // [128][68]
    float* Ks = Qs + 128 * 68;   // [256][68]
    float* Vs = Ks + 256 * 68;   // [256][68]
    int tid = threadIdx.x, lane = tid & 31, w = tid >> 5;
    int qt = blockIdx.x, bh = blockIdx.y;
    int b = bh >> 4, h = bh & 15;

    const float* Qg = qkv + ((long)b * SS + qt * 128) * DD + h * DK;
    const float* Kg = qkv + (long)BB*SS*DD + (long)b * SS * DD + h * DK;
    const float* Vg = Kg + (long)BB*SS*DD;

    for (int idx = tid; idx < 128 * 16; idx += 256) {
        int r = idx >> 4, c = (idx & 15) * 4;
        float4 v = *(const float4*)&Qg[(long)r * DD + c];
        v.x = rtf32(v.x * 0.125f); v.y = rtf32(v.y * 0.125f);
        v.z = rtf32(v.z * 0.125f); v.w = rtf32(v.w * 0.125f);
        *(float4*)&Qs[r * 68 + c] = v;
    }
    for (int idx = tid; idx < 256 * 16; idx += 256) {
        int r = idx >> 4, c = (idx & 15) * 4;
        float4 kv = *(const float4*)&Kg[(long)r * DD + c];
        kv.x = rtf32(kv.x); kv.y = rtf32(kv.y); kv.z = rtf32(kv.z); kv.w = rtf32(kv.w);
        *(float4*)&Ks[r * 68 + c] = kv;
        float4 vv = *(const float4*)&Vg[(long)r * DD + c];
        vv.x = rtf32(vv.x); vv.y = rtf32(vv.y); vv.z = rtf32(vv.z); vv.w = rtf32(vv.w);
        *(float4*)&Vs[r * 68 + c] = vv;
    }
    __syncthreads();

    int g = lane >> 2, tig = lane & 3;

    unsigned qa[8][4];
    #pragma unroll
    for (int ks = 0; ks < 8; ks++) {
        const float* qb = Qs + (w * 16 + g) * 68 + ks * 8 + tig;
        qa[ks][0] = __float_as_uint(qb[0]);
        qa[ks][1] = __float_as_uint(qb[8 * 68]);
        qa[ks][2] = __float_as_uint(qb[4]);
        qa[ks][3] = __float_as_uint(qb[8 * 68 + 4]);
    }

    float sc[32][4];
    #pragma unroll
    for (int nf = 0; nf < 32; nf++) {
        sc[nf][0] = sc[nf][1] = sc[nf][2] = sc[nf][3] = 0.f;
        #pragma unroll
        for (int ks = 0; ks < 8; ks++) {
            unsigned bb[2];
            bb[0] = __float_as_uint(Ks[(nf * 8 + g) * 68 + ks * 8 + tig]);
            bb[1] = __float_as_uint(Ks[(nf * 8 + g) * 68 + ks * 8 + tig + 4]);
            mma_tf32(sc[nf], qa[ks], bb);
        }
    }

    float mx0 = -1e30f, mx1 = -1e30f;
    #pragma unroll
    for (int nf = 0; nf < 32; nf++) {
        mx0 = fmaxf(mx0, fmaxf(sc[nf][0], sc[nf][1]));
        mx1 = fmaxf(mx1, fmaxf(sc[nf][2], sc[nf][3]));
    }
    mx0 = fmaxf(mx0, __shfl_xor_sync(~0u, mx0, 1));
    mx0 = fmaxf(mx0, __shfl_xor_sync(~0u, mx0, 2));
    mx1 = fmaxf(mx1, __shfl_xor_sync(~0u, mx1, 1));
    mx1 = fmaxf(mx1, __shfl_xor_sync(~0u, mx1, 2));
    float sum0 = 0.f, sum1 = 0.f;
    #pragma unroll
    for (int nf = 0; nf < 32; nf++) {
        float p0 = __expf(sc[nf][0] - mx0), p1 = __expf(sc[nf][1] - mx0);
        float p2 = __expf(sc[nf][2] - mx1), p3 = __expf(sc[nf][3] - mx1);
        sum0 += p0 + p1; sum1 += p2 + p3;
        sc[nf][0] = rtf32(p0); sc[nf][1] = rtf32(p1);
        sc[nf][2] = rtf32(p2); sc[nf][3] = rtf32(p3);
    }
    sum0 += __shfl_xor_sync(~0u, sum0, 1); sum0 += __shfl_xor_sync(~0u, sum0, 2);
    sum1 += __shfl_xor_sync(~0u, sum1, 1); sum1 += __shfl_xor_sync(~0u, sum1, 2);

    int srcA = (lane & 28) | (tig >> 1);
    int srcB = srcA + 2;
    bool odd = tig & 1;
    #pragma unroll
    for (int f = 0; f < 32; f++) {
        float t0 = __shfl_sync(~0u, sc[f][0], srcA);
        float t1 = __shfl_sync(~0u, sc[f][1], srcA);
        float t2 = __shfl_sync(~0u, sc[f][2], srcA);
        float t3 = __shfl_sync(~0u, sc[f][3], srcA);
        float u0 = __shfl_sync(~0u, sc[f][0], srcB);
        float u1 = __shfl_sync(~0u, sc[f][1], srcB);
        float u2 = __shfl_sync(~0u, sc[f][2], srcB);
        float u3 = __shfl_sync(~0u, sc[f][3], srcB);
        sc[f][0] = odd ? t1 : t0;
        sc[f][1] = odd ? t3 : t2;
        sc[f][2] = odd ? u1 : u0;
        sc[f][3] = odd ? u3 : u2;
    }

    float o[8][4];
    #pragma unroll
    for (int nf = 0; nf < 8; nf++) { o[nf][0]=o[nf][1]=o[nf][2]=o[nf][3]=0.f; }
    #pragma unroll
    for (int nf = 0; nf < 8; nf++) {
        #pragma unroll
        for (int ks = 0; ks < 32; ks++) {
            unsigned bb[2];
            bb[0] = __float_as_uint(Vs[(ks * 8 + tig) * 68 + nf * 8 + g]);
            bb[1] = __float_as_uint(Vs[(ks * 8 + tig + 4) * 68 + nf * 8 + g]);
            mma_tf32_f(o[nf], sc[ks], bb);
        }
    }

    float inv0 = 1.f / sum0, inv1 = 1.f / sum1;
    long orow0 = ((long)b * SS + qt * 128 + w * 16 + g) * DD + h * DK;
    long orow1 = orow0 + 8L * DD;
    #pragma unroll
    for (int nf = 0; nf < 8; nf++) {
        int c = nf * 8 + 2 * tig;
        *(float2*)&out[orow0 + c] = make_float2(o[nf][0] * inv0, o[nf][1] * inv0);
        *(float2*)&out[orow1 + c] = make_float2(o[nf][2] * inv1, o[nf][3] * inv1);
    }
}

// ---------------- LayerNorm over sequence + transpose to [B,D,S], tiled ----------------
__global__ void __launch_bounds__(256) ln_c_kernel(const float* __restrict__ xin,
                                                   const float* __restrict__ ac,
                                                   const float* __restrict__ bcv,
                                                   float* __restrict__ xt)
{
    __shared__ float tile[32][257];
    __shared__ float red[8][32], red2[8][32];
    __shared__ float s_mean[32], s_inv[32];
    int b = blockIdx.y, d0 = blockIdx.x * 32;
    int tid = threadIdx.x, lane = tid & 31, w = tid >> 5;
    const float* base = xin + (long)b * SS * DD + d0;
    #pragma unroll 4
    for (int i = 0; i < 32; i++) {
        int s = w * 32 + i;
        tile[lane][s] = base[(long)s * DD + lane];
    }
    __syncthreads();
    {
        int d = tid & 31, ch = tid >> 5;
        float s1 = 0.f, s2 = 0.f;
        #pragma unroll
        for (int j = 0; j < 32; j++) {
            float v = tile[d][ch * 32 + j]; s1 += v; s2 += v * v;
        }
        red[ch][d] = s1; red2[ch][d] = s2;
    }
    __syncthreads();
    if (tid < 32) {
        float s1 = 0.f, s2 = 0.f;
        #pragma unroll
        for (int ch = 0; ch < 8; ch++) { s1 += red[ch][tid]; s2 += red2[ch][tid]; }
        float mean = s1 * (1.f / SS);
        float var  = (s2 - s1 * mean) * (1.f / (SS - 1));
        s_mean[tid] = mean;
        s_inv[tid]  = 1.f / (sqrtf(var) + EPSV);
    }
    __syncthreads();
    {
        int d = tid >> 3, s0 = (tid & 7) * 32;
        float mean = s_mean[d], inv = s_inv[d];
        float* dst = xt + ((long)b * DD + d0 + d) * SS;
        #pragma unroll
        for (int j = 0; j < 32; j += 4) {
            int s = s0 + j;
            float4 o;
            o.x = ac[s+0] * (tile[d][s+0] - mean) * inv + bcv[s+0];
            o.y = ac[s+1] * (tile[d][s+1] - mean) * inv + bcv[s+1];
            o.z = ac[s+2] * (tile[d][s+2] - mean) * inv + bcv[s+2];
            o.w = ac[s+3] * (tile[d][s+3] - mean) * inv + bcv[s+3];
            *(float4*)&dst[s] = o;
        }
    }
}

// ---------------- channel attention via tensor cores (flash, online softmax) ----------------
#define CA_SMEM_BYTES ((128 + 128 + 128) * 36 * 4)
__global__ void __launch_bounds__(256) chan_attn_mma(const float* __restrict__ qkvc,
                                                     float* __restrict__ xcatt)
{
    extern __shared__ float sm[];
    float* Qs = sm;              // [128][36]
    float* Ks = Qs + 128 * 36;
    float* Vs = Ks + 128 * 36;
    int tid = threadIdx.x, lane = tid & 31, w = tid >> 5;
    int qt = blockIdx.x, bh = blockIdx.y;
    int b = bh >> 3, h = bh & 7;
    const float scale = 0.1767766952966369f;

    const long qBase = (long)b * DD * SS + h * SK;
    const long nStride = (long)BB * DD * SS;

    for (int idx = tid; idx < 128 * 8; idx += 256) {
        int r = idx >> 3, c = (idx & 7) * 4;
        float4 v = *(const float4*)&qkvc[qBase + (long)(qt * 128 + r) * SS + c];
        v.x = rtf32(v.x * scale); v.y = rtf32(v.y * scale);
        v.z = rtf32(v.z * scale); v.w = rtf32(v.w * scale);
        *(float4*)&Qs[r * 36 + c] = v;
    }
    __syncthreads();

    int g = lane >> 2, tig = lane & 3;

    unsigned qa[4][4];
    #pragma unroll
    for (int ks = 0; ks < 4; ks++) {
        const float* qb = Qs + (w * 16 + g) * 36 + ks * 8 + tig;
        qa[ks][0] = __float_as_uint(qb[0]);
        qa[ks][1] = __float_as_uint(qb[8 * 36]);
        qa[ks][2] = __float_as_uint(qb[4]);
        qa[ks][3] = __float_as_uint(qb[8 * 36 + 4]);
    }

    float m0 = -1e30f, m1 = -1e30f, l0 = 0.f, l1 = 0.f;
    float o[4][4];
    #pragma unroll
    for (int nf = 0; nf < 4; nf++) { o[nf][0]=o[nf][1]=o[nf][2]=o[nf][3]=0.f; }

    int srcA = (lane & 28) | (tig >> 1);
    int srcB = srcA + 2;
    bool odd = tig & 1;

    for (int st = 0; st < 8; st++) {
        __syncthreads();
        for (int idx = tid; idx < 128 * 8; idx += 256) {
            int r = idx >> 3, c = (idx & 7) * 4;
            float4 kv = *(const float4*)&qkvc[qBase + nStride + (long)(st * 128 + r) * SS + c];
            kv.x = rtf32(kv.x); kv.y = rtf32(kv.y); kv.z = rtf32(kv.z); kv.w = rtf32(kv.w);
            *(float4*)&Ks[r * 36 + c] = kv;
            float4 vv = *(const float4*)&qkvc[qBase + 2 * nStride + (long)(st * 128 + r) * SS + c];
            vv.x = rtf32(vv.x); vv.y = rtf32(vv.y); vv.z = rtf32(vv.z); vv.w = rtf32(vv.w);
            *(float4*)&Vs[r * 36 + c] = vv;
        }
        __syncthreads();

        float sc[16][4];
        #pragma unroll
        for (int nf = 0; nf < 16; nf++) {
            sc[nf][0] = sc[nf][1] = sc[nf][2] = sc[nf][3] = 0.f;
            #pragma unroll
            for (int ks = 0; ks < 4; ks++) {
                unsigned bb[2];
                bb[0] = __float_as_uint(Ks[(nf * 8 + g) * 36 + ks * 8 + tig]);
                bb[1] = __float_as_uint(Ks[(nf * 8 + g) * 36 + ks * 8 + tig + 4]);
                mma_tf32(sc[nf], qa[ks], bb);
            }
        }
        float tm0 = -1e30f, tm1 = -1e30f;
        #pragma unroll
        for (int nf = 0; nf < 16; nf++) {
            tm0 = fmaxf(tm0, fmaxf(sc[nf][0], sc[nf][1]));
            tm1 = fmaxf(tm1, fmaxf(sc[nf][2], sc[nf][3]));
        }
        tm0 = fmaxf(tm0, __shfl_xor_sync(~0u, tm0, 1));
        tm0 = fmaxf(tm0, __shfl_xor_sync(~0u, tm0, 2));
        tm1 = fmaxf(tm1, __shfl_xor_sync(~0u, tm1, 1));
        tm1 = fmaxf(tm1, __shfl_xor_sync(~0u, tm1, 2));
        float nm0 = fmaxf(m0, tm0), nm1 = fmaxf(m1, tm1);
        float al0 = __expf(m0 - nm0), al1 = __expf(m1 - nm1);
        m0 = nm0; m1 = nm1;
        float ts0 = 0.f, ts1 = 0.f;
        #pragma unroll
        for (int nf = 0; nf < 16; nf++) {
            float p0 = __expf(sc[nf][0] - nm0), p1 = __expf(sc[nf][1] - nm0);
            float p2 = __expf(sc[nf][2] - nm1), p3 = __expf(sc[nf][3] - nm1);
            ts0 += p0 + p1; ts1 += p2 + p3;
            sc[nf][0] = rtf32(p0); sc[nf][1] = rtf32(p1);
            sc[nf][2] = rtf32(p2); sc[nf][3] = rtf32(p3);
        }
        ts0 += __shfl_xor_sync(~0u, ts0, 1); ts0 += __shfl_xor_sync(~0u, ts0, 2);
        ts1 += __shfl_xor_sync(~0u, ts1, 1); ts1 += __shfl_xor_sync(~0u, ts1, 2);
        l0 = l0 * al0 + ts0; l1 = l1 * al1 + ts1;
        #pragma unroll
        for (int nf = 0; nf < 4; nf++) {
            o[nf][0] *= al0; o[nf][1] *= al0;
            o[nf][2] *= al1; o[nf][3] *= al1;
        }
        #pragma unroll
        for (int f = 0; f < 16; f++) {
            float t0 = __shfl_sync(~0u, sc[f][0], srcA);
            float t1 = __shfl_sync(~0u, sc[f][1], srcA);
            float t2 = __shfl_sync(~0u, sc[f][2], srcA);
            float t3 = __shfl_sync(~0u, sc[f][3], srcA);
            float u0 = __shfl_sync(~0u, sc[f][0], srcB);
            float u1 = __shfl_sync(~0u, sc[f][1], srcB);
            float u2 = __shfl_sync(~0u, sc[f][2], srcB);
            float u3 = __shfl_sync(~0u, sc[f][3], srcB);
            sc[f][0] = odd ? t1 : t0;
            sc[f][1] = odd ? t3 : t2;
            sc[f][2] = odd ? u1 : u0;
            sc[f][3] = odd ? u3 : u2;
        }
        #pragma unroll
        for (int nf = 0; nf < 4; nf++) {
            #pragma unroll
            for (int ks = 0; ks < 16; ks++) {
                unsigned bb[2];
                bb[0] = __float_as_uint(Vs[(ks * 8 + tig) * 36 + nf * 8 + g]);
                bb[1] = __float_as_uint(Vs[(ks * 8 + tig + 4) * 36 + nf * 8 + g]);
                mma_tf32_f(o[nf], sc[ks], bb);
            }
        }
    }

    float inv0 = 1.f / l0, inv1 = 1.f / l1;
    long orow0 = ((long)b * DD + qt * 128 + w * 16 + g) * SS + h * SK;
    long orow1 = orow0 + 8L * SS;
    #pragma unroll
    for (int nf = 0; nf < 4; nf++) {
        int c = nf * 8 + 2 * tig;
        *(float2*)&xcatt[orow0 + c] = make_float2(o[nf][0] * inv0, o[nf][1] * inv0);
        *(float2*)&xcatt[orow1 + c] = make_float2(o[nf][2] * inv1, o[nf][3] * inv1);
    }
}

// ---------------- final transpose [B,D,S] -> [B,S,D] ----------------
__global__ void transpose_out(const float* __restrict__ in, float* __restrict__ out)
{
    __shared__ float tile[32][33];
    int b = blockIdx.z;
    int d0 = blockIdx.x * 32, s0 = blockIdx.y * 32;
    int tx = threadIdx.x, ty = threadIdx.y;
    #pragma unroll
    for (int k = 0; k < 32; k += 8)
        tile[ty+k][tx] = in[((long)b*DD + d0+ty+k) * SS + s0 + tx];
    __syncthreads();
    #pragma unroll
    for (int k = 0; k < 32; k += 8)
        out[((long)b*SS + s0+ty+k) * DD + d0 + tx] = tile[tx][ty+k];
}

// ---------------- launch ----------------
extern "C" void kernel_launch(void* const* d_in, const int* in_sizes, int n_in,
                              void* d_out, int out_size)
{
    const float* x   = (const float*)d_in[0];
    const float* Wp  = (const float*)d_in[1];
    const float* bp  = (const float*)d_in[2];
    const float* Wc  = (const float*)d_in[3];
    const float* bc  = (const float*)d_in[4];
    const float* ap  = (const float*)d_in[5];
    const float* bpp = (const float*)d_in[6];
    const float* ac  = (const float*)d_in[7];
    const float* bcc = (const float*)d_in[8];
    float* out = (float*)d_out;

    void *p_xp, *p_qkv, *p_xp2, *p_xt, *p_qkvc, *p_xcatt, *p_proj;
    void *p_wph, *p_wpl, *p_wch, *p_wcl;
    cudaGetSymbolAddress(&p_xp, g_xp);
    cudaGetSymbolAddress(&p_qkv, g_qkv);
    cudaGetSymbolAddress(&p_xp2, g_xp2);
    cudaGetSymbolAddress(&p_xt, g_xt);
    cudaGetSymbolAddress(&p_qkvc, g_qkvc);
    cudaGetSymbolAddress(&p_xcatt, g_xcatt);
    cudaGetSymbolAddress(&p_proj, g_proj);
    cudaGetSymbolAddress(&p_wph, g_WpT_hi);
    cudaGetSymbolAddress(&p_wpl, g_WpT_lo);
    cudaGetSymbolAddress(&p_wch, g_WcT_hi);
    cudaGetSymbolAddress(&p_wcl, g_WcT_lo);
    float* xp    = (float*)p_xp;
    float* qkv   = (float*)p_qkv;
    float* xp2   = (float*)p_xp2;
    float* xt    = (float*)p_xt;
    float* qkvc  = (float*)p_qkvc;
    float* xcatt = (float*)p_xcatt;
    float* proj  = (float*)p_proj;
    __nv_bfloat16* WpTh = (__nv_bfloat16*)p_wph;
    __nv_bfloat16* WpTl = (__nv_bfloat16*)p_wpl;
    __nv_bfloat16* WcTh = (__nv_bfloat16*)p_wch;
    __nv_bfloat16* WcTl = (__nv_bfloat16*)p_wcl;

    cudaFuncSetAttribute((const void*)pos_attn_mma,  cudaFuncAttributeMaxDynamicSharedMemorySize, PA_SMEM_BYTES);
    cudaFuncSetAttribute((const void*)chan_attn_mma, cudaFuncAttributeMaxDynamicSharedMemorySize, CA_SMEM_BYTES);
    cudaFuncSetAttribute((const void*)gemm_bf16,     cudaFuncAttributeMaxDynamicSharedMemorySize, GEMM_SMEM_BYTES);

    // 0. transpose + bf16 hi/lo split of weights
    split_transpose<<<dim3(DD/32, DD/32, 3), 256>>>(Wp, WpTh, WpTl, DD, DD);
    split_transpose<<<dim3(SS/32, SS/32, 4), 256>>>(Wc, WcTh, WcTl, SS, SS);

    // 1. LayerNorm over D
    ln_p_kernel<<<BB*SS, 256>>>(x, ap, bpp, xp);

    // 2. positional qkv (bf16x3): [4096,1024]x[1024,1024] batched 3
    gemm_bf16<<<dim3(DD/128, (BB*SS)/128, 3), 256, GEMM_SMEM_BYTES>>>(
        xp, WpTh, WpTl, bp, qkv, DD, DD,
        0L, (long)DD*DD, (long)DD, (long)BB*SS*DD);

    // 3. positional attention (tensor cores)
    pos_attn_mma<<<dim3(2, BB*HP), 256, PA_SMEM_BYTES>>>(qkv, xp2);

    // 4. LayerNorm over S + transpose to [B,D,S]
    ln_c_kernel<<<dim3(DD/32, BB), 256>>>(xp2, ac, bcc, xt);

    // 5. channel qkv (bf16x3): [16384,256]x[256,256] batched 3
    gemm_bf16<<<dim3(SS/128, (BB*DD)/128, 3), 256, GEMM_SMEM_BYTES>>>(
        xt, WcTh, WcTl, bc, qkvc, SS, SS,
        0L, (long)SS*SS, (long)SS, (long)BB*DD*SS);

    // 6. channel attention (tensor cores, flash)
    chan_attn_mma<<<dim3(8, BB*HC), 256, CA_SMEM_BYTES>>>(qkvc, xcatt);

    // 7. output projection (bf16x3) with Wc[3], bc[3]
    gemm_bf16<<<dim3(SS/128, (BB*DD)/128, 1), 256, GEMM_SMEM_BYTES>>>(
        xcatt, WcTh + 3L*SS*SS, WcTl + 3L*SS*SS, bc + 3L*SS, proj, SS, SS,
        0L, 0L, 0L, 0L);

    // 8. transpose [B,D,S] -> [B,S,D]
    transpose_out<<<dim3(DD/32, SS/32, BB), dim3(32, 8)>>>(proj, out);
}

// round 6
// speedup vs baseline: 3.0939x; 1.0018x over previous
#include <cuda_runtime.h>
#include <cuda_bf16.h>
#include <math.h>
#include <stdint.h>

// Problem constants
#define BB 16
#define SS 256
#define DD 1024
#define HP 16
#define DK 64
#define HC 8
#define SK 32
#define EPSV 1e-6f

// ---------------- scratch buffers (static device memory; no allocation) ----------------
__device__ __nv_bfloat16 g_xp_hi[BB*SS*DD];   // LN_p output hi  [B,S,D]
__device__ __nv_bfloat16 g_xp_lo[BB*SS*DD];   // LN_p output lo
__device__ float g_qkv[3*BB*SS*DD];           // pos qkv          [3,B,S,D]
__device__ float g_xp2[BB*SS*DD];             // pos attn out     [B,S,D]
__device__ __nv_bfloat16 g_xt_hi[BB*DD*SS];   // LN_c out (transposed) hi [B,D,S]
__device__ __nv_bfloat16 g_xt_lo[BB*DD*SS];
__device__ float g_qkvc[3*BB*DD*SS];          // channel qkv      [3,B,D,S]
__device__ __nv_bfloat16 g_xcatt_hi[BB*DD*SS]; // channel attn out hi [B,D,S]
__device__ __nv_bfloat16 g_xcatt_lo[BB*DD*SS];
__device__ float g_proj[BB*DD*SS];            // final proj (pre-transpose) [B,D,S]
__device__ __nv_bfloat16 g_WpT_hi[3*DD*DD];   // Wp transposed [N][K], bf16 hi
__device__ __nv_bfloat16 g_WpT_lo[3*DD*DD];
__device__ __nv_bfloat16 g_WcT_hi[4*SS*SS];
__device__ __nv_bfloat16 g_WcT_lo[4*SS*SS];

// ---------------- helpers ----------------
__device__ __forceinline__ float rtf32(float x) {
    unsigned u;
    asm("cvt.rna.tf32.f32 %0, %1;" : "=r"(u) : "f"(x));
    return __uint_as_float(u);
}

__device__ __forceinline__ void cp_async16(uint32_t smem, const void* g) {
    asm volatile("cp.async.cg.shared.global [%0], [%1], 16;" :: "r"(smem), "l"(g));
}

__device__ __forceinline__ void mma_tf32(float* c, const unsigned* a, const unsigned* b) {
    asm volatile("mma.sync.aligned.m16n8k8.row.col.f32.tf32.tf32.f32 "
        "{%0,%1,%2,%3}, {%4,%5,%6,%7}, {%8,%9}, {%0,%1,%2,%3};"
        : "+f"(c[0]), "+f"(c[1]), "+f"(c[2]), "+f"(c[3])
        : "r"(a[0]), "r"(a[1]), "r"(a[2]), "r"(a[3]), "r"(b[0]), "r"(b[1]));
}

__device__ __forceinline__ void mma_tf32_f(float* c, const float* a, const unsigned* b) {
    asm volatile("mma.sync.aligned.m16n8k8.row.col.f32.tf32.tf32.f32 "
        "{%0,%1,%2,%3}, {%4,%5,%6,%7}, {%8,%9}, {%0,%1,%2,%3};"
        : "+f"(c[0]), "+f"(c[1]), "+f"(c[2]), "+f"(c[3])
        : "r"(__float_as_uint(a[0])), "r"(__float_as_uint(a[1])),
          "r"(__float_as_uint(a[2])), "r"(__float_as_uint(a[3])),
          "r"(b[0]), "r"(b[1]));
}

__device__ __forceinline__ void mma_bf16(float* c, const unsigned* a, const unsigned* b) {
    asm volatile("mma.sync.aligned.m16n8k16.row.col.f32.bf16.bf16.f32 "
        "{%0,%1,%2,%3}, {%4,%5,%6,%7}, {%8,%9}, {%0,%1,%2,%3};"
        : "+f"(c[0]), "+f"(c[1]), "+f"(c[2]), "+f"(c[3])
        : "r"(a[0]), "r"(a[1]), "r"(a[2]), "r"(a[3]), "r"(b[0]), "r"(b[1]));
}

#define LDM4(r, addr) \
    asm volatile("ldmatrix.sync.aligned.m8n8.x4.shared.b16 {%0,%1,%2,%3}, [%4];" \
        : "=r"((r)[0]), "=r"((r)[1]), "=r"((r)[2]), "=r"((r)[3]) : "r"(addr))

__device__ __forceinline__ uint32_t smem_u32(const void* p) {
    uint32_t a;
    asm("{ .reg .u64 t; cvta.to.shared.u64 t, %1; cvt.u32.u64 %0, t; }" : "=r"(a) : "l"(p));
    return a;
}

__device__ __forceinline__ void split_bf16(float v, __nv_bfloat16& h, __nv_bfloat16& l) {
    h = __float2bfloat16(v);
    l = __float2bfloat16(v - __bfloat162float(h));
}

// ---------------- weight transpose + bf16 hi/lo split ----------------
// W: [batch][K][N] row-major fp32 -> hi/lo: [batch][N][K] bf16
__global__ void __launch_bounds__(256) split_transpose(const float* __restrict__ W,
                                                       __nv_bfloat16* __restrict__ hi,
                                                       __nv_bfloat16* __restrict__ lo,
                                                       int K, int N)
{
    __shared__ float t[32][33];
    int bz = blockIdx.z;
    W  += (long)bz * K * N;
    hi += (long)bz * K * N;
    lo += (long)bz * K * N;
    int n0 = blockIdx.x * 32, k0 = blockIdx.y * 32;
    int tx = threadIdx.x & 31, ty = threadIdx.x >> 5;  // 32 x 8
    #pragma unroll
    for (int j = 0; j < 32; j += 8)
        t[ty + j][tx] = W[(long)(k0 + ty + j) * N + n0 + tx];
    __syncthreads();
    #pragma unroll
    for (int j = 0; j < 32; j += 8) {
        float v = t[tx][ty + j];
        __nv_bfloat16 h, l;
        split_bf16(v, h, l);
        long o = (long)(n0 + ty + j) * K + k0 + tx;
        hi[o] = h; lo[o] = l;
    }
}

// ---------------- LayerNorm over channels -> bf16 hi/lo ----------------
__global__ void __launch_bounds__(256) ln_p_kernel(const float* __restrict__ x,
                                                   const float* __restrict__ ap,
                                                   const float* __restrict__ bp,
                                                   __nv_bfloat16* __restrict__ hi,
                                                   __nv_bfloat16* __restrict__ lo)
{
    long row = blockIdx.x;
    const float* xr = x + row * DD;
    int tid = threadIdx.x;
    float s = 0.f, s2 = 0.f;
    #pragma unroll
    for (int i = tid; i < DD; i += 256) { float v = xr[i]; s += v; s2 += v*v; }
    __shared__ float rs[8], rs2[8];
    #pragma unroll
    for (int o = 16; o; o >>= 1) { s += __shfl_xor_sync(~0u, s, o); s2 += __shfl_xor_sync(~0u, s2, o); }
    if ((tid & 31) == 0) { rs[tid>>5] = s; rs2[tid>>5] = s2; }
    __syncthreads();
    s = 0.f; s2 = 0.f;
    #pragma unroll
    for (int w = 0; w < 8; w++) { s += rs[w]; s2 += rs2[w]; }
    float mean = s * (1.f / DD);
    float var  = (s2 - s * mean) * (1.f / (DD - 1));
    float inv  = 1.f / (sqrtf(var) + EPSV);
    #pragma unroll
    for (int i = tid; i < DD; i += 256) {
        float v = xr[i];
        float vout = ap[i] * (v - mean) * inv + bp[i];
        __nv_bfloat16 h, l;
        split_bf16(vout, h, l);
        hi[row * DD + i] = h;
        lo[row * DD + i] = l;
    }
}

// ---------------- bf16x3 tensor GEMM, all-cp.async, ldmatrix fragments ----------------
// C = A * B^T + bias. Ah/Al [M][K] bf16, Bh/Bl [N][K] bf16 (K-major).
// BM=128 BN=128 BK=32, 256 threads, warp tile 32x64. smem rows stride 40 bf16.
#define GT_TILE 10240
#define GEMM_SMEM_BYTES (8 * GT_TILE)

__device__ __forceinline__ void gemm_load_chunk(
    uint32_t sbase,
    const __nv_bfloat16* __restrict__ Ah, const __nv_bfloat16* __restrict__ Al,
    const __nv_bfloat16* __restrict__ Bh, const __nv_bfloat16* __restrict__ Bl,
    long row0, int col0, int K, int k0, int buf, int tid)
{
    uint32_t base = sbase + buf * 4 * GT_TILE;
    #pragma unroll
    for (int i = 0; i < 2; i++) {
        int idx = tid + i * 256;
        int r = idx >> 2, sgi = idx & 3;
        uint32_t d = base + (uint32_t)(r * 80 + sgi * 16);
        long aoff = (row0 + r) * (long)K + k0 + sgi * 8;
        long boff = (long)(col0 + r) * K + k0 + sgi * 8;
        cp_async16(d,               &Ah[aoff]);
        cp_async16(d + GT_TILE,     &Al[aoff]);
        cp_async16(d + 2*GT_TILE,   &Bh[boff]);
        cp_async16(d + 3*GT_TILE,   &Bl[boff]);
    }
    asm volatile("cp.async.commit_group;");
}

__global__ void __launch_bounds__(256, 2) gemm_bf16(const __nv_bfloat16* __restrict__ Ah,
                                                    const __nv_bfloat16* __restrict__ Al,
                                                    const __nv_bfloat16* __restrict__ Bh,
                                                    const __nv_bfloat16* __restrict__ Bl,
                                                    const float* __restrict__ bias,
                                                    float* __restrict__ C,
                                                    int K, int Ntot,
                                                    long aB, long bB, long biasB, long cB)
{
    extern __shared__ char smem[];
    uint32_t sbase = smem_u32(smem);
    int tid  = threadIdx.x;
    int warp = tid >> 5, lane = tid & 31;
    int wm = warp & 3, wn = warp >> 2;
    int g = lane >> 2, t = lane & 3;
    int bz = blockIdx.z;
    Ah   += (long)bz * aB;
    Al   += (long)bz * aB;
    Bh   += (long)bz * bB;
    Bl   += (long)bz * bB;
    bias += (long)bz * biasB;
    C    += (long)bz * cB;
    long row0 = (long)blockIdx.y * 128;
    int  col0 = blockIdx.x * 128;

    // per-thread ldmatrix base addresses (buf 0, ks 0)
    // A x4: lanes 0-7 -> rows m+0..7 (k lo), 8-15 -> m+8..15 (k lo), 16-23 -> m+0..7 (k hi), 24-31 -> m+8..15 (k hi)
    uint32_t aAddr = sbase +
        (uint32_t)(((wm * 32 + (lane & 7) + ((lane >> 3) & 1) * 8) * 40 + (lane >> 4) * 8) * 2);
    // B x4: lanes 0-7 -> n+0..7 (k lo), 8-15 -> n+0..7 (k hi), 16-23 -> n+8..15 (k lo), 24-31 -> n+8..15 (k hi)
    uint32_t bAddr = sbase + 2 * GT_TILE +
        (uint32_t)(((wn * 64 + (lane & 7) + ((lane >> 4) & 1) * 8) * 40 + ((lane >> 3) & 1) * 8) * 2);

    float acc[2][8][4];
    #pragma unroll
    for (int mi = 0; mi < 2; mi++)
        #pragma unroll
        for (int ni = 0; ni < 8; ni++)
            #pragma unroll
            for (int r = 0; r < 4; r++) acc[mi][ni][r] = 0.f;

    int NC = K >> 5;
    gemm_load_chunk(sbase, Ah, Al, Bh, Bl, row0, col0, K, 0, 0, tid);
    asm volatile("cp.async.wait_group 0;" ::: "memory");
    __syncthreads();

    for (int c = 0; c < NC; c++) {
        int buf = c & 1;
        if (c + 1 < NC)
            gemm_load_chunk(sbase, Ah, Al, Bh, Bl, row0, col0, K, (c + 1) << 5, buf ^ 1, tid);

        uint32_t bo = buf * 4 * GT_TILE;
        #pragma unroll
        for (int ks = 0; ks < 2; ks++) {
            uint32_t ak = aAddr + bo + ks * 32;
            unsigned ah0[4], ah1[4], al0[4], al1[4];
            LDM4(ah0, ak);
            LDM4(ah1, ak + 1280);
            LDM4(al0, ak + GT_TILE);
            LDM4(al1, ak + GT_TILE + 1280);
            #pragma unroll
            for (int gi = 0; gi < 4; gi++) {
                uint32_t bk = bAddr + bo + ks * 32 + gi * 1280;
                unsigned bh[4], bl[4];
                LDM4(bh, bk);
                LDM4(bl, bk + GT_TILE);
                int n0 = gi * 2, n1 = gi * 2 + 1;
                mma_bf16(acc[0][n0], ah0, bh);
                mma_bf16(acc[0][n0], al0, bh);
                mma_bf16(acc[0][n0], ah0, bl);
                mma_bf16(acc[1][n0], ah1, bh);
                mma_bf16(acc[1][n0], al1, bh);
                mma_bf16(acc[1][n0], ah1, bl);
                mma_bf16(acc[0][n1], ah0, bh + 2);
                mma_bf16(acc[0][n1], al0, bh + 2);
                mma_bf16(acc[0][n1], ah0, bl + 2);
                mma_bf16(acc[1][n1], ah1, bh + 2);
                mma_bf16(acc[1][n1], al1, bh + 2);
                mma_bf16(acc[1][n1], ah1, bl + 2);
            }
        }
        if (c + 1 < NC) {
            asm volatile("cp.async.wait_group 0;" ::: "memory");
            __syncthreads();
        }
    }

    // epilogue
    #pragma unroll
    for (int mi = 0; mi < 2; mi++) {
        #pragma unroll
        for (int ni = 0; ni < 8; ni++) {
            long r = row0 + wm * 32 + mi * 16 + g;
            int  cc = col0 + wn * 64 + ni * 8 + 2 * t;
            float b0 = bias[cc], b1 = bias[cc + 1];
            float2 v0 = make_float2(acc[mi][ni][0] + b0, acc[mi][ni][1] + b1);
            float2 v1 = make_float2(acc[mi][ni][2] + b0, acc[mi][ni][3] + b1);
            *(float2*)&C[r * Ntot + cc]       = v0;
            *(float2*)&C[(r + 8) * Ntot + cc] = v1;
        }
    }
}

// ---------------- positional attention via tensor cores ----------------
#define PA_SMEM_BYTES ((128 + 256 + 256) * 68 * 4)
__global__ void __launch_bounds__(256) pos_attn_mma(const float* __restrict__ qkv,
                                                    float* __restrict__ out)
{
    extern __shared__ float sm[];
    float* Qs = sm;              // [128][68]
    float* Ks = Qs + 128 * 68;   // [256][68]
    float* Vs = Ks + 256 * 68;   // [256][68]
    int tid = threadIdx.x, lane = tid & 31, w = tid >> 5;
    int qt = blockIdx.x, bh = blockIdx.y;
    int b = bh >> 4, h = bh & 15;

    const float* Qg = qkv + ((long)b * SS + qt * 128) * DD + h * DK;
    const float* Kg = qkv + (long)BB*SS*DD + (long)b * SS * DD + h * DK;
    const float* Vg = Kg + (long)BB*SS*DD;

    for (int idx = tid; idx < 128 * 16; idx += 256) {
        int r = idx >> 4, c = (idx & 15) * 4;
        float4 v = *(const float4*)&Qg[(long)r * DD + c];
        v.x = rtf32(v.x * 0.125f); v.y = rtf32(v.y * 0.125f);
        v.z = rtf32(v.z * 0.125f); v.w = rtf32(v.w * 0.125f);
        *(float4*)&Qs[r * 68 + c] = v;
    }
    for (int idx = tid; idx < 256 * 16; idx += 256) {
        int r = idx >> 4, c = (idx & 15) * 4;
        float4 kv = *(const float4*)&Kg[(long)r * DD + c];
        kv.x = rtf32(kv.x); kv.y = rtf32(kv.y); kv.z = rtf32(kv.z); kv.w = rtf32(kv.w);
        *(float4*)&Ks[r * 68 + c] = kv;
        float4 vv = *(const float4*)&Vg[(long)r * DD + c];
        vv.x = rtf32(vv.x); vv.y = rtf32(vv.y); vv.z = rtf32(vv.z); vv.w = rtf32(vv.w);
        *(float4*)&Vs[r * 68 + c] = vv;
    }
    __syncthreads();

    int g = lane >> 2, tig = lane & 3;

    unsigned qa[8][4];
    #pragma unroll
    for (int ks = 0; ks < 8; ks++) {
        const float* qb = Qs + (w * 16 + g) * 68 + ks * 8 + tig;
        qa[ks][0] = __float_as_uint(qb[0]);
        qa[ks][1] = __float_as_uint(qb[8 * 68]);
        qa[ks][2] = __float_as_uint(qb[4]);
        qa[ks][3] = __float_as_uint(qb[8 * 68 + 4]);
    }

    float sc[32][4];
    #pragma unroll
    for (int nf = 0; nf < 32; nf++) {
        sc[nf][0] = sc[nf][1] = sc[nf][2] = sc[nf][3] = 0.f;
        #pragma unroll
        for (int ks = 0; ks < 8; ks++) {
            unsigned bb[2];
            bb[0] = __float_as_uint(Ks[(nf * 8 + g) * 68 + ks * 8 + tig]);
            bb[1] = __float_as_uint(Ks[(nf * 8 + g) * 68 + ks * 8 + tig + 4]);
            mma_tf32(sc[nf], qa[ks], bb);
        }
    }

    float mx0 = -1e30f, mx1 = -1e30f;
    #pragma unroll
    for (int nf = 0; nf < 32; nf++) {
        mx0 = fmaxf(mx0, fmaxf(sc[nf][0], sc[nf][1]));
        mx1 = fmaxf(mx1, fmaxf(sc[nf][2], sc[nf][3]));
    }
    mx0 = fmaxf(mx0, __shfl_xor_sync(~0u, mx0, 1));
    mx0 = fmaxf(mx0, __shfl_xor_sync(~0u, mx0, 2));
    mx1 = fmaxf(mx1, __shfl_xor_sync(~0u, mx1, 1));
    mx1 = fmaxf(mx1, __shfl_xor_sync(~0u, mx1, 2));
    float sum0 = 0.f, sum1 = 0.f;
    #pragma unroll
    for (int nf = 0; nf < 32; nf++) {
        float p0 = __expf(sc[nf][0] - mx0), p1 = __expf(sc[nf][1] - mx0);
        float p2 = __expf(sc[nf][2] - mx1), p3 = __expf(sc[nf][3] - mx1);
        sum0 += p0 + p1; sum1 += p2 + p3;
        sc[nf][0] = rtf32(p0); sc[nf][1] = rtf32(p1);
        sc[nf][2] = rtf32(p2); sc[nf][3] = rtf32(p3);
    }
    sum0 += __shfl_xor_sync(~0u, sum0, 1); sum0 += __shfl_xor_sync(~0u, sum0, 2);
    sum1 += __shfl_xor_sync(~0u, sum1, 1); sum1 += __shfl_xor_sync(~0u, sum1, 2);

    int srcA = (lane & 28) | (tig >> 1);
    int srcB = srcA + 2;
    bool odd = tig & 1;
    #pragma unroll
    for (int f = 0; f < 32; f++) {
        float t0 = __shfl_sync(~0u, sc[f][0], srcA);
        float t1 = __shfl_sync(~0u, sc[f][1], srcA);
        float t2 = __shfl_sync(~0u, sc[f][2], srcA);
        float t3 = __shfl_sync(~0u, sc[f][3], srcA);
        float u0 = __shfl_sync(~0u, sc[f][0], srcB);
        float u1 = __shfl_sync(~0u, sc[f][1], srcB);
        float u2 = __shfl_sync(~0u, sc[f][2], srcB);
        float u3 = __shfl_sync(~0u, sc[f][3], srcB);
        sc[f][0] = odd ? t1 : t0;
        sc[f][1] = odd ? t3 : t2;
        sc[f][2] = odd ? u1 : u0;
        sc[f][3] = odd ? u3 : u2;
    }

    float o[8][4];
    #pragma unroll
    for (int nf = 0; nf < 8; nf++) { o[nf][0]=o[nf][1]=o[nf][2]=o[nf][3]=0.f; }
    #pragma unroll
    for (int nf = 0; nf < 8; nf++) {
        #pragma unroll
        for (int ks = 0; ks < 32; ks++) {
            unsigned bb[2];
            bb[0] = __float_as_uint(Vs[(ks * 8 + tig) * 68 + nf * 8 + g]);
            bb[1] = __float_as_uint(Vs[(ks * 8 + tig + 4) * 68 + nf * 8 + g]);
            mma_tf32_f(o[nf], sc[ks], bb);
        }
    }

    float inv0 = 1.f / sum0, inv1 = 1.f / sum1;
    long orow0 = ((long)b * SS + qt * 128 + w * 16 + g) * DD + h * DK;
    long orow1 = orow0 + 8L * DD;
    #pragma unroll
    for (int nf = 0; nf < 8; nf++) {
        int c = nf * 8 + 2 * tig;
        *(float2*)&out[orow0 + c] = make_float2(o[nf][0] * inv0, o[nf][1] * inv0);
        *(float2*)&out[orow1 + c] = make_float2(o[nf][2] * inv1, o[nf][3] * inv1);
    }
}

// ---------------- LayerNorm over sequence + transpose -> bf16 hi/lo [B,D,S] ----------------
__global__ void __launch_bounds__(256) ln_c_kernel(const float* __restrict__ xin,
                                                   const float* __restrict__ ac,
                                                   const float* __restrict__ bcv,
                                                   __nv_bfloat16* __restrict__ hi,
                                                   __nv_bfloat16* __restrict__ lo)
{
    __shared__ float tile[32][257];
    __shared__ float red[8][32], red2[8][32];
    __shared__ float s_mean[32], s_inv[32];
    int b = blockIdx.y, d0 = blockIdx.x * 32;
    int tid = threadIdx.x, lane = tid & 31, w = tid >> 5;
    const float* base = xin + (long)b * SS * DD + d0;
    #pragma unroll 4
    for (int i = 0; i < 32; i++) {
        int s = w * 32 + i;
        tile[lane][s] = base[(long)s * DD + lane];
    }
    __syncthreads();
    {
        int d = tid & 31, ch = tid >> 5;
        float s1 = 0.f, s2 = 0.f;
        #pragma unroll
        for (int j = 0; j < 32; j++) {
            float v = tile[d][ch * 32 + j]; s1 += v; s2 += v * v;
        }
        red[ch][d] = s1; red2[ch][d] = s2;
    }
    __syncthreads();
    if (tid < 32) {
        float s1 = 0.f, s2 = 0.f;
        #pragma unroll
        for (int ch = 0; ch < 8; ch++) { s1 += red[ch][tid]; s2 += red2[ch][tid]; }
        float mean = s1 * (1.f / SS);
        float var  = (s2 - s1 * mean) * (1.f / (SS - 1));
        s_mean[tid] = mean;
        s_inv[tid]  = 1.f / (sqrtf(var) + EPSV);
    }
    __syncthreads();
    {
        int d = tid >> 3, s0 = (tid & 7) * 32;
        float mean = s_mean[d], inv = s_inv[d];
        long dstBase = ((long)b * DD + d0 + d) * SS;
        #pragma unroll
        for (int j = 0; j < 32; j += 2) {
            int s = s0 + j;
            float v0 = ac[s+0] * (tile[d][s+0] - mean) * inv + bcv[s+0];
            float v1 = ac[s+1] * (tile[d][s+1] - mean) * inv + bcv[s+1];
            __nv_bfloat16 h0, l0, h1, l1;
            split_bf16(v0, h0, l0);
            split_bf16(v1, h1, l1);
            *(__nv_bfloat162*)&hi[dstBase + s] = __nv_bfloat162(h0, h1);
            *(__nv_bfloat162*)&lo[dstBase + s] = __nv_bfloat162(l0, l1);
        }
    }
}

// ---------------- channel attention via tensor cores (flash, online softmax) ----------------
#define CA_SMEM_BYTES ((128 + 128 + 128) * 36 * 4)
__global__ void __launch_bounds__(256) chan_attn_mma(const float* __restrict__ qkvc,
                                                     __nv_bfloat16* __restrict__ xc_hi,
                                                     __nv_bfloat16* __restrict__ xc_lo)
{
    extern __shared__ float sm[];
    float* Qs = sm;              // [128][36]
    float* Ks = Qs + 128 * 36;
    float* Vs = Ks + 128 * 36;
    int tid = threadIdx.x, lane = tid & 31, w = tid >> 5;
    int qt = blockIdx.x, bh = blockIdx.y;
    int b = bh >> 3, h = bh & 7;
    const float scale = 0.1767766952966369f;

    const long qBase = (long)b * DD * SS + h * SK;
    const long nStride = (long)BB * DD * SS;

    for (int idx = tid; idx < 128 * 8; idx += 256) {
        int r = idx >> 3, c = (idx & 7) * 4;
        float4 v = *(const float4*)&qkvc[qBase + (long)(qt * 128 + r) * SS + c];
        v.x = rtf32(v.x * scale); v.y = rtf32(v.y * scale);
        v.z = rtf32(v.z * scale); v.w = rtf32(v.w * scale);
        *(float4*)&Qs[r * 36 + c] = v;
    }
    __syncthreads();

    int g = lane >> 2, tig = lane & 3;

    unsigned qa[4][4];
    #pragma unroll
    for (int ks = 0; ks < 4; ks++) {
        const float* qb = Qs + (w * 16 + g) * 36 + ks * 8 + tig;
        qa[ks][0] = __float_as_uint(qb[0]);
        qa[ks][1] = __float_as_uint(qb[8 * 36]);
        qa[ks][2] = __float_as_uint(qb[4]);
        qa[ks][3] = __float_as_uint(qb[8 * 36 + 4]);
    }

    float m0 = -1e30f, m1 = -1e30f, l0 = 0.f, l1 = 0.f;
    float o[4][4];
    #pragma unroll
    for (int nf = 0; nf < 4; nf++) { o[nf][0]=o[nf][1]=o[nf][2]=o[nf][3]=0.f; }

    int srcA = (lane & 28) | (tig >> 1);
    int srcB = srcA + 2;
    bool odd = tig & 1;

    for (int st = 0; st < 8; st++) {
        __syncthreads();
        for (int idx = tid; idx < 128 * 8; idx += 256) {
            int r = idx >> 3, c = (idx & 7) * 4;
            float4 kv = *(const float4*)&qkvc[qBase + nStride + (long)(st * 128 + r) * SS + c];
            kv.x = rtf32(kv.x); kv.y = rtf32(kv.y); kv.z = rtf32(kv.z); kv.w = rtf32(kv.w);
            *(float4*)&Ks[r * 36 + c] = kv;
            float4 vv = *(const float4*)&qkvc[qBase + 2 * nStride + (long)(st * 128 + r) * SS + c];
            vv.x = rtf32(vv.x); vv.y = rtf32(vv.y); vv.z = rtf32(vv.z); vv.w = rtf32(vv.w);
            *(float4*)&Vs[r * 36 + c] = vv;
        }
        __syncthreads();

        float sc[16][4];
        #pragma unroll
        for (int nf = 0; nf < 16; nf++) {
            sc[nf][0] = sc[nf][1] = sc[nf][2] = sc[nf][3] = 0.f;
            #pragma unroll
            for (int ks = 0; ks < 4; ks++) {
                unsigned bb[2];
                bb[0] = __float_as_uint(Ks[(nf * 8 + g) * 36 + ks * 8 + tig]);
                bb[1] = __float_as_uint(Ks[(nf * 8 + g) * 36 + ks * 8 + tig + 4]);
                mma_tf32(sc[nf], qa[ks], bb);
            }
        }
        float tm0 = -1e30f, tm1 = -1e30f;
        #pragma unroll
        for (int nf = 0; nf < 16; nf++) {
            tm0 = fmaxf(tm0, fmaxf(sc[nf][0], sc[nf][1]));
            tm1 = fmaxf(tm1, fmaxf(sc[nf][2], sc[nf][3]));
        }
        tm0 = fmaxf(tm0, __shfl_xor_sync(~0u, tm0, 1));
        tm0 = fmaxf(tm0, __shfl_xor_sync(~0u, tm0, 2));
        tm1 = fmaxf(tm1, __shfl_xor_sync(~0u, tm1, 1));
        tm1 = fmaxf(tm1, __shfl_xor_sync(~0u, tm1, 2));
        float nm0 = fmaxf(m0, tm0), nm1 = fmaxf(m1, tm1);
        float al0 = __expf(m0 - nm0), al1 = __expf(m1 - nm1);
        m0 = nm0; m1 = nm1;
        float ts0 = 0.f, ts1 = 0.f;
        #pragma unroll
        for (int nf = 0; nf < 16; nf++) {
            float p0 = __expf(sc[nf][0] - nm0), p1 = __expf(sc[nf][1] - nm0);
            float p2 = __expf(sc[nf][2] - nm1), p3 = __expf(sc[nf][3] - nm1);
            ts0 += p0 + p1; ts1 += p2 + p3;
            sc[nf][0] = rtf32(p0); sc[nf][1] = rtf32(p1);
            sc[nf][2] = rtf32(p2); sc[nf][3] = rtf32(p3);
        }
        ts0 += __shfl_xor_sync(~0u, ts0, 1); ts0 += __shfl_xor_sync(~0u, ts0, 2);
        ts1 += __shfl_xor_sync(~0u, ts1, 1); ts1 += __shfl_xor_sync(~0u, ts1, 2);
        l0 = l0 * al0 + ts0; l1 = l1 * al1 + ts1;
        #pragma unroll
        for (int nf = 0; nf < 4; nf++) {
            o[nf][0] *= al0; o[nf][1] *= al0;
            o[nf][2] *= al1; o[nf][3] *= al1;
        }
        #pragma unroll
        for (int f = 0; f < 16; f++) {
            float t0 = __shfl_sync(~0u, sc[f][0], srcA);
            float t1 = __shfl_sync(~0u, sc[f][1], srcA);
            float t2 = __shfl_sync(~0u, sc[f][2], srcA);
            float t3 = __shfl_sync(~0u, sc[f][3], srcA);
            float u0 = __shfl_sync(~0u, sc[f][0], srcB);
            float u1 = __shfl_sync(~0u, sc[f][1], srcB);
            float u2 = __shfl_sync(~0u, sc[f][2], srcB);
            float u3 = __shfl_sync(~0u, sc[f][3], srcB);
            sc[f][0] = odd ? t1 : t0;
            sc[f][1] = odd ? t3 : t2;
            sc[f][2] = odd ? u1 : u0;
            sc[f][3] = odd ? u3 : u2;
        }
        #pragma unroll
        for (int nf = 0; nf < 4; nf++) {
            #pragma unroll
            for (int ks = 0; ks < 16; ks++) {
                unsigned bb[2];
                bb[0] = __float_as_uint(Vs[(ks * 8 + tig) * 36 + nf * 8 + g]);
                bb[1] = __float_as_uint(Vs[(ks * 8 + tig + 4) * 36 + nf * 8 + g]);
                mma_tf32_f(o[nf], sc[ks], bb);
            }
        }
    }

    float inv0 = 1.f / l0, inv1 = 1.f / l1;
    long orow0 = ((long)b * DD + qt * 128 + w * 16 + g) * SS + h * SK;
    long orow1 = orow0 + 8L * SS;
    #pragma unroll
    for (int nf = 0; nf < 4; nf++) {
        int c = nf * 8 + 2 * tig;
        float v0 = o[nf][0] * inv0, v1 = o[nf][1] * inv0;
        float v2 = o[nf][2] * inv1, v3 = o[nf][3] * inv1;
        __nv_bfloat16 h0, lo0, h1, lo1, h2, lo2, h3, lo3;
        split_bf16(v0, h0, lo0); split_bf16(v1, h1, lo1);
        split_bf16(v2, h2, lo2); split_bf16(v3, h3, lo3);
        *(__nv_bfloat162*)&xc_hi[orow0 + c] = __nv_bfloat162(h0, h1);
        *(__nv_bfloat162*)&xc_lo[orow0 + c] = __nv_bfloat162(lo0, lo1);
        *(__nv_bfloat162*)&xc_hi[orow1 + c] = __nv_bfloat162(h2, h3);
        *(__nv_bfloat162*)&xc_lo[orow1 + c] = __nv_bfloat162(lo2, lo3);
    }
}

// ---------------- final transpose [B,D,S] -> [B,S,D] ----------------
__global__ void transpose_out(const float* __restrict__ in, float* __restrict__ out)
{
    __shared__ float tile[32][33];
    int b = blockIdx.z;
    int d0 = blockIdx.x * 32, s0 = blockIdx.y * 32;
    int tx = threadIdx.x, ty = threadIdx.y;
    #pragma unroll
    for (int k = 0; k < 32; k += 8)
        tile[ty+k][tx] = in[((long)b*DD + d0+ty+k) * SS + s0 + tx];
    __syncthreads();
    #pragma unroll
    for (int k = 0; k < 32; k += 8)
        out[((long)b*SS + s0+ty+k) * DD + d0 + tx] = tile[tx][ty+k];
}

// ---------------- launch ----------------
extern "C" void kernel_launch(void* const* d_in, const int* in_sizes, int n_in,
                              void* d_out, int out_size)
{
    const float* x   = (const float*)d_in[0];
    const float* Wp  = (const float*)d_in[1];
    const float* bp  = (const float*)d_in[2];
    const float* Wc  = (const float*)d_in[3];
    const float* bc  = (const float*)d_in[4];
    const float* ap  = (const float*)d_in[5];
    const float* bpp = (const float*)d_in[6];
    const float* ac  = (const float*)d_in[7];
    const float* bcc = (const float*)d_in[8];
    float* out = (float*)d_out;

    void *p_xph, *p_xpl, *p_qkv, *p_xp2, *p_xth, *p_xtl, *p_qkvc, *p_xch, *p_xcl, *p_proj;
    void *p_wph, *p_wpl, *p_wch, *p_wcl;
    cudaGetSymbolAddress(&p_xph, g_xp_hi);
    cudaGetSymbolAddress(&p_xpl, g_xp_lo);
    cudaGetSymbolAddress(&p_qkv, g_qkv);
    cudaGetSymbolAddress(&p_xp2, g_xp2);
    cudaGetSymbolAddress(&p_xth, g_xt_hi);
    cudaGetSymbolAddress(&p_xtl, g_xt_lo);
    cudaGetSymbolAddress(&p_qkvc, g_qkvc);
    cudaGetSymbolAddress(&p_xch, g_xcatt_hi);
    cudaGetSymbolAddress(&p_xcl, g_xcatt_lo);
    cudaGetSymbolAddress(&p_proj, g_proj);
    cudaGetSymbolAddress(&p_wph, g_WpT_hi);
    cudaGetSymbolAddress(&p_wpl, g_WpT_lo);
    cudaGetSymbolAddress(&p_wch, g_WcT_hi);
    cudaGetSymbolAddress(&p_wcl, g_WcT_lo);
    __nv_bfloat16* xpH = (__nv_bfloat16*)p_xph;
    __nv_bfloat16* xpL = (__nv_bfloat16*)p_xpl;
    float* qkv   = (float*)p_qkv;
    float* xp2   = (float*)p_xp2;
    __nv_bfloat16* xtH = (__nv_bfloat16*)p_xth;
    __nv_bfloat16* xtL = (__nv_bfloat16*)p_xtl;
    float* qkvc  = (float*)p_qkvc;
    __nv_bfloat16* xcH = (__nv_bfloat16*)p_xch;
    __nv_bfloat16* xcL = (__nv_bfloat16*)p_xcl;
    float* proj  = (float*)p_proj;
    __nv_bfloat16* WpTh = (__nv_bfloat16*)p_wph;
    __nv_bfloat16* WpTl = (__nv_bfloat16*)p_wpl;
    __nv_bfloat16* WcTh = (__nv_bfloat16*)p_wch;
    __nv_bfloat16* WcTl = (__nv_bfloat16*)p_wcl;

    cudaFuncSetAttribute((const void*)pos_attn_mma,  cudaFuncAttributeMaxDynamicSharedMemorySize, PA_SMEM_BYTES);
    cudaFuncSetAttribute((const void*)chan_attn_mma, cudaFuncAttributeMaxDynamicSharedMemorySize, CA_SMEM_BYTES);
    cudaFuncSetAttribute((const void*)gemm_bf16,     cudaFuncAttributeMaxDynamicSharedMemorySize, GEMM_SMEM_BYTES);

    // 0. transpose + bf16 hi/lo split of weights
    split_transpose<<<dim3(DD/32, DD/32, 3), 256>>>(Wp, WpTh, WpTl, DD, DD);
    split_transpose<<<dim3(SS/32, SS/32, 4), 256>>>(Wc, WcTh, WcTl, SS, SS);

    // 1. LayerNorm over D -> bf16 hi/lo
    ln_p_kernel<<<BB*SS, 256>>>(x, ap, bpp, xpH, xpL);

    // 2. positional qkv (bf16x3): [4096,1024]x[1024,1024] batched 3
    gemm_bf16<<<dim3(DD/128, (BB*SS)/128, 3), 256, GEMM_SMEM_BYTES>>>(
        xpH, xpL, WpTh, WpTl, bp, qkv, DD, DD,
        0L, (long)DD*DD, (long)DD, (long)BB*SS*DD);

    // 3. positional attention (tensor cores)
    pos_attn_mma<<<dim3(2, BB*HP), 256, PA_SMEM_BYTES>>>(qkv, xp2);

    // 4. LayerNorm over S + transpose -> bf16 hi/lo [B,D,S]
    ln_c_kernel<<<dim3(DD/32, BB), 256>>>(xp2, ac, bcc, xtH, xtL);

    // 5. channel qkv (bf16x3): [16384,256]x[256,256] batched 3
    gemm_bf16<<<dim3(SS/128, (BB*DD)/128, 3), 256, GEMM_SMEM_BYTES>>>(
        xtH, xtL, WcTh, WcTl, bc, qkvc, SS, SS,
        0L, (long)SS*SS, (long)SS, (long)BB*DD*SS);

    // 6. channel attention (tensor cores, flash) -> bf16 hi/lo
    chan_attn_mma<<<dim3(8, BB*HC), 256, CA_SMEM_BYTES>>>(qkvc, xcH, xcL);

    // 7. output projection (bf16x3) with Wc[3], bc[3]
    gemm_bf16<<<dim3(SS/128, (BB*DD)/128, 1), 256, GEMM_SMEM_BYTES>>>(
        xcH, xcL, WcTh + 3L*SS*SS, WcTl + 3L*SS*SS, bc + 3L*SS, proj, SS, SS,
        0L, 0L, 0L, 0L);

    // 8. transpose [B,D,S] -> [B,S,D]
    transpose_out<<<dim3(DD/32, SS/32, BB), dim3(32, 8)>>>(proj, out);
}

// round 7
// speedup vs baseline: 4.6397x; 1.4996x over previous
#include <cuda_runtime.h>
#include <cuda_fp16.h>
#include <math.h>
#include <stdint.h>

// Problem constants
#define BB 16
#define SS 256
#define DD 1024
#define HP 16
#define DK 64
#define HC 8
#define SK 32
#define EPSV 1e-6f

// ---------------- scratch buffers (static device memory; no allocation) ----------------
__device__ __half g_xp[BB*SS*DD];        // LN_p output fp16 [B,S,D]
__device__ float  g_qkv[3*BB*SS*DD];     // pos qkv           [3,B,S,D]
__device__ float  g_xp2[BB*SS*DD];       // pos attn out      [B,S,D]
__device__ __half g_xt[BB*DD*SS];        // LN_c out (transposed) fp16 [B,D,S]
__device__ float  g_qkvc[3*BB*DD*SS];    // channel qkv       [3,B,D,S]
__device__ __half g_xc[BB*DD*SS];        // channel attn out fp16 [B,D,S]
__device__ __half g_WpT_hi[3*DD*DD];     // Wp transposed [N][K], fp16 hi
__device__ __half g_WpT_lo[3*DD*DD];     // fp16 lo (residual)
__device__ __half g_WcT_hi[4*SS*SS];
__device__ __half g_WcT_lo[4*SS*SS];

// ---------------- helpers ----------------
__device__ __forceinline__ void cp_async16(uint32_t smem, const void* g) {
    asm volatile("cp.async.cg.shared.global [%0], [%1], 16;" :: "r"(smem), "l"(g));
}

__device__ __forceinline__ void mma_f16(float* c, const unsigned* a, const unsigned* b) {
    asm volatile("mma.sync.aligned.m16n8k16.row.col.f32.f16.f16.f32 "
        "{%0,%1,%2,%3}, {%4,%5,%6,%7}, {%8,%9}, {%0,%1,%2,%3};"
        : "+f"(c[0]), "+f"(c[1]), "+f"(c[2]), "+f"(c[3])
        : "r"(a[0]), "r"(a[1]), "r"(a[2]), "r"(a[3]), "r"(b[0]), "r"(b[1]));
}

#define LDM4(r, addr) \
    asm volatile("ldmatrix.sync.aligned.m8n8.x4.shared.b16 {%0,%1,%2,%3}, [%4];" \
        : "=r"((r)[0]), "=r"((r)[1]), "=r"((r)[2]), "=r"((r)[3]) : "r"(addr))

__device__ __forceinline__ uint32_t smem_u32(const void* p) {
    uint32_t a;
    asm("{ .reg .u64 t; cvta.to.shared.u64 t, %1; cvt.u32.u64 %0, t; }" : "=r"(a) : "l"(p));
    return a;
}

__device__ __forceinline__ unsigned packh2(float x, float y) {
    __half2 h = __floats2half2_rn(x, y);
    return *(unsigned*)&h;
}

// ---------------- weight transpose + fp16 hi/lo split ----------------
// W: [batch][K][N] row-major fp32 -> hi/lo: [batch][N][K] fp16
__global__ void __launch_bounds__(256) split_transpose(const float* __restrict__ W,
                                                       __half* __restrict__ hi,
                                                       __half* __restrict__ lo,
                                                       int K, int N)
{
    __shared__ float t[32][33];
    int bz = blockIdx.z;
    W  += (long)bz * K * N;
    hi += (long)bz * K * N;
    lo += (long)bz * K * N;
    int n0 = blockIdx.x * 32, k0 = blockIdx.y * 32;
    int tx = threadIdx.x & 31, ty = threadIdx.x >> 5;  // 32 x 8
    #pragma unroll
    for (int j = 0; j < 32; j += 8)
        t[ty + j][tx] = W[(long)(k0 + ty + j) * N + n0 + tx];
    __syncthreads();
    #pragma unroll
    for (int j = 0; j < 32; j += 8) {
        float v = t[tx][ty + j];
        __half h = __float2half_rn(v);
        __half l = __float2half_rn(v - __half2float(h));
        long o = (long)(n0 + ty + j) * K + k0 + tx;
        hi[o] = h; lo[o] = l;
    }
}

// ---------------- LayerNorm over channels -> fp16 ----------------
__global__ void __launch_bounds__(256) ln_p_kernel(const float* __restrict__ x,
                                                   const float* __restrict__ ap,
                                                   const float* __restrict__ bp,
                                                   __half* __restrict__ xo)
{
    long row = blockIdx.x;
    const float* xr = x + row * DD;
    int tid = threadIdx.x;
    float s = 0.f, s2 = 0.f;
    #pragma unroll
    for (int i = tid; i < DD; i += 256) { float v = xr[i]; s += v; s2 += v*v; }
    __shared__ float rs[8], rs2[8];
    #pragma unroll
    for (int o = 16; o; o >>= 1) { s += __shfl_xor_sync(~0u, s, o); s2 += __shfl_xor_sync(~0u, s2, o); }
    if ((tid & 31) == 0) { rs[tid>>5] = s; rs2[tid>>5] = s2; }
    __syncthreads();
    s = 0.f; s2 = 0.f;
    #pragma unroll
    for (int w = 0; w < 8; w++) { s += rs[w]; s2 += rs2[w]; }
    float mean = s * (1.f / DD);
    float var  = (s2 - s * mean) * (1.f / (DD - 1));
    float inv  = 1.f / (sqrtf(var) + EPSV);
    #pragma unroll
    for (int i = tid; i < DD; i += 256) {
        float v = xr[i];
        xo[row * DD + i] = __float2half_rn(ap[i] * (v - mean) * inv + bp[i]);
    }
}

// ---------------- fp16x2 tensor GEMM: C = A * (Bhi+Blo)^T + bias ----------------
// A [M][K] fp16, Bh/Bl [N][K] fp16 (K-major). BM=128 BN=128 BK=32, 256 threads,
// warp tile 32x64. smem rows stride 40 halfs. 6 tiles x 10240 B; epilogue may
// reuse smem as a 128x129 fp32 transpose buffer (66048 B) when transOut=1.
#define GT_TILE 10240
#define GEMM_SMEM_BYTES 66048

__device__ __forceinline__ void gemm_load_chunk(
    uint32_t sbase,
    const __half* __restrict__ A,
    const __half* __restrict__ Bh, const __half* __restrict__ Bl,
    long row0, int col0, int K, int k0, int buf, int tid)
{
    uint32_t base = sbase + buf * 3 * GT_TILE;
    #pragma unroll
    for (int i = 0; i < 2; i++) {
        int idx = tid + i * 256;
        int r = idx >> 2, sgi = idx & 3;
        uint32_t d = base + (uint32_t)(r * 80 + sgi * 16);
        long aoff = (row0 + r) * (long)K + k0 + sgi * 8;
        long boff = (long)(col0 + r) * K + k0 + sgi * 8;
        cp_async16(d,               &A[aoff]);
        cp_async16(d + GT_TILE,     &Bh[boff]);
        cp_async16(d + 2*GT_TILE,   &Bl[boff]);
    }
    asm volatile("cp.async.commit_group;");
}

__global__ void __launch_bounds__(256, 2) gemm_f16(const __half* __restrict__ A,
                                                   const __half* __restrict__ Bh,
                                                   const __half* __restrict__ Bl,
                                                   const float* __restrict__ bias,
                                                   float* __restrict__ C,
                                                   int K, int Ntot,
                                                   long aB, long bB, long biasB, long cB,
                                                   int transOut)
{
    extern __shared__ char smem[];
    uint32_t sbase = smem_u32(smem);
    int tid  = threadIdx.x;
    int warp = tid >> 5, lane = tid & 31;
    int wm = warp & 3, wn = warp >> 2;
    int g = lane >> 2, t = lane & 3;
    int bz = blockIdx.z;
    A    += (long)bz * aB;
    Bh   += (long)bz * bB;
    Bl   += (long)bz * bB;
    bias += (long)bz * biasB;
    C    += (long)bz * cB;
    long row0 = (long)blockIdx.y * 128;
    int  col0 = blockIdx.x * 128;

    // per-thread ldmatrix base addresses (buf 0, ks 0)
    uint32_t aAddr = sbase +
        (uint32_t)(((wm * 32 + (lane & 7) + ((lane >> 3) & 1) * 8) * 40 + (lane >> 4) * 8) * 2);
    uint32_t bAddr = sbase + GT_TILE +
        (uint32_t)(((wn * 64 + (lane & 7) + ((lane >> 4) & 1) * 8) * 40 + ((lane >> 3) & 1) * 8) * 2);

    float acc[2][8][4];
    #pragma unroll
    for (int mi = 0; mi < 2; mi++)
        #pragma unroll
        for (int ni = 0; ni < 8; ni++)
            #pragma unroll
            for (int r = 0; r < 4; r++) acc[mi][ni][r] = 0.f;

    int NC = K >> 5;
    gemm_load_chunk(sbase, A, Bh, Bl, row0, col0, K, 0, 0, tid);
    asm volatile("cp.async.wait_group 0;" ::: "memory");
    __syncthreads();

    for (int c = 0; c < NC; c++) {
        int buf = c & 1;
        if (c + 1 < NC)
            gemm_load_chunk(sbase, A, Bh, Bl, row0, col0, K, (c + 1) << 5, buf ^ 1, tid);

        uint32_t bo = buf * 3 * GT_TILE;
        #pragma unroll
        for (int ks = 0; ks < 2; ks++) {
            uint32_t ak = aAddr + bo + ks * 32;
            unsigned a0[4], a1[4];
            LDM4(a0, ak);
            LDM4(a1, ak + 1280);
            #pragma unroll
            for (int gi = 0; gi < 4; gi++) {
                uint32_t bk = bAddr + bo + ks * 32 + gi * 1280;
                unsigned bh[4], bl[4];
                LDM4(bh, bk);
                LDM4(bl, bk + GT_TILE);
                int n0 = gi * 2, n1 = gi * 2 + 1;
                mma_f16(acc[0][n0], a0, bh);
                mma_f16(acc[0][n0], a0, bl);
                mma_f16(acc[1][n0], a1, bh);
                mma_f16(acc[1][n0], a1, bl);
                mma_f16(acc[0][n1], a0, bh + 2);
                mma_f16(acc[0][n1], a0, bl + 2);
                mma_f16(acc[1][n1], a1, bh + 2);
                mma_f16(acc[1][n1], a1, bl + 2);
            }
        }
        if (c + 1 < NC) {
            asm volatile("cp.async.wait_group 0;" ::: "memory");
            __syncthreads();
        }
    }

    if (!transOut) {
        #pragma unroll
        for (int mi = 0; mi < 2; mi++) {
            #pragma unroll
            for (int ni = 0; ni < 8; ni++) {
                long r = row0 + wm * 32 + mi * 16 + g;
                int  cc = col0 + wn * 64 + ni * 8 + 2 * t;
                float b0 = bias[cc], b1 = bias[cc + 1];
                float2 v0 = make_float2(acc[mi][ni][0] + b0, acc[mi][ni][1] + b1);
                float2 v1 = make_float2(acc[mi][ni][2] + b0, acc[mi][ni][3] + b1);
                *(float2*)&C[r * Ntot + cc]       = v0;
                *(float2*)&C[(r + 8) * Ntot + cc] = v1;
            }
        }
    } else {
        // stage to smem [s][d] then write out[b][s][d] coalesced
        __syncthreads();
        float* Ts = (float*)smem;
        int b = (int)(row0 >> 10), d0 = (int)(row0 & 1023);
        #pragma unroll
        for (int mi = 0; mi < 2; mi++) {
            #pragma unroll
            for (int ni = 0; ni < 8; ni++) {
                int rl = wm * 32 + mi * 16 + g;
                int cl = wn * 64 + ni * 8 + 2 * t;
                float b0 = bias[col0 + cl], b1 = bias[col0 + cl + 1];
                Ts[cl * 129 + rl]           = acc[mi][ni][0] + b0;
                Ts[(cl + 1) * 129 + rl]     = acc[mi][ni][1] + b1;
                Ts[cl * 129 + rl + 8]       = acc[mi][ni][2] + b0;
                Ts[(cl + 1) * 129 + rl + 8] = acc[mi][ni][3] + b1;
            }
        }
        __syncthreads();
        #pragma unroll
        for (int j = 0; j < 16; j++) {
            int sl = j * 8 + (tid >> 5);
            int d4 = (tid & 31) * 4;
            float4 o = make_float4(Ts[sl * 129 + d4], Ts[sl * 129 + d4 + 1],
                                   Ts[sl * 129 + d4 + 2], Ts[sl * 129 + d4 + 3]);
            *(float4*)&C[((long)(b * SS + col0 + sl)) * DD + d0 + d4] = o;
        }
    }
}

// ---------------- positional attention via fp16 tensor cores ----------------
// Qs [128][72] fp16, Ks [256][72] fp16, Vt [64][264] fp16 (V transposed)
#define PA_SMEM_BYTES ((128*72 + 256*72 + 64*264) * 2)
__global__ void __launch_bounds__(256) pos_attn_mma(const float* __restrict__ qkv,
                                                    float* __restrict__ out)
{
    extern __shared__ __half smh[];
    __half* Qs = smh;                 // [128][72]
    __half* Ks = Qs + 128 * 72;       // [256][72]
    __half* Vt = Ks + 256 * 72;       // [64][264]
    int tid = threadIdx.x, lane = tid & 31, w = tid >> 5;
    int qt = blockIdx.x, bh = blockIdx.y;
    int b = bh >> 4, h = bh & 15;

    const float* Qg = qkv + ((long)b * SS + qt * 128) * DD + h * DK;
    const float* Kg = qkv + (long)BB*SS*DD + (long)b * SS * DD + h * DK;
    const float* Vg = Kg + (long)BB*SS*DD;

    for (int idx = tid; idx < 128 * 16; idx += 256) {
        int r = idx >> 4, c = (idx & 15) * 4;
        float4 v = *(const float4*)&Qg[(long)r * DD + c];
        *(__half2*)&Qs[r * 72 + c]     = __floats2half2_rn(v.x * 0.125f, v.y * 0.125f);
        *(__half2*)&Qs[r * 72 + c + 2] = __floats2half2_rn(v.z * 0.125f, v.w * 0.125f);
    }
    for (int idx = tid; idx < 256 * 16; idx += 256) {
        int r = idx >> 4, c = (idx & 15) * 4;
        float4 kv = *(const float4*)&Kg[(long)r * DD + c];
        *(__half2*)&Ks[r * 72 + c]     = __floats2half2_rn(kv.x, kv.y);
        *(__half2*)&Ks[r * 72 + c + 2] = __floats2half2_rn(kv.z, kv.w);
        float4 vv = *(const float4*)&Vg[(long)r * DD + c];
        Vt[(c+0) * 264 + r] = __float2half_rn(vv.x);
        Vt[(c+1) * 264 + r] = __float2half_rn(vv.y);
        Vt[(c+2) * 264 + r] = __float2half_rn(vv.z);
        Vt[(c+3) * 264 + r] = __float2half_rn(vv.w);
    }
    __syncthreads();

    int g = lane >> 2, tig = lane & 3;
    int row = w * 16 + g;

    // Q a-frags: 4 k16 steps over DK=64
    unsigned qa[4][4];
    #pragma unroll
    for (int ks = 0; ks < 4; ks++) {
        const __half* qb = Qs + row * 72 + ks * 16 + 2 * tig;
        qa[ks][0] = *(const unsigned*)qb;
        qa[ks][1] = *(const unsigned*)(qb + 8 * 72);
        qa[ks][2] = *(const unsigned*)(qb + 8);
        qa[ks][3] = *(const unsigned*)(qb + 8 * 72 + 8);
    }

    // scores: 16 rows x 256 cols per warp
    float sc[32][4];
    #pragma unroll
    for (int nf = 0; nf < 32; nf++) {
        sc[nf][0] = sc[nf][1] = sc[nf][2] = sc[nf][3] = 0.f;
        const __half* kb = Ks + (nf * 8 + g) * 72 + 2 * tig;
        #pragma unroll
        for (int ks = 0; ks < 4; ks++) {
            unsigned bb[2];
            bb[0] = *(const unsigned*)(kb + ks * 16);
            bb[1] = *(const unsigned*)(kb + ks * 16 + 8);
            mma_f16(sc[nf], qa[ks], bb);
        }
    }

    // exact softmax (rows g and g+8)
    float mx0 = -1e30f, mx1 = -1e30f;
    #pragma unroll
    for (int nf = 0; nf < 32; nf++) {
        mx0 = fmaxf(mx0, fmaxf(sc[nf][0], sc[nf][1]));
        mx1 = fmaxf(mx1, fmaxf(sc[nf][2], sc[nf][3]));
    }
    mx0 = fmaxf(mx0, __shfl_xor_sync(~0u, mx0, 1));
    mx0 = fmaxf(mx0, __shfl_xor_sync(~0u, mx0, 2));
    mx1 = fmaxf(mx1, __shfl_xor_sync(~0u, mx1, 1));
    mx1 = fmaxf(mx1, __shfl_xor_sync(~0u, mx1, 2));
    float sum0 = 0.f, sum1 = 0.f;
    #pragma unroll
    for (int nf = 0; nf < 32; nf++) {
        float p0 = __expf(sc[nf][0] - mx0), p1 = __expf(sc[nf][1] - mx0);
        float p2 = __expf(sc[nf][2] - mx1), p3 = __expf(sc[nf][3] - mx1);
        sum0 += p0 + p1; sum1 += p2 + p3;
        sc[nf][0] = p0; sc[nf][1] = p1; sc[nf][2] = p2; sc[nf][3] = p3;
    }
    sum0 += __shfl_xor_sync(~0u, sum0, 1); sum0 += __shfl_xor_sync(~0u, sum0, 2);
    sum1 += __shfl_xor_sync(~0u, sum1, 1); sum1 += __shfl_xor_sync(~0u, sum1, 2);

    // pack P c-frags -> fp16 a-frags in place (no shuffles)
    #pragma unroll
    for (int ksi = 0; ksi < 16; ksi++) {
        unsigned p0 = packh2(sc[2*ksi][0],   sc[2*ksi][1]);
        unsigned p1 = packh2(sc[2*ksi][2],   sc[2*ksi][3]);
        unsigned p2 = packh2(sc[2*ksi+1][0], sc[2*ksi+1][1]);
        unsigned p3 = packh2(sc[2*ksi+1][2], sc[2*ksi+1][3]);
        unsigned* d = (unsigned*)sc[2*ksi];
        d[0] = p0; d[1] = p1; d[2] = p2; d[3] = p3;
    }

    // PV: O[16][64] per warp
    float o[8][4];
    #pragma unroll
    for (int nf = 0; nf < 8; nf++) { o[nf][0]=o[nf][1]=o[nf][2]=o[nf][3]=0.f; }
    #pragma unroll
    for (int nf = 0; nf < 8; nf++) {
        const __half* vb = Vt + (nf * 8 + g) * 264 + 2 * tig;
        #pragma unroll
        for (int ksi = 0; ksi < 16; ksi++) {
            unsigned bb[2];
            bb[0] = *(const unsigned*)(vb + ksi * 16);
            bb[1] = *(const unsigned*)(vb + ksi * 16 + 8);
            mma_f16(o[nf], (const unsigned*)sc[2*ksi], bb);
        }
    }

    float inv0 = 1.f / sum0, inv1 = 1.f / sum1;
    long orow0 = ((long)b * SS + qt * 128 + row) * DD + h * DK;
    long orow1 = orow0 + 8L * DD;
    #pragma unroll
    for (int nf = 0; nf < 8; nf++) {
        int c = nf * 8 + 2 * tig;
        *(float2*)&out[orow0 + c] = make_float2(o[nf][0] * inv0, o[nf][1] * inv0);
        *(float2*)&out[orow1 + c] = make_float2(o[nf][2] * inv1, o[nf][3] * inv1);
    }
}

// ---------------- LayerNorm over sequence + transpose -> fp16 [B,D,S] ----------------
__global__ void __launch_bounds__(256) ln_c_kernel(const float* __restrict__ xin,
                                                   const float* __restrict__ ac,
                                                   const float* __restrict__ bcv,
                                                   __half* __restrict__ xo)
{
    __shared__ float tile[32][257];
    __shared__ float red[8][32], red2[8][32];
    __shared__ float s_mean[32], s_inv[32];
    int b = blockIdx.y, d0 = blockIdx.x * 32;
    int tid = threadIdx.x, lane = tid & 31, w = tid >> 5;
    const float* base = xin + (long)b * SS * DD + d0;
    #pragma unroll 4
    for (int i = 0; i < 32; i++) {
        int s = w * 32 + i;
        tile[lane][s] = base[(long)s * DD + lane];
    }
    __syncthreads();
    {
        int d = tid & 31, ch = tid >> 5;
        float s1 = 0.f, s2 = 0.f;
        #pragma unroll
        for (int j = 0; j < 32; j++) {
            float v = tile[d][ch * 32 + j]; s1 += v; s2 += v * v;
        }
        red[ch][d] = s1; red2[ch][d] = s2;
    }
    __syncthreads();
    if (tid < 32) {
        float s1 = 0.f, s2 = 0.f;
        #pragma unroll
        for (int ch = 0; ch < 8; ch++) { s1 += red[ch][tid]; s2 += red2[ch][tid]; }
        float mean = s1 * (1.f / SS);
        float var  = (s2 - s1 * mean) * (1.f / (SS - 1));
        s_mean[tid] = mean;
        s_inv[tid]  = 1.f / (sqrtf(var) + EPSV);
    }
    __syncthreads();
    {
        int d = tid >> 3, s0 = (tid & 7) * 32;
        float mean = s_mean[d], inv = s_inv[d];
        long dstBase = ((long)b * DD + d0 + d) * SS;
        #pragma unroll
        for (int j = 0; j < 32; j += 2) {
            int s = s0 + j;
            float v0 = ac[s+0] * (tile[d][s+0] - mean) * inv + bcv[s+0];
            float v1 = ac[s+1] * (tile[d][s+1] - mean) * inv + bcv[s+1];
            *(__half2*)&xo[dstBase + s] = __floats2half2_rn(v0, v1);
        }
    }
}

// ---------------- channel attention via fp16 tensor cores (flash) ----------------
// Qs [128][40], Ks [128][40], Vt [32][136] fp16
#define CA_SMEM_BYTES ((128*40 + 128*40 + 32*136) * 2)
__global__ void __launch_bounds__(256) chan_attn_mma(const float* __restrict__ qkvc,
                                                     __half* __restrict__ xc)
{
    extern __shared__ __half smh[];
    __half* Qs = smh;                // [128][40]
    __half* Ks = Qs + 128 * 40;
    __half* Vt = Ks + 128 * 40;      // [32][136]
    int tid = threadIdx.x, lane = tid & 31, w = tid >> 5;
    int qt = blockIdx.x, bh = blockIdx.y;
    int b = bh >> 3, h = bh & 7;
    const float scale = 0.1767766952966369f;   // 1/sqrt(32)

    const long qBase = (long)b * DD * SS + h * SK;
    const long nStride = (long)BB * DD * SS;

    for (int idx = tid; idx < 128 * 8; idx += 256) {
        int r = idx >> 3, c = (idx & 7) * 4;
        float4 v = *(const float4*)&qkvc[qBase + (long)(qt * 128 + r) * SS + c];
        *(__half2*)&Qs[r * 40 + c]     = __floats2half2_rn(v.x * scale, v.y * scale);
        *(__half2*)&Qs[r * 40 + c + 2] = __floats2half2_rn(v.z * scale, v.w * scale);
    }
    __syncthreads();

    int g = lane >> 2, tig = lane & 3;
    int row = w * 16 + g;

    unsigned qa[2][4];
    #pragma unroll
    for (int ks = 0; ks < 2; ks++) {
        const __half* qb = Qs + row * 40 + ks * 16 + 2 * tig;
        qa[ks][0] = *(const unsigned*)qb;
        qa[ks][1] = *(const unsigned*)(qb + 8 * 40);
        qa[ks][2] = *(const unsigned*)(qb + 8);
        qa[ks][3] = *(const unsigned*)(qb + 8 * 40 + 8);
    }

    float m0 = -1e30f, m1 = -1e30f, l0 = 0.f, l1 = 0.f;
    float o[4][4];
    #pragma unroll
    for (int nf = 0; nf < 4; nf++) { o[nf][0]=o[nf][1]=o[nf][2]=o[nf][3]=0.f; }

    for (int st = 0; st < 8; st++) {
        __syncthreads();
        for (int idx = tid; idx < 128 * 8; idx += 256) {
            int r = idx >> 3, c = (idx & 7) * 4;
            float4 kv = *(const float4*)&qkvc[qBase + nStride + (long)(st * 128 + r) * SS + c];
            *(__half2*)&Ks[r * 40 + c]     = __floats2half2_rn(kv.x, kv.y);
            *(__half2*)&Ks[r * 40 + c + 2] = __floats2half2_rn(kv.z, kv.w);
            float4 vv = *(const float4*)&qkvc[qBase + 2 * nStride + (long)(st * 128 + r) * SS + c];
            Vt[(c+0) * 136 + r] = __float2half_rn(vv.x);
            Vt[(c+1) * 136 + r] = __float2half_rn(vv.y);
            Vt[(c+2) * 136 + r] = __float2half_rn(vv.z);
            Vt[(c+3) * 136 + r] = __float2half_rn(vv.w);
        }
        __syncthreads();

        float sc[16][4];
        #pragma unroll
        for (int nf = 0; nf < 16; nf++) {
            sc[nf][0] = sc[nf][1] = sc[nf][2] = sc[nf][3] = 0.f;
            const __half* kb = Ks + (nf * 8 + g) * 40 + 2 * tig;
            #pragma unroll
            for (int ks = 0; ks < 2; ks++) {
                unsigned bb[2];
                bb[0] = *(const unsigned*)(kb + ks * 16);
                bb[1] = *(const unsigned*)(kb + ks * 16 + 8);
                mma_f16(sc[nf], qa[ks], bb);
            }
        }
        float tm0 = -1e30f, tm1 = -1e30f;
        #pragma unroll
        for (int nf = 0; nf < 16; nf++) {
            tm0 = fmaxf(tm0, fmaxf(sc[nf][0], sc[nf][1]));
            tm1 = fmaxf(tm1, fmaxf(sc[nf][2], sc[nf][3]));
        }
        tm0 = fmaxf(tm0, __shfl_xor_sync(~0u, tm0, 1));
        tm0 = fmaxf(tm0, __shfl_xor_sync(~0u, tm0, 2));
        tm1 = fmaxf(tm1, __shfl_xor_sync(~0u, tm1, 1));
        tm1 = fmaxf(tm1, __shfl_xor_sync(~0u, tm1, 2));
        float nm0 = fmaxf(m0, tm0), nm1 = fmaxf(m1, tm1);
        float al0 = __expf(m0 - nm0), al1 = __expf(m1 - nm1);
        m0 = nm0; m1 = nm1;
        float ts0 = 0.f, ts1 = 0.f;
        #pragma unroll
        for (int nf = 0; nf < 16; nf++) {
            float p0 = __expf(sc[nf][0] - nm0), p1 = __expf(sc[nf][1] - nm0);
            float p2 = __expf(sc[nf][2] - nm1), p3 = __expf(sc[nf][3] - nm1);
            ts0 += p0 + p1; ts1 += p2 + p3;
            sc[nf][0] = p0; sc[nf][1] = p1; sc[nf][2] = p2; sc[nf][3] = p3;
        }
        ts0 += __shfl_xor_sync(~0u, ts0, 1); ts0 += __shfl_xor_sync(~0u, ts0, 2);
        ts1 += __shfl_xor_sync(~0u, ts1, 1); ts1 += __shfl_xor_sync(~0u, ts1, 2);
        l0 = l0 * al0 + ts0; l1 = l1 * al1 + ts1;
        #pragma unroll
        for (int nf = 0; nf < 4; nf++) {
            o[nf][0] *= al0; o[nf][1] *= al0;
            o[nf][2] *= al1; o[nf][3] *= al1;
        }
        // pack P -> fp16 a-frags in place
        #pragma unroll
        for (int ksi = 0; ksi < 8; ksi++) {
            unsigned p0 = packh2(sc[2*ksi][0],   sc[2*ksi][1]);
            unsigned p1 = packh2(sc[2*ksi][2],   sc[2*ksi][3]);
            unsigned p2 = packh2(sc[2*ksi+1][0], sc[2*ksi+1][1]);
            unsigned p3 = packh2(sc[2*ksi+1][2], sc[2*ksi+1][3]);
            unsigned* d = (unsigned*)sc[2*ksi];
            d[0] = p0; d[1] = p1; d[2] = p2; d[3] = p3;
        }
        #pragma unroll
        for (int nf = 0; nf < 4; nf++) {
            const __half* vb = Vt + (nf * 8 + g) * 136 + 2 * tig;
            #pragma unroll
            for (int ksi = 0; ksi < 8; ksi++) {
                unsigned bb[2];
                bb[0] = *(const unsigned*)(vb + ksi * 16);
                bb[1] = *(const unsigned*)(vb + ksi * 16 + 8);
                mma_f16(o[nf], (const unsigned*)sc[2*ksi], bb);
            }
        }
    }

    float inv0 = 1.f / l0, inv1 = 1.f / l1;
    long orow0 = ((long)b * DD + qt * 128 + row) * SS + h * SK;
    long orow1 = orow0 + 8L * SS;
    #pragma unroll
    for (int nf = 0; nf < 4; nf++) {
        int c = nf * 8 + 2 * tig;
        *(__half2*)&xc[orow0 + c] = __floats2half2_rn(o[nf][0] * inv0, o[nf][1] * inv0);
        *(__half2*)&xc[orow1 + c] = __floats2half2_rn(o[nf][2] * inv1, o[nf][3] * inv1);
    }
}

// ---------------- launch ----------------
extern "C" void kernel_launch(void* const* d_in, const int* in_sizes, int n_in,
                              void* d_out, int out_size)
{
    const float* x   = (const float*)d_in[0];
    const float* Wp  = (const float*)d_in[1];
    const float* bp  = (const float*)d_in[2];
    const float* Wc  = (const float*)d_in[3];
    const float* bc  = (const float*)d_in[4];
    const float* ap  = (const float*)d_in[5];
    const float* bpp = (const float*)d_in[6];
    const float* ac  = (const float*)d_in[7];
    const float* bcc = (const float*)d_in[8];
    float* out = (float*)d_out;

    void *p_xp, *p_qkv, *p_xp2, *p_xt, *p_qkvc, *p_xc;
    void *p_wph, *p_wpl, *p_wch, *p_wcl;
    cudaGetSymbolAddress(&p_xp, g_xp);
    cudaGetSymbolAddress(&p_qkv, g_qkv);
    cudaGetSymbolAddress(&p_xp2, g_xp2);
    cudaGetSymbolAddress(&p_xt, g_xt);
    cudaGetSymbolAddress(&p_qkvc, g_qkvc);
    cudaGetSymbolAddress(&p_xc, g_xc);
    cudaGetSymbolAddress(&p_wph, g_WpT_hi);
    cudaGetSymbolAddress(&p_wpl, g_WpT_lo);
    cudaGetSymbolAddress(&p_wch, g_WcT_hi);
    cudaGetSymbolAddress(&p_wcl, g_WcT_lo);
    __half* xp   = (__half*)p_xp;
    float* qkv   = (float*)p_qkv;
    float* xp2   = (float*)p_xp2;
    __half* xt   = (__half*)p_xt;
    float* qkvc  = (float*)p_qkvc;
    __half* xc   = (__half*)p_xc;
    __half* WpTh = (__half*)p_wph;
    __half* WpTl = (__half*)p_wpl;
    __half* WcTh = (__half*)p_wch;
    __half* WcTl = (__half*)p_wcl;

    cudaFuncSetAttribute((const void*)pos_attn_mma,  cudaFuncAttributeMaxDynamicSharedMemorySize, PA_SMEM_BYTES);
    cudaFuncSetAttribute((const void*)chan_attn_mma, cudaFuncAttributeMaxDynamicSharedMemorySize, CA_SMEM_BYTES);
    cudaFuncSetAttribute((const void*)gemm_f16,      cudaFuncAttributeMaxDynamicSharedMemorySize, GEMM_SMEM_BYTES);

    // 0. transpose + fp16 hi/lo split of weights
    split_transpose<<<dim3(DD/32, DD/32, 3), 256>>>(Wp, WpTh, WpTl, DD, DD);
    split_transpose<<<dim3(SS/32, SS/32, 4), 256>>>(Wc, WcTh, WcTl, SS, SS);

    // 1. LayerNorm over D -> fp16
    ln_p_kernel<<<BB*SS, 256>>>(x, ap, bpp, xp);

    // 2. positional qkv (fp16x2): [4096,1024]x[1024,1024] batched 3
    gemm_f16<<<dim3(DD/128, (BB*SS)/128, 3), 256, GEMM_SMEM_BYTES>>>(
        xp, WpTh, WpTl, bp, qkv, DD, DD,
        0L, (long)DD*DD, (long)DD, (long)BB*SS*DD, 0);

    // 3. positional attention (fp16 tensor cores)
    pos_attn_mma<<<dim3(2, BB*HP), 256, PA_SMEM_BYTES>>>(qkv, xp2);

    // 4. LayerNorm over S + transpose -> fp16 [B,D,S]
    ln_c_kernel<<<dim3(DD/32, BB), 256>>>(xp2, ac, bcc, xt);

    // 5. channel qkv (fp16x2): [16384,256]x[256,256] batched 3
    gemm_f16<<<dim3(SS/128, (BB*DD)/128, 3), 256, GEMM_SMEM_BYTES>>>(
        xt, WcTh, WcTl, bc, qkvc, SS, SS,
        0L, (long)SS*SS, (long)SS, (long)BB*DD*SS, 0);

    // 6. channel attention (fp16 tensor cores, flash) -> fp16
    chan_attn_mma<<<dim3(8, BB*HC), 256, CA_SMEM_BYTES>>>(qkvc, xc);

    // 7. output projection (fp16x2) with Wc[3], bc[3]; fused transpose -> out [B,S,D]
    gemm_f16<<<dim3(SS/128, (BB*DD)/128, 1), 256, GEMM_SMEM_BYTES>>>(
        xc, WcTh + 3L*SS*SS, WcTl + 3L*SS*SS, bc + 3L*SS, out, SS, SS,
        0L, 0L, 0L, 0L, 1);
}

// round 8
// speedup vs baseline: 4.8388x; 1.0429x over previous
#include <cuda_runtime.h>
#include <cuda_fp16.h>
#include <math.h>
#include <stdint.h>

// Problem constants
#define BB 16
#define SS 256
#define DD 1024
#define HP 16
#define DK 64
#define HC 8
#define SK 32
#define EPSV 1e-6f

// ---------------- scratch buffers (static device memory; no allocation) ----------------
__device__ __half g_xp[BB*SS*DD];        // LN_p output fp16 [B,S,D]
__device__ __half g_qkv[3*BB*SS*DD];     // pos qkv fp16      [3,B,S,D]
__device__ float  g_xp2[BB*SS*DD];       // pos attn out      [B,S,D]
__device__ __half g_xt[BB*DD*SS];        // LN_c out (transposed) fp16 [B,D,S]
__device__ __half g_qkvc[3*BB*DD*SS];    // channel qkv fp16  [3,B,D,S]
__device__ __half g_xc[BB*DD*SS];        // channel attn out fp16 [B,D,S]
__device__ __half g_WpT_hi[3*DD*DD];     // Wp transposed [N][K], fp16 hi
__device__ __half g_WpT_lo[3*DD*DD];     // fp16 lo (residual)
__device__ __half g_WcT_hi[4*SS*SS];
__device__ __half g_WcT_lo[4*SS*SS];

// ---------------- helpers ----------------
__device__ __forceinline__ void cp_async16(uint32_t smem, const void* g) {
    asm volatile("cp.async.cg.shared.global [%0], [%1], 16;" :: "r"(smem), "l"(g));
}

__device__ __forceinline__ void mma_f16(float* c, const unsigned* a, const unsigned* b) {
    asm volatile("mma.sync.aligned.m16n8k16.row.col.f32.f16.f16.f32 "
        "{%0,%1,%2,%3}, {%4,%5,%6,%7}, {%8,%9}, {%0,%1,%2,%3};"
        : "+f"(c[0]), "+f"(c[1]), "+f"(c[2]), "+f"(c[3])
        : "r"(a[0]), "r"(a[1]), "r"(a[2]), "r"(a[3]), "r"(b[0]), "r"(b[1]));
}

#define LDM4(r, addr) \
    asm volatile("ldmatrix.sync.aligned.m8n8.x4.shared.b16 {%0,%1,%2,%3}, [%4];" \
        : "=r"((r)[0]), "=r"((r)[1]), "=r"((r)[2]), "=r"((r)[3]) : "r"(addr))

__device__ __forceinline__ uint32_t smem_u32(const void* p) {
    uint32_t a;
    asm("{ .reg .u64 t; cvta.to.shared.u64 t, %1; cvt.u32.u64 %0, t; }" : "=r"(a) : "l"(p));
    return a;
}

__device__ __forceinline__ unsigned packh2(float x, float y) {
    __half2 h = __floats2half2_rn(x, y);
    return *(unsigned*)&h;
}

// ---------------- weight transpose + fp16 hi/lo split ----------------
__global__ void __launch_bounds__(256) split_transpose(const float* __restrict__ W,
                                                       __half* __restrict__ hi,
                                                       __half* __restrict__ lo,
                                                       int K, int N)
{
    __shared__ float t[32][33];
    int bz = blockIdx.z;
    W  += (long)bz * K * N;
    hi += (long)bz * K * N;
    lo += (long)bz * K * N;
    int n0 = blockIdx.x * 32, k0 = blockIdx.y * 32;
    int tx = threadIdx.x & 31, ty = threadIdx.x >> 5;
    #pragma unroll
    for (int j = 0; j < 32; j += 8)
        t[ty + j][tx] = W[(long)(k0 + ty + j) * N + n0 + tx];
    __syncthreads();
    #pragma unroll
    for (int j = 0; j < 32; j += 8) {
        float v = t[tx][ty + j];
        __half h = __float2half_rn(v);
        __half l = __float2half_rn(v - __half2float(h));
        long o = (long)(n0 + ty + j) * K + k0 + tx;
        hi[o] = h; lo[o] = l;
    }
}

// ---------------- LayerNorm over channels -> fp16 ----------------
__global__ void __launch_bounds__(256) ln_p_kernel(const float* __restrict__ x,
                                                   const float* __restrict__ ap,
                                                   const float* __restrict__ bp,
                                                   __half* __restrict__ xo)
{
    long row = blockIdx.x;
    const float* xr = x + row * DD;
    int tid = threadIdx.x;
    float s = 0.f, s2 = 0.f;
    #pragma unroll
    for (int i = tid; i < DD; i += 256) { float v = xr[i]; s += v; s2 += v*v; }
    __shared__ float rs[8], rs2[8];
    #pragma unroll
    for (int o = 16; o; o >>= 1) { s += __shfl_xor_sync(~0u, s, o); s2 += __shfl_xor_sync(~0u, s2, o); }
    if ((tid & 31) == 0) { rs[tid>>5] = s; rs2[tid>>5] = s2; }
    __syncthreads();
    s = 0.f; s2 = 0.f;
    #pragma unroll
    for (int w = 0; w < 8; w++) { s += rs[w]; s2 += rs2[w]; }
    float mean = s * (1.f / DD);
    float var  = (s2 - s * mean) * (1.f / (DD - 1));
    float inv  = 1.f / (sqrtf(var) + EPSV);
    #pragma unroll
    for (int i = tid; i < DD; i += 256) {
        float v = xr[i];
        xo[row * DD + i] = __float2half_rn(ap[i] * (v - mean) * inv + bp[i]);
    }
}

// ---------------- fp16x2 tensor GEMM: C = A * (Bhi+Blo)^T + bias ----------------
// 3-stage cp.async pipeline. A [M][K] fp16, Bh/Bl [N][K] fp16 (K-major).
// BM=128 BN=128 BK=32, 256 threads, warp tile 32x64, smem rows stride 40 halfs.
// outMode: 0 = fp32 C, 1 = fp32 with fused [B,D,S]->[B,S,D] transpose, 2 = fp16 C.
#define GT_TILE 10240
#define GEMM_SMEM_BYTES (9 * GT_TILE)   // 92160; transpose buffer (66048) fits

__device__ __forceinline__ void gemm_load_chunk(
    uint32_t sbase,
    const __half* __restrict__ A,
    const __half* __restrict__ Bh, const __half* __restrict__ Bl,
    long row0, int col0, int K, int k0, int buf, int tid)
{
    uint32_t base = sbase + buf * 3 * GT_TILE;
    #pragma unroll
    for (int i = 0; i < 2; i++) {
        int idx = tid + i * 256;
        int r = idx >> 2, sgi = idx & 3;
        uint32_t d = base + (uint32_t)(r * 80 + sgi * 16);
        long aoff = (row0 + r) * (long)K + k0 + sgi * 8;
        long boff = (long)(col0 + r) * K + k0 + sgi * 8;
        cp_async16(d,               &A[aoff]);
        cp_async16(d + GT_TILE,     &Bh[boff]);
        cp_async16(d + 2*GT_TILE,   &Bl[boff]);
    }
    asm volatile("cp.async.commit_group;");
}

__global__ void __launch_bounds__(256, 2) gemm_f16(const __half* __restrict__ A,
                                                   const __half* __restrict__ Bh,
                                                   const __half* __restrict__ Bl,
                                                   const float* __restrict__ bias,
                                                   float* __restrict__ C,
                                                   int K, int Ntot,
                                                   long aB, long bB, long biasB, long cB,
                                                   int outMode)
{
    extern __shared__ char smem[];
    uint32_t sbase = smem_u32(smem);
    int tid  = threadIdx.x;
    int warp = tid >> 5, lane = tid & 31;
    int wm = warp & 3, wn = warp >> 2;
    int g = lane >> 2, t = lane & 3;
    int bz = blockIdx.z;
    A    += (long)bz * aB;
    Bh   += (long)bz * bB;
    Bl   += (long)bz * bB;
    bias += (long)bz * biasB;
    long row0 = (long)blockIdx.y * 128;
    int  col0 = blockIdx.x * 128;

    uint32_t aAddr = sbase +
        (uint32_t)(((wm * 32 + (lane & 7) + ((lane >> 3) & 1) * 8) * 40 + (lane >> 4) * 8) * 2);
    uint32_t bAddr = sbase + GT_TILE +
        (uint32_t)(((wn * 64 + (lane & 7) + ((lane >> 4) & 1) * 8) * 40 + ((lane >> 3) & 1) * 8) * 2);

    float acc[2][8][4];
    #pragma unroll
    for (int mi = 0; mi < 2; mi++)
        #pragma unroll
        for (int ni = 0; ni < 8; ni++)
            #pragma unroll
            for (int r = 0; r < 4; r++) acc[mi][ni][r] = 0.f;

    int NC = K >> 5;
    gemm_load_chunk(sbase, A, Bh, Bl, row0, col0, K, 0, 0, tid);
    if (NC > 1) gemm_load_chunk(sbase, A, Bh, Bl, row0, col0, K, 32, 1, tid);

    for (int c = 0; c < NC; c++) {
        int buf = c % 3;
        if (c + 1 < NC) {
            asm volatile("cp.async.wait_group 1;" ::: "memory");
        } else {
            asm volatile("cp.async.wait_group 0;" ::: "memory");
        }
        __syncthreads();
        if (c + 2 < NC)
            gemm_load_chunk(sbase, A, Bh, Bl, row0, col0, K, (c + 2) << 5, (c + 2) % 3, tid);

        uint32_t bo = buf * 3 * GT_TILE;
        #pragma unroll
        for (int ks = 0; ks < 2; ks++) {
            uint32_t ak = aAddr + bo + ks * 32;
            unsigned a0[4], a1[4];
            LDM4(a0, ak);
            LDM4(a1, ak + 1280);
            #pragma unroll
            for (int gi = 0; gi < 4; gi++) {
                uint32_t bk = bAddr + bo + ks * 32 + gi * 1280;
                unsigned bh[4], bl[4];
                LDM4(bh, bk);
                LDM4(bl, bk + GT_TILE);
                int n0 = gi * 2, n1 = gi * 2 + 1;
                mma_f16(acc[0][n0], a0, bh);
                mma_f16(acc[0][n0], a0, bl);
                mma_f16(acc[1][n0], a1, bh);
                mma_f16(acc[1][n0], a1, bl);
                mma_f16(acc[0][n1], a0, bh + 2);
                mma_f16(acc[0][n1], a0, bl + 2);
                mma_f16(acc[1][n1], a1, bh + 2);
                mma_f16(acc[1][n1], a1, bl + 2);
            }
        }
    }

    if (outMode == 0) {
        float* Cf = C + (long)bz * cB;
        #pragma unroll
        for (int mi = 0; mi < 2; mi++) {
            #pragma unroll
            for (int ni = 0; ni < 8; ni++) {
                long r = row0 + wm * 32 + mi * 16 + g;
                int  cc = col0 + wn * 64 + ni * 8 + 2 * t;
                float b0 = bias[cc], b1 = bias[cc + 1];
                *(float2*)&Cf[r * Ntot + cc]       = make_float2(acc[mi][ni][0] + b0, acc[mi][ni][1] + b1);
                *(float2*)&Cf[(r + 8) * Ntot + cc] = make_float2(acc[mi][ni][2] + b0, acc[mi][ni][3] + b1);
            }
        }
    } else if (outMode == 2) {
        __half* Ch = (__half*)C + (long)bz * cB;
        #pragma unroll
        for (int mi = 0; mi < 2; mi++) {
            #pragma unroll
            for (int ni = 0; ni < 8; ni++) {
                long r = row0 + wm * 32 + mi * 16 + g;
                int  cc = col0 + wn * 64 + ni * 8 + 2 * t;
                float b0 = bias[cc], b1 = bias[cc + 1];
                *(__half2*)&Ch[r * Ntot + cc]       = __floats2half2_rn(acc[mi][ni][0] + b0, acc[mi][ni][1] + b1);
                *(__half2*)&Ch[(r + 8) * Ntot + cc] = __floats2half2_rn(acc[mi][ni][2] + b0, acc[mi][ni][3] + b1);
            }
        }
    } else {
        // stage to smem [s][d] then write out[b][s][d] coalesced
        __syncthreads();
        float* Ts = (float*)smem;
        int b = (int)(row0 >> 10), d0 = (int)(row0 & 1023);
        #pragma unroll
        for (int mi = 0; mi < 2; mi++) {
            #pragma unroll
            for (int ni = 0; ni < 8; ni++) {
                int rl = wm * 32 + mi * 16 + g;
                int cl = wn * 64 + ni * 8 + 2 * t;
                float b0 = bias[col0 + cl], b1 = bias[col0 + cl + 1];
                Ts[cl * 129 + rl]           = acc[mi][ni][0] + b0;
                Ts[(cl + 1) * 129 + rl]     = acc[mi][ni][1] + b1;
                Ts[cl * 129 + rl + 8]       = acc[mi][ni][2] + b0;
                Ts[(cl + 1) * 129 + rl + 8] = acc[mi][ni][3] + b1;
            }
        }
        __syncthreads();
        #pragma unroll
        for (int j = 0; j < 16; j++) {
            int sl = j * 8 + (tid >> 5);
            int d4 = (tid & 31) * 4;
            float4 o = make_float4(Ts[sl * 129 + d4], Ts[sl * 129 + d4 + 1],
                                   Ts[sl * 129 + d4 + 2], Ts[sl * 129 + d4 + 3]);
            *(float4*)&C[((long)(b * SS + col0 + sl)) * DD + d0 + d4] = o;
        }
    }
}

// ---------------- positional attention via fp16 tensor cores ----------------
// Qs [128][72] fp16, Ks [256][72] fp16, Vt [64][264] fp16 (V transposed)
#define PA_SMEM_BYTES ((128*72 + 256*72 + 64*264) * 2)
__global__ void __launch_bounds__(256) pos_attn_mma(const __half* __restrict__ qkv,
                                                    float* __restrict__ out)
{
    extern __shared__ __half smh[];
    __half* Qs = smh;                 // [128][72]
    __half* Ks = Qs + 128 * 72;       // [256][72]
    __half* Vt = Ks + 256 * 72;       // [64][264]
    int tid = threadIdx.x, lane = tid & 31, w = tid >> 5;
    int qt = blockIdx.x, bh = blockIdx.y;
    int b = bh >> 4, h = bh & 15;

    const __half* Qg = qkv + ((long)b * SS + qt * 128) * DD + h * DK;
    const __half* Kg = qkv + (long)BB*SS*DD + (long)b * SS * DD + h * DK;
    const __half* Vg = Kg + (long)BB*SS*DD;

    for (int idx = tid; idx < 128 * 8; idx += 256) {
        int r = idx >> 3, c = (idx & 7) * 8;
        *(uint4*)&Qs[r * 72 + c] = *(const uint4*)&Qg[(long)r * DD + c];
    }
    for (int idx = tid; idx < 256 * 8; idx += 256) {
        int r = idx >> 3, c = (idx & 7) * 8;
        *(uint4*)&Ks[r * 72 + c] = *(const uint4*)&Kg[(long)r * DD + c];
        uint4 vv = *(const uint4*)&Vg[(long)r * DD + c];
        const __half* vh = (const __half*)&vv;
        #pragma unroll
        for (int j = 0; j < 8; j++) Vt[(c + j) * 264 + r] = vh[j];
    }
    __syncthreads();

    int g = lane >> 2, tig = lane & 3;
    int row = w * 16 + g;

    unsigned qa[4][4];
    #pragma unroll
    for (int ks = 0; ks < 4; ks++) {
        const __half* qb = Qs + row * 72 + ks * 16 + 2 * tig;
        qa[ks][0] = *(const unsigned*)qb;
        qa[ks][1] = *(const unsigned*)(qb + 8 * 72);
        qa[ks][2] = *(const unsigned*)(qb + 8);
        qa[ks][3] = *(const unsigned*)(qb + 8 * 72 + 8);
    }

    float sc[32][4];
    #pragma unroll
    for (int nf = 0; nf < 32; nf++) {
        sc[nf][0] = sc[nf][1] = sc[nf][2] = sc[nf][3] = 0.f;
        const __half* kb = Ks + (nf * 8 + g) * 72 + 2 * tig;
        #pragma unroll
        for (int ks = 0; ks < 4; ks++) {
            unsigned bb[2];
            bb[0] = *(const unsigned*)(kb + ks * 16);
            bb[1] = *(const unsigned*)(kb + ks * 16 + 8);
            mma_f16(sc[nf], qa[ks], bb);
        }
    }

    // softmax on raw scores with folded 1/8 scale
    float mx0 = -1e30f, mx1 = -1e30f;
    #pragma unroll
    for (int nf = 0; nf < 32; nf++) {
        mx0 = fmaxf(mx0, fmaxf(sc[nf][0], sc[nf][1]));
        mx1 = fmaxf(mx1, fmaxf(sc[nf][2], sc[nf][3]));
    }
    mx0 = fmaxf(mx0, __shfl_xor_sync(~0u, mx0, 1));
    mx0 = fmaxf(mx0, __shfl_xor_sync(~0u, mx0, 2));
    mx1 = fmaxf(mx1, __shfl_xor_sync(~0u, mx1, 1));
    mx1 = fmaxf(mx1, __shfl_xor_sync(~0u, mx1, 2));
    float sum0 = 0.f, sum1 = 0.f;
    #pragma unroll
    for (int nf = 0; nf < 32; nf++) {
        float p0 = __expf((sc[nf][0] - mx0) * 0.125f), p1 = __expf((sc[nf][1] - mx0) * 0.125f);
        float p2 = __expf((sc[nf][2] - mx1) * 0.125f), p3 = __expf((sc[nf][3] - mx1) * 0.125f);
        sum0 += p0 + p1; sum1 += p2 + p3;
        sc[nf][0] = p0; sc[nf][1] = p1; sc[nf][2] = p2; sc[nf][3] = p3;
    }
    sum0 += __shfl_xor_sync(~0u, sum0, 1); sum0 += __shfl_xor_sync(~0u, sum0, 2);
    sum1 += __shfl_xor_sync(~0u, sum1, 1); sum1 += __shfl_xor_sync(~0u, sum1, 2);

    // pack P c-frags -> fp16 a-frags in place
    #pragma unroll
    for (int ksi = 0; ksi < 16; ksi++) {
        unsigned p0 = packh2(sc[2*ksi][0],   sc[2*ksi][1]);
        unsigned p1 = packh2(sc[2*ksi][2],   sc[2*ksi][3]);
        unsigned p2 = packh2(sc[2*ksi+1][0], sc[2*ksi+1][1]);
        unsigned p3 = packh2(sc[2*ksi+1][2], sc[2*ksi+1][3]);
        unsigned* d = (unsigned*)sc[2*ksi];
        d[0] = p0; d[1] = p1; d[2] = p2; d[3] = p3;
    }

    float o[8][4];
    #pragma unroll
    for (int nf = 0; nf < 8; nf++) { o[nf][0]=o[nf][1]=o[nf][2]=o[nf][3]=0.f; }
    #pragma unroll
    for (int nf = 0; nf < 8; nf++) {
        const __half* vb = Vt + (nf * 8 + g) * 264 + 2 * tig;
        #pragma unroll
        for (int ksi = 0; ksi < 16; ksi++) {
            unsigned bb[2];
            bb[0] = *(const unsigned*)(vb + ksi * 16);
            bb[1] = *(const unsigned*)(vb + ksi * 16 + 8);
            mma_f16(o[nf], (const unsigned*)sc[2*ksi], bb);
        }
    }

    float inv0 = 1.f / sum0, inv1 = 1.f / sum1;
    long orow0 = ((long)b * SS + qt * 128 + row) * DD + h * DK;
    long orow1 = orow0 + 8L * DD;
    #pragma unroll
    for (int nf = 0; nf < 8; nf++) {
        int c = nf * 8 + 2 * tig;
        *(float2*)&out[orow0 + c] = make_float2(o[nf][0] * inv0, o[nf][1] * inv0);
        *(float2*)&out[orow1 + c] = make_float2(o[nf][2] * inv1, o[nf][3] * inv1);
    }
}

// ---------------- LayerNorm over sequence + transpose -> fp16 [B,D,S] ----------------
__global__ void __launch_bounds__(256) ln_c_kernel(const float* __restrict__ xin,
                                                   const float* __restrict__ ac,
                                                   const float* __restrict__ bcv,
                                                   __half* __restrict__ xo)
{
    __shared__ float tile[32][257];
    __shared__ float red[8][32], red2[8][32];
    __shared__ float s_mean[32], s_inv[32];
    int b = blockIdx.y, d0 = blockIdx.x * 32;
    int tid = threadIdx.x, lane = tid & 31, w = tid >> 5;
    const float* base = xin + (long)b * SS * DD + d0;
    #pragma unroll 4
    for (int i = 0; i < 32; i++) {
        int s = w * 32 + i;
        tile[lane][s] = base[(long)s * DD + lane];
    }
    __syncthreads();
    {
        int d = tid & 31, ch = tid >> 5;
        float s1 = 0.f, s2 = 0.f;
        #pragma unroll
        for (int j = 0; j < 32; j++) {
            float v = tile[d][ch * 32 + j]; s1 += v; s2 += v * v;
        }
        red[ch][d] = s1; red2[ch][d] = s2;
    }
    __syncthreads();
    if (tid < 32) {
        float s1 = 0.f, s2 = 0.f;
        #pragma unroll
        for (int ch = 0; ch < 8; ch++) { s1 += red[ch][tid]; s2 += red2[ch][tid]; }
        float mean = s1 * (1.f / SS);
        float var  = (s2 - s1 * mean) * (1.f / (SS - 1));
        s_mean[tid] = mean;
        s_inv[tid]  = 1.f / (sqrtf(var) + EPSV);
    }
    __syncthreads();
    {
        int d = tid >> 3, s0 = (tid & 7) * 32;
        float mean = s_mean[d], inv = s_inv[d];
        long dstBase = ((long)b * DD + d0 + d) * SS;
        #pragma unroll
        for (int j = 0; j < 32; j += 2) {
            int s = s0 + j;
            float v0 = ac[s+0] * (tile[d][s+0] - mean) * inv + bcv[s+0];
            float v1 = ac[s+1] * (tile[d][s+1] - mean) * inv + bcv[s+1];
            *(__half2*)&xo[dstBase + s] = __floats2half2_rn(v0, v1);
        }
    }
}

// ---------------- channel attention via fp16 tensor cores (flash) ----------------
// Qs [128][40], Ks [128][40], Vt [32][136] fp16
#define CA_SMEM_BYTES ((128*40 + 128*40 + 32*136) * 2)
__global__ void __launch_bounds__(256) chan_attn_mma(const __half* __restrict__ qkvc,
                                                     __half* __restrict__ xc)
{
    extern __shared__ __half smh[];
    __half* Qs = smh;                // [128][40]
    __half* Ks = Qs + 128 * 40;
    __half* Vt = Ks + 128 * 40;      // [32][136]
    int tid = threadIdx.x, lane = tid & 31, w = tid >> 5;
    int qt = blockIdx.x, bh = blockIdx.y;
    int b = bh >> 3, h = bh & 7;
    const float scale = 0.1767766952966369f;   // 1/sqrt(32)

    const long qBase = (long)b * DD * SS + h * SK;
    const long nStride = (long)BB * DD * SS;

    for (int idx = tid; idx < 128 * 4; idx += 256) {
        int r = idx >> 2, c = (idx & 3) * 8;
        *(uint4*)&Qs[r * 40 + c] = *(const uint4*)&qkvc[qBase + (long)(qt * 128 + r) * SS + c];
    }
    __syncthreads();

    int g = lane >> 2, tig = lane & 3;
    int row = w * 16 + g;

    unsigned qa[2][4];
    #pragma unroll
    for (int ks = 0; ks < 2; ks++) {
        const __half* qb = Qs + row * 40 + ks * 16 + 2 * tig;
        qa[ks][0] = *(const unsigned*)qb;
        qa[ks][1] = *(const unsigned*)(qb + 8 * 40);
        qa[ks][2] = *(const unsigned*)(qb + 8);
        qa[ks][3] = *(const unsigned*)(qb + 8 * 40 + 8);
    }

    float m0 = -1e30f, m1 = -1e30f, l0 = 0.f, l1 = 0.f;
    float o[4][4];
    #pragma unroll
    for (int nf = 0; nf < 4; nf++) { o[nf][0]=o[nf][1]=o[nf][2]=o[nf][3]=0.f; }

    for (int st = 0; st < 8; st++) {
        __syncthreads();
        for (int idx = tid; idx < 128 * 4; idx += 256) {
            int r = idx >> 2, c = (idx & 3) * 8;
            *(uint4*)&Ks[r * 40 + c] = *(const uint4*)&qkvc[qBase + nStride + (long)(st * 128 + r) * SS + c];
            uint4 vv = *(const uint4*)&qkvc[qBase + 2 * nStride + (long)(st * 128 + r) * SS + c];
            const __half* vh = (const __half*)&vv;
            #pragma unroll
            for (int j = 0; j < 8; j++) Vt[(c + j) * 136 + r] = vh[j];
        }
        __syncthreads();

        float sc[16][4];
        #pragma unroll
        for (int nf = 0; nf < 16; nf++) {
            sc[nf][0] = sc[nf][1] = sc[nf][2] = sc[nf][3] = 0.f;
            const __half* kb = Ks + (nf * 8 + g) * 40 + 2 * tig;
            #pragma unroll
            for (int ks = 0; ks < 2; ks++) {
                unsigned bb[2];
                bb[0] = *(const unsigned*)(kb + ks * 16);
                bb[1] = *(const unsigned*)(kb + ks * 16 + 8);
                mma_f16(sc[nf], qa[ks], bb);
            }
        }
        float tm0 = -1e30f, tm1 = -1e30f;
        #pragma unroll
        for (int nf = 0; nf < 16; nf++) {
            tm0 = fmaxf(tm0, fmaxf(sc[nf][0], sc[nf][1]));
            tm1 = fmaxf(tm1, fmaxf(sc[nf][2], sc[nf][3]));
        }
        tm0 = fmaxf(tm0, __shfl_xor_sync(~0u, tm0, 1));
        tm0 = fmaxf(tm0, __shfl_xor_sync(~0u, tm0, 2));
        tm1 = fmaxf(tm1, __shfl_xor_sync(~0u, tm1, 1));
        tm1 = fmaxf(tm1, __shfl_xor_sync(~0u, tm1, 2));
        float nm0 = fmaxf(m0, tm0), nm1 = fmaxf(m1, tm1);
        float al0 = __expf((m0 - nm0) * scale), al1 = __expf((m1 - nm1) * scale);
        m0 = nm0; m1 = nm1;
        float ts0 = 0.f, ts1 = 0.f;
        #pragma unroll
        for (int nf = 0; nf < 16; nf++) {
            float p0 = __expf((sc[nf][0] - nm0) * scale), p1 = __expf((sc[nf][1] - nm0) * scale);
            float p2 = __expf((sc[nf][2] - nm1) * scale), p3 = __expf((sc[nf][3] - nm1) * scale);
            ts0 += p0 + p1; ts1 += p2 + p3;
            sc[nf][0] = p0; sc[nf][1] = p1; sc[nf][2] = p2; sc[nf][3] = p3;
        }
        ts0 += __shfl_xor_sync(~0u, ts0, 1); ts0 += __shfl_xor_sync(~0u, ts0, 2);
        ts1 += __shfl_xor_sync(~0u, ts1, 1); ts1 += __shfl_xor_sync(~0u, ts1, 2);
        l0 = l0 * al0 + ts0; l1 = l1 * al1 + ts1;
        #pragma unroll
        for (int nf = 0; nf < 4; nf++) {
            o[nf][0] *= al0; o[nf][1] *= al0;
            o[nf][2] *= al1; o[nf][3] *= al1;
        }
        #pragma unroll
        for (int ksi = 0; ksi < 8; ksi++) {
            unsigned p0 = packh2(sc[2*ksi][0],   sc[2*ksi][1]);
            unsigned p1 = packh2(sc[2*ksi][2],   sc[2*ksi][3]);
            unsigned p2 = packh2(sc[2*ksi+1][0], sc[2*ksi+1][1]);
            unsigned p3 = packh2(sc[2*ksi+1][2], sc[2*ksi+1][3]);
            unsigned* d = (unsigned*)sc[2*ksi];
            d[0] = p0; d[1] = p1; d[2] = p2; d[3] = p3;
        }
        #pragma unroll
        for (int nf = 0; nf < 4; nf++) {
            const __half* vb = Vt + (nf * 8 + g) * 136 + 2 * tig;
            #pragma unroll
            for (int ksi = 0; ksi < 8; ksi++) {
                unsigned bb[2];
                bb[0] = *(const unsigned*)(vb + ksi * 16);
                bb[1] = *(const unsigned*)(vb + ksi * 16 + 8);
                mma_f16(o[nf], (const unsigned*)sc[2*ksi], bb);
            }
        }
    }

    float inv0 = 1.f / l0, inv1 = 1.f / l1;
    long orow0 = ((long)b * DD + qt * 128 + row) * SS + h * SK;
    long orow1 = orow0 + 8L * SS;
    #pragma unroll
    for (int nf = 0; nf < 4; nf++) {
        int c = nf * 8 + 2 * tig;
        *(__half2*)&xc[orow0 + c] = __floats2half2_rn(o[nf][0] * inv0, o[nf][1] * inv0);
        *(__half2*)&xc[orow1 + c] = __floats2half2_rn(o[nf][2] * inv1, o[nf][3] * inv1);
    }
}

// ---------------- launch ----------------
extern "C" void kernel_launch(void* const* d_in, const int* in_sizes, int n_in,
                              void* d_out, int out_size)
{
    const float* x   = (const float*)d_in[0];
    const float* Wp  = (const float*)d_in[1];
    const float* bp  = (const float*)d_in[2];
    const float* Wc  = (const float*)d_in[3];
    const float* bc  = (const float*)d_in[4];
    const float* ap  = (const float*)d_in[5];
    const float* bpp = (const float*)d_in[6];
    const float* ac  = (const float*)d_in[7];
    const float* bcc = (const float*)d_in[8];
    float* out = (float*)d_out;

    void *p_xp, *p_qkv, *p_xp2, *p_xt, *p_qkvc, *p_xc;
    void *p_wph, *p_wpl, *p_wch, *p_wcl;
    cudaGetSymbolAddress(&p_xp, g_xp);
    cudaGetSymbolAddress(&p_qkv, g_qkv);
    cudaGetSymbolAddress(&p_xp2, g_xp2);
    cudaGetSymbolAddress(&p_xt, g_xt);
    cudaGetSymbolAddress(&p_qkvc, g_qkvc);
    cudaGetSymbolAddress(&p_xc, g_xc);
    cudaGetSymbolAddress(&p_wph, g_WpT_hi);
    cudaGetSymbolAddress(&p_wpl, g_WpT_lo);
    cudaGetSymbolAddress(&p_wch, g_WcT_hi);
    cudaGetSymbolAddress(&p_wcl, g_WcT_lo);
    __half* xp   = (__half*)p_xp;
    __half* qkv  = (__half*)p_qkv;
    float* xp2   = (float*)p_xp2;
    __half* xt   = (__half*)p_xt;
    __half* qkvc = (__half*)p_qkvc;
    __half* xc   = (__half*)p_xc;
    __half* WpTh = (__half*)p_wph;
    __half* WpTl = (__half*)p_wpl;
    __half* WcTh = (__half*)p_wch;
    __half* WcTl = (__half*)p_wcl;

    cudaFuncSetAttribute((const void*)pos_attn_mma,  cudaFuncAttributeMaxDynamicSharedMemorySize, PA_SMEM_BYTES);
    cudaFuncSetAttribute((const void*)chan_attn_mma, cudaFuncAttributeMaxDynamicSharedMemorySize, CA_SMEM_BYTES);
    cudaFuncSetAttribute((const void*)gemm_f16,      cudaFuncAttributeMaxDynamicSharedMemorySize, GEMM_SMEM_BYTES);

    // 0. transpose + fp16 hi/lo split of weights
    split_transpose<<<dim3(DD/32, DD/32, 3), 256>>>(Wp, WpTh, WpTl, DD, DD);
    split_transpose<<<dim3(SS/32, SS/32, 4), 256>>>(Wc, WcTh, WcTl, SS, SS);

    // 1. LayerNorm over D -> fp16
    ln_p_kernel<<<BB*SS, 256>>>(x, ap, bpp, xp);

    // 2. positional qkv (fp16x2) -> fp16 qkv
    gemm_f16<<<dim3(DD/128, (BB*SS)/128, 3), 256, GEMM_SMEM_BYTES>>>(
        xp, WpTh, WpTl, bp, (float*)qkv, DD, DD,
        0L, (long)DD*DD, (long)DD, (long)BB*SS*DD, 2);

    // 3. positional attention (fp16 tensor cores)
    pos_attn_mma<<<dim3(2, BB*HP), 256, PA_SMEM_BYTES>>>(qkv, xp2);

    // 4. LayerNorm over S + transpose -> fp16 [B,D,S]
    ln_c_kernel<<<dim3(DD/32, BB), 256>>>(xp2, ac, bcc, xt);

    // 5. channel qkv (fp16x2) -> fp16 qkvc
    gemm_f16<<<dim3(SS/128, (BB*DD)/128, 3), 256, GEMM_SMEM_BYTES>>>(
        xt, WcTh, WcTl, bc, (float*)qkvc, SS, SS,
        0L, (long)SS*SS, (long)SS, (long)BB*DD*SS, 2);

    // 6. channel attention (fp16 tensor cores, flash) -> fp16
    chan_attn_mma<<<dim3(8, BB*HC), 256, CA_SMEM_BYTES>>>(qkvc, xc);

    // 7. output projection (fp16x2) with Wc[3], bc[3]; fused transpose -> out [B,S,D]
    gemm_f16<<<dim3(SS/128, (BB*DD)/128, 1), 256, GEMM_SMEM_BYTES>>>(
        xc, WcTh + 3L*SS*SS, WcTl + 3L*SS*SS, bc + 3L*SS, out, SS, SS,
        0L, 0L, 0L, 0L, 1);
}

// round 9
// speedup vs baseline: 4.8659x; 1.0056x over previous
#include <cuda_runtime.h>
#include <cuda_fp16.h>
#include <math.h>
#include <stdint.h>

// Problem constants
#define BB 16
#define SS 256
#define DD 1024
#define HP 16
#define DK 64
#define HC 8
#define SK 32
#define EPSV 1e-6f

// ---------------- scratch buffers (static device memory; no allocation) ----------------
__device__ __half g_xp[BB*SS*DD];        // LN_p output fp16 [B,S,D]
__device__ __half g_qkv[3*BB*SS*DD];     // pos qkv fp16      [3,B,S,D]
__device__ float  g_xp2[BB*SS*DD];       // pos attn out      [B,S,D]
__device__ __half g_xt[BB*DD*SS];        // LN_c out (transposed) fp16 [B,D,S]
__device__ __half g_qkvc[3*BB*DD*SS];    // channel qkv fp16  [3,B,D,S]
__device__ __half g_xc[BB*DD*SS];        // channel attn out fp16 [B,D,S]
__device__ __half g_WpT_hi[3*DD*DD];     // Wp transposed [N][K], fp16 hi
__device__ __half g_WpT_lo[3*DD*DD];     // fp16 lo (residual)
__device__ __half g_WcT_hi[4*SS*SS];
__device__ __half g_WcT_lo[4*SS*SS];

// ---------------- helpers ----------------
__device__ __forceinline__ void cp_async16(uint32_t smem, const void* g) {
    asm volatile("cp.async.cg.shared.global [%0], [%1], 16;" :: "r"(smem), "l"(g));
}

__device__ __forceinline__ void mma_f16(float* c, const unsigned* a, const unsigned* b) {
    asm volatile("mma.sync.aligned.m16n8k16.row.col.f32.f16.f16.f32 "
        "{%0,%1,%2,%3}, {%4,%5,%6,%7}, {%8,%9}, {%0,%1,%2,%3};"
        : "+f"(c[0]), "+f"(c[1]), "+f"(c[2]), "+f"(c[3])
        : "r"(a[0]), "r"(a[1]), "r"(a[2]), "r"(a[3]), "r"(b[0]), "r"(b[1]));
}

#define LDM4(r, addr) \
    asm volatile("ldmatrix.sync.aligned.m8n8.x4.shared.b16 {%0,%1,%2,%3}, [%4];" \
        : "=r"((r)[0]), "=r"((r)[1]), "=r"((r)[2]), "=r"((r)[3]) : "r"(addr))

__device__ __forceinline__ uint32_t smem_u32(const void* p) {
    uint32_t a;
    asm("{ .reg .u64 t; cvta.to.shared.u64 t, %1; cvt.u32.u64 %0, t; }" : "=r"(a) : "l"(p));
    return a;
}

__device__ __forceinline__ unsigned packh2(float x, float y) {
    __half2 h = __floats2half2_rn(x, y);
    return *(unsigned*)&h;
}

// ---------------- weight transpose + fp16 hi/lo split ----------------
__global__ void __launch_bounds__(256) split_transpose(const float* __restrict__ W,
                                                       __half* __restrict__ hi,
                                                       __half* __restrict__ lo,
                                                       int K, int N)
{
    __shared__ float t[32][33];
    int bz = blockIdx.z;
    W  += (long)bz * K * N;
    hi += (long)bz * K * N;
    lo += (long)bz * K * N;
    int n0 = blockIdx.x * 32, k0 = blockIdx.y * 32;
    int tx = threadIdx.x & 31, ty = threadIdx.x >> 5;
    #pragma unroll
    for (int j = 0; j < 32; j += 8)
        t[ty + j][tx] = W[(long)(k0 + ty + j) * N + n0 + tx];
    __syncthreads();
    #pragma unroll
    for (int j = 0; j < 32; j += 8) {
        float v = t[tx][ty + j];
        __half h = __float2half_rn(v);
        __half l = __float2half_rn(v - __half2float(h));
        long o = (long)(n0 + ty + j) * K + k0 + tx;
        hi[o] = h; lo[o] = l;
    }
}

// ---------------- LayerNorm over channels -> fp16 ----------------
__global__ void __launch_bounds__(256) ln_p_kernel(const float* __restrict__ x,
                                                   const float* __restrict__ ap,
                                                   const float* __restrict__ bp,
                                                   __half* __restrict__ xo)
{
    long row = blockIdx.x;
    const float* xr = x + row * DD;
    int tid = threadIdx.x;
    float s = 0.f, s2 = 0.f;
    #pragma unroll
    for (int i = tid; i < DD; i += 256) { float v = xr[i]; s += v; s2 += v*v; }
    __shared__ float rs[8], rs2[8];
    #pragma unroll
    for (int o = 16; o; o >>= 1) { s += __shfl_xor_sync(~0u, s, o); s2 += __shfl_xor_sync(~0u, s2, o); }
    if ((tid & 31) == 0) { rs[tid>>5] = s; rs2[tid>>5] = s2; }
    __syncthreads();
    s = 0.f; s2 = 0.f;
    #pragma unroll
    for (int w = 0; w < 8; w++) { s += rs[w]; s2 += rs2[w]; }
    float mean = s * (1.f / DD);
    float var  = (s2 - s * mean) * (1.f / (DD - 1));
    float inv  = 1.f / (sqrtf(var) + EPSV);
    #pragma unroll
    for (int i = tid; i < DD; i += 256) {
        float v = xr[i];
        xo[row * DD + i] = __float2half_rn(ap[i] * (v - mean) * inv + bp[i]);
    }
}

// ---------------- fp16x2 tensor GEMM: C = A * (Bhi+Blo)^T + bias ----------------
// 3-stage cp.async pipeline. A [M][K] fp16, Bh/Bl [N][K] fp16 (K-major).
// BM=128 BN=128 BK=32, 256 threads. Warp grid 2(M) x 4(N), warp tile 64x32.
// smem rows stride 40 halfs. outMode: 0=fp32 C, 1=fp32 fused transpose, 2=fp16 C.
#define GT_TILE 10240
#define GEMM_SMEM_BYTES (9 * GT_TILE)   // 92160; transpose buffer (66048) fits

__device__ __forceinline__ void gemm_load_chunk(
    uint32_t sbase,
    const __half* __restrict__ A,
    const __half* __restrict__ Bh, const __half* __restrict__ Bl,
    long row0, int col0, int K, int k0, int buf, int tid)
{
    uint32_t base = sbase + buf * 3 * GT_TILE;
    #pragma unroll
    for (int i = 0; i < 2; i++) {
        int idx = tid + i * 256;
        int r = idx >> 2, sgi = idx & 3;
        uint32_t d = base + (uint32_t)(r * 80 + sgi * 16);
        long aoff = (row0 + r) * (long)K + k0 + sgi * 8;
        long boff = (long)(col0 + r) * K + k0 + sgi * 8;
        cp_async16(d,               &A[aoff]);
        cp_async16(d + GT_TILE,     &Bh[boff]);
        cp_async16(d + 2*GT_TILE,   &Bl[boff]);
    }
    asm volatile("cp.async.commit_group;");
}

__global__ void __launch_bounds__(256, 2) gemm_f16(const __half* __restrict__ A,
                                                   const __half* __restrict__ Bh,
                                                   const __half* __restrict__ Bl,
                                                   const float* __restrict__ bias,
                                                   float* __restrict__ C,
                                                   int K, int Ntot,
                                                   long aB, long bB, long biasB, long cB,
                                                   int outMode)
{
    extern __shared__ char smem[];
    uint32_t sbase = smem_u32(smem);
    int tid  = threadIdx.x;
    int warp = tid >> 5, lane = tid & 31;
    int wm = warp & 1, wn = warp >> 1;        // 2 x 4 warp grid, tile 64M x 32N
    int g = lane >> 2, t = lane & 3;
    int bz = blockIdx.z;
    A    += (long)bz * aB;
    Bh   += (long)bz * bB;
    Bl   += (long)bz * bB;
    bias += (long)bz * biasB;
    long row0 = (long)blockIdx.y * 128;
    int  col0 = blockIdx.x * 128;

    uint32_t aAddr = sbase +
        (uint32_t)(((wm * 64 + (lane & 7) + ((lane >> 3) & 1) * 8) * 40 + (lane >> 4) * 8) * 2);
    uint32_t bAddr = sbase + GT_TILE +
        (uint32_t)(((wn * 32 + (lane & 7) + ((lane >> 4) & 1) * 8) * 40 + ((lane >> 3) & 1) * 8) * 2);

    float acc[4][4][4];
    #pragma unroll
    for (int mi = 0; mi < 4; mi++)
        #pragma unroll
        for (int ni = 0; ni < 4; ni++)
            #pragma unroll
            for (int r = 0; r < 4; r++) acc[mi][ni][r] = 0.f;

    int NC = K >> 5;
    gemm_load_chunk(sbase, A, Bh, Bl, row0, col0, K, 0, 0, tid);
    if (NC > 1) gemm_load_chunk(sbase, A, Bh, Bl, row0, col0, K, 32, 1, tid);

    for (int c = 0; c < NC; c++) {
        int buf = c % 3;
        if (c + 1 < NC) {
            asm volatile("cp.async.wait_group 1;" ::: "memory");
        } else {
            asm volatile("cp.async.wait_group 0;" ::: "memory");
        }
        __syncthreads();
        if (c + 2 < NC)
            gemm_load_chunk(sbase, A, Bh, Bl, row0, col0, K, (c + 2) << 5, (c + 2) % 3, tid);

        uint32_t bo = buf * 3 * GT_TILE;
        #pragma unroll
        for (int ks = 0; ks < 2; ks++) {
            uint32_t ak = aAddr + bo + ks * 32;
            uint32_t bk = bAddr + bo + ks * 32;
            unsigned af[4][4];
            LDM4(af[0], ak);
            LDM4(af[1], ak + 1280);
            LDM4(af[2], ak + 2560);
            LDM4(af[3], ak + 3840);
            unsigned bhf[2][4], blf[2][4];
            LDM4(bhf[0], bk);
            LDM4(bhf[1], bk + 1280);
            LDM4(blf[0], bk + GT_TILE);
            LDM4(blf[1], bk + GT_TILE + 1280);
            // all-hi then all-lo: no adjacent dependent MMAs on same acc
            #pragma unroll
            for (int mi = 0; mi < 4; mi++)
                #pragma unroll
                for (int ni = 0; ni < 4; ni++)
                    mma_f16(acc[mi][ni], af[mi], &bhf[ni >> 1][(ni & 1) * 2]);
            #pragma unroll
            for (int mi = 0; mi < 4; mi++)
                #pragma unroll
                for (int ni = 0; ni < 4; ni++)
                    mma_f16(acc[mi][ni], af[mi], &blf[ni >> 1][(ni & 1) * 2]);
        }
    }

    if (outMode == 0) {
        float* Cf = C + (long)bz * cB;
        #pragma unroll
        for (int mi = 0; mi < 4; mi++) {
            #pragma unroll
            for (int ni = 0; ni < 4; ni++) {
                long r = row0 + wm * 64 + mi * 16 + g;
                int  cc = col0 + wn * 32 + ni * 8 + 2 * t;
                float b0 = bias[cc], b1 = bias[cc + 1];
                *(float2*)&Cf[r * Ntot + cc]       = make_float2(acc[mi][ni][0] + b0, acc[mi][ni][1] + b1);
                *(float2*)&Cf[(r + 8) * Ntot + cc] = make_float2(acc[mi][ni][2] + b0, acc[mi][ni][3] + b1);
            }
        }
    } else if (outMode == 2) {
        __half* Ch = (__half*)C + (long)bz * cB;
        #pragma unroll
        for (int mi = 0; mi < 4; mi++) {
            #pragma unroll
            for (int ni = 0; ni < 4; ni++) {
                long r = row0 + wm * 64 + mi * 16 + g;
                int  cc = col0 + wn * 32 + ni * 8 + 2 * t;
                float b0 = bias[cc], b1 = bias[cc + 1];
                *(__half2*)&Ch[r * Ntot + cc]       = __floats2half2_rn(acc[mi][ni][0] + b0, acc[mi][ni][1] + b1);
                *(__half2*)&Ch[(r + 8) * Ntot + cc] = __floats2half2_rn(acc[mi][ni][2] + b0, acc[mi][ni][3] + b1);
            }
        }
    } else {
        // stage to smem [s][d] then write out[b][s][d] coalesced
        __syncthreads();
        float* Ts = (float*)smem;
        int b = (int)(row0 >> 10), d0 = (int)(row0 & 1023);
        #pragma unroll
        for (int mi = 0; mi < 4; mi++) {
            #pragma unroll
            for (int ni = 0; ni < 4; ni++) {
                int rl = wm * 64 + mi * 16 + g;
                int cl = wn * 32 + ni * 8 + 2 * t;
                float b0 = bias[col0 + cl], b1 = bias[col0 + cl + 1];
                Ts[cl * 129 + rl]           = acc[mi][ni][0] + b0;
                Ts[(cl + 1) * 129 + rl]     = acc[mi][ni][1] + b1;
                Ts[cl * 129 + rl + 8]       = acc[mi][ni][2] + b0;
                Ts[(cl + 1) * 129 + rl + 8] = acc[mi][ni][3] + b1;
            }
        }
        __syncthreads();
        #pragma unroll
        for (int j = 0; j < 16; j++) {
            int sl = j * 8 + (tid >> 5);
            int d4 = (tid & 31) * 4;
            float4 o = make_float4(Ts[sl * 129 + d4], Ts[sl * 129 + d4 + 1],
                                   Ts[sl * 129 + d4 + 2], Ts[sl * 129 + d4 + 3]);
            *(float4*)&C[((long)(b * SS + col0 + sl)) * DD + d0 + d4] = o;
        }
    }
}

// ---------------- positional attention via fp16 tensor cores ----------------
// Qs [128][72] fp16, Ks [256][72] fp16, Vt [64][264] fp16 (V transposed)
#define PA_SMEM_BYTES ((128*72 + 256*72 + 64*264) * 2)
__global__ void __launch_bounds__(256) pos_attn_mma(const __half* __restrict__ qkv,
                                                    float* __restrict__ out)
{
    extern __shared__ __half smh[];
    __half* Qs = smh;                 // [128][72]
    __half* Ks = Qs + 128 * 72;       // [256][72]
    __half* Vt = Ks + 256 * 72;       // [64][264]
    int tid = threadIdx.x, lane = tid & 31, w = tid >> 5;
    int qt = blockIdx.x, bh = blockIdx.y;
    int b = bh >> 4, h = bh & 15;

    const __half* Qg = qkv + ((long)b * SS + qt * 128) * DD + h * DK;
    const __half* Kg = qkv + (long)BB*SS*DD + (long)b * SS * DD + h * DK;
    const __half* Vg = Kg + (long)BB*SS*DD;

    for (int idx = tid; idx < 128 * 8; idx += 256) {
        int r = idx >> 3, c = (idx & 7) * 8;
        *(uint4*)&Qs[r * 72 + c] = *(const uint4*)&Qg[(long)r * DD + c];
    }
    for (int idx = tid; idx < 256 * 8; idx += 256) {
        int r = idx >> 3, c = (idx & 7) * 8;
        *(uint4*)&Ks[r * 72 + c] = *(const uint4*)&Kg[(long)r * DD + c];
        uint4 vv = *(const uint4*)&Vg[(long)r * DD + c];
        const __half* vh = (const __half*)&vv;
        #pragma unroll
        for (int j = 0; j < 8; j++) Vt[(c + j) * 264 + r] = vh[j];
    }
    __syncthreads();

    int g = lane >> 2, tig = lane & 3;
    int row = w * 16 + g;

    unsigned qa[4][4];
    #pragma unroll
    for (int ks = 0; ks < 4; ks++) {
        const __half* qb = Qs + row * 72 + ks * 16 + 2 * tig;
        qa[ks][0] = *(const unsigned*)qb;
        qa[ks][1] = *(const unsigned*)(qb + 8 * 72);
        qa[ks][2] = *(const unsigned*)(qb + 8);
        qa[ks][3] = *(const unsigned*)(qb + 8 * 72 + 8);
    }

    float sc[32][4];
    #pragma unroll
    for (int nf = 0; nf < 32; nf++) {
        sc[nf][0] = sc[nf][1] = sc[nf][2] = sc[nf][3] = 0.f;
        const __half* kb = Ks + (nf * 8 + g) * 72 + 2 * tig;
        #pragma unroll
        for (int ks = 0; ks < 4; ks++) {
            unsigned bb[2];
            bb[0] = *(const unsigned*)(kb + ks * 16);
            bb[1] = *(const unsigned*)(kb + ks * 16 + 8);
            mma_f16(sc[nf], qa[ks], bb);
        }
    }

    float mx0 = -1e30f, mx1 = -1e30f;
    #pragma unroll
    for (int nf = 0; nf < 32; nf++) {
        mx0 = fmaxf(mx0, fmaxf(sc[nf][0], sc[nf][1]));
        mx1 = fmaxf(mx1, fmaxf(sc[nf][2], sc[nf][3]));
    }
    mx0 = fmaxf(mx0, __shfl_xor_sync(~0u, mx0, 1));
    mx0 = fmaxf(mx0, __shfl_xor_sync(~0u, mx0, 2));
    mx1 = fmaxf(mx1, __shfl_xor_sync(~0u, mx1, 1));
    mx1 = fmaxf(mx1, __shfl_xor_sync(~0u, mx1, 2));
    float sum0 = 0.f, sum1 = 0.f;
    #pragma unroll
    for (int nf = 0; nf < 32; nf++) {
        float p0 = __expf((sc[nf][0] - mx0) * 0.125f), p1 = __expf((sc[nf][1] - mx0) * 0.125f);
        float p2 = __expf((sc[nf][2] - mx1) * 0.125f), p3 = __expf((sc[nf][3] - mx1) * 0.125f);
        sum0 += p0 + p1; sum1 += p2 + p3;
        sc[nf][0] = p0; sc[nf][1] = p1; sc[nf][2] = p2; sc[nf][3] = p3;
    }
    sum0 += __shfl_xor_sync(~0u, sum0, 1); sum0 += __shfl_xor_sync(~0u, sum0, 2);
    sum1 += __shfl_xor_sync(~0u, sum1, 1); sum1 += __shfl_xor_sync(~0u, sum1, 2);

    #pragma unroll
    for (int ksi = 0; ksi < 16; ksi++) {
        unsigned p0 = packh2(sc[2*ksi][0],   sc[2*ksi][1]);
        unsigned p1 = packh2(sc[2*ksi][2],   sc[2*ksi][3]);
        unsigned p2 = packh2(sc[2*ksi+1][0], sc[2*ksi+1][1]);
        unsigned p3 = packh2(sc[2*ksi+1][2], sc[2*ksi+1][3]);
        unsigned* d = (unsigned*)sc[2*ksi];
        d[0] = p0; d[1] = p1; d[2] = p2; d[3] = p3;
    }

    float o[8][4];
    #pragma unroll
    for (int nf = 0; nf < 8; nf++) { o[nf][0]=o[nf][1]=o[nf][2]=o[nf][3]=0.f; }
    #pragma unroll
    for (int nf = 0; nf < 8; nf++) {
        const __half* vb = Vt + (nf * 8 + g) * 264 + 2 * tig;
        #pragma unroll
        for (int ksi = 0; ksi < 16; ksi++) {
            unsigned bb[2];
            bb[0] = *(const unsigned*)(vb + ksi * 16);
            bb[1] = *(const unsigned*)(vb + ksi * 16 + 8);
            mma_f16(o[nf], (const unsigned*)sc[2*ksi], bb);
        }
    }

    float inv0 = 1.f / sum0, inv1 = 1.f / sum1;
    long orow0 = ((long)b * SS + qt * 128 + row) * DD + h * DK;
    long orow1 = orow0 + 8L * DD;
    #pragma unroll
    for (int nf = 0; nf < 8; nf++) {
        int c = nf * 8 + 2 * tig;
        *(float2*)&out[orow0 + c] = make_float2(o[nf][0] * inv0, o[nf][1] * inv0);
        *(float2*)&out[orow1 + c] = make_float2(o[nf][2] * inv1, o[nf][3] * inv1);
    }
}

// ---------------- LayerNorm over sequence + transpose -> fp16 [B,D,S] ----------------
__global__ void __launch_bounds__(256) ln_c_kernel(const float* __restrict__ xin,
                                                   const float* __restrict__ ac,
                                                   const float* __restrict__ bcv,
                                                   __half* __restrict__ xo)
{
    __shared__ float tile[32][257];
    __shared__ float red[8][32], red2[8][32];
    __shared__ float s_mean[32], s_inv[32];
    int b = blockIdx.y, d0 = blockIdx.x * 32;
    int tid = threadIdx.x, lane = tid & 31, w = tid >> 5;
    const float* base = xin + (long)b * SS * DD + d0;
    #pragma unroll 4
    for (int i = 0; i < 32; i++) {
        int s = w * 32 + i;
        tile[lane][s] = base[(long)s * DD + lane];
    }
    __syncthreads();
    {
        int d = tid & 31, ch = tid >> 5;
        float s1 = 0.f, s2 = 0.f;
        #pragma unroll
        for (int j = 0; j < 32; j++) {
            float v = tile[d][ch * 32 + j]; s1 += v; s2 += v * v;
        }
        red[ch][d] = s1; red2[ch][d] = s2;
    }
    __syncthreads();
    if (tid < 32) {
        float s1 = 0.f, s2 = 0.f;
        #pragma unroll
        for (int ch = 0; ch < 8; ch++) { s1 += red[ch][tid]; s2 += red2[ch][tid]; }
        float mean = s1 * (1.f / SS);
        float var  = (s2 - s1 * mean) * (1.f / (SS - 1));
        s_mean[tid] = mean;
        s_inv[tid]  = 1.f / (sqrtf(var) + EPSV);
    }
    __syncthreads();
    {
        int d = tid >> 3, s0 = (tid & 7) * 32;
        float mean = s_mean[d], inv = s_inv[d];
        long dstBase = ((long)b * DD + d0 + d) * SS;
        #pragma unroll
        for (int j = 0; j < 32; j += 2) {
            int s = s0 + j;
            float v0 = ac[s+0] * (tile[d][s+0] - mean) * inv + bcv[s+0];
            float v1 = ac[s+1] * (tile[d][s+1] - mean) * inv + bcv[s+1];
            *(__half2*)&xo[dstBase + s] = __floats2half2_rn(v0, v1);
        }
    }
}

// ---------------- channel attention via fp16 tensor cores (flash) ----------------
// Qs [128][40], Ks [128][40], Vt [32][136] fp16
#define CA_SMEM_BYTES ((128*40 + 128*40 + 32*136) * 2)
__global__ void __launch_bounds__(256) chan_attn_mma(const __half* __restrict__ qkvc,
                                                     __half* __restrict__ xc)
{
    extern __shared__ __half smh[];
    __half* Qs = smh;                // [128][40]
    __half* Ks = Qs + 128 * 40;
    __half* Vt = Ks + 128 * 40;      // [32][136]
    int tid = threadIdx.x, lane = tid & 31, w = tid >> 5;
    int qt = blockIdx.x, bh = blockIdx.y;
    int b = bh >> 3, h = bh & 7;
    const float scale = 0.1767766952966369f;   // 1/sqrt(32)

    const long qBase = (long)b * DD * SS + h * SK;
    const long nStride = (long)BB * DD * SS;

    for (int idx = tid; idx < 128 * 4; idx += 256) {
        int r = idx >> 2, c = (idx & 3) * 8;
        *(uint4*)&Qs[r * 40 + c] = *(const uint4*)&qkvc[qBase + (long)(qt * 128 + r) * SS + c];
    }
    __syncthreads();

    int g = lane >> 2, tig = lane & 3;
    int row = w * 16 + g;

    unsigned qa[2][4];
    #pragma unroll
    for (int ks = 0; ks < 2; ks++) {
        const __half* qb = Qs + row * 40 + ks * 16 + 2 * tig;
        qa[ks][0] = *(const unsigned*)qb;
        qa[ks][1] = *(const unsigned*)(qb + 8 * 40);
        qa[ks][2] = *(const unsigned*)(qb + 8);
        qa[ks][3] = *(const unsigned*)(qb + 8 * 40 + 8);
    }

    float m0 = -1e30f, m1 = -1e30f, l0 = 0.f, l1 = 0.f;
    float o[4][4];
    #pragma unroll
    for (int nf = 0; nf < 4; nf++) { o[nf][0]=o[nf][1]=o[nf][2]=o[nf][3]=0.f; }

    for (int st = 0; st < 8; st++) {
        __syncthreads();
        for (int idx = tid; idx < 128 * 4; idx += 256) {
            int r = idx >> 2, c = (idx & 3) * 8;
            *(uint4*)&Ks[r * 40 + c] = *(const uint4*)&qkvc[qBase + nStride + (long)(st * 128 + r) * SS + c];
            uint4 vv = *(const uint4*)&qkvc[qBase + 2 * nStride + (long)(st * 128 + r) * SS + c];
            const __half* vh = (const __half*)&vv;
            #pragma unroll
            for (int j = 0; j < 8; j++) Vt[(c + j) * 136 + r] = vh[j];
        }
        __syncthreads();

        float sc[16][4];
        #pragma unroll
        for (int nf = 0; nf < 16; nf++) {
            sc[nf][0] = sc[nf][1] = sc[nf][2] = sc[nf][3] = 0.f;
            const __half* kb = Ks + (nf * 8 + g) * 40 + 2 * tig;
            #pragma unroll
            for (int ks = 0; ks < 2; ks++) {
                unsigned bb[2];
                bb[0] = *(const unsigned*)(kb + ks * 16);
                bb[1] = *(const unsigned*)(kb + ks * 16 + 8);
                mma_f16(sc[nf], qa[ks], bb);
            }
        }
        float tm0 = -1e30f, tm1 = -1e30f;
        #pragma unroll
        for (int nf = 0; nf < 16; nf++) {
            tm0 = fmaxf(tm0, fmaxf(sc[nf][0], sc[nf][1]));
            tm1 = fmaxf(tm1, fmaxf(sc[nf][2], sc[nf][3]));
        }
        tm0 = fmaxf(tm0, __shfl_xor_sync(~0u, tm0, 1));
        tm0 = fmaxf(tm0, __shfl_xor_sync(~0u, tm0, 2));
        tm1 = fmaxf(tm1, __shfl_xor_sync(~0u, tm1, 1));
        tm1 = fmaxf(tm1, __shfl_xor_sync(~0u, tm1, 2));
        float nm0 = fmaxf(m0, tm0), nm1 = fmaxf(m1, tm1);
        float al0 = __expf((m0 - nm0) * scale), al1 = __expf((m1 - nm1) * scale);
        m0 = nm0; m1 = nm1;
        float ts0 = 0.f, ts1 = 0.f;
        #pragma unroll
        for (int nf = 0; nf < 16; nf++) {
            float p0 = __expf((sc[nf][0] - nm0) * scale), p1 = __expf((sc[nf][1] - nm0) * scale);
            float p2 = __expf((sc[nf][2] - nm1) * scale), p3 = __expf((sc[nf][3] - nm1) * scale);
            ts0 += p0 + p1; ts1 += p2 + p3;
            sc[nf][0] = p0; sc[nf][1] = p1; sc[nf][2] = p2; sc[nf][3] = p3;
        }
        ts0 += __shfl_xor_sync(~0u, ts0, 1); ts0 += __shfl_xor_sync(~0u, ts0, 2);
        ts1 += __shfl_xor_sync(~0u, ts1, 1); ts1 += __shfl_xor_sync(~0u, ts1, 2);
        l0 = l0 * al0 + ts0; l1 = l1 * al1 + ts1;
        #pragma unroll
        for (int nf = 0; nf < 4; nf++) {
            o[nf][0] *= al0; o[nf][1] *= al0;
            o[nf][2] *= al1; o[nf][3] *= al1;
        }
        #pragma unroll
        for (int ksi = 0; ksi < 8; ksi++) {
            unsigned p0 = packh2(sc[2*ksi][0],   sc[2*ksi][1]);
            unsigned p1 = packh2(sc[2*ksi][2],   sc[2*ksi][3]);
            unsigned p2 = packh2(sc[2*ksi+1][0], sc[2*ksi+1][1]);
            unsigned p3 = packh2(sc[2*ksi+1][2], sc[2*ksi+1][3]);
            unsigned* d = (unsigned*)sc[2*ksi];
            d[0] = p0; d[1] = p1; d[2] = p2; d[3] = p3;
        }
        #pragma unroll
        for (int nf = 0; nf < 4; nf++) {
            const __half* vb = Vt + (nf * 8 + g) * 136 + 2 * tig;
            #pragma unroll
            for (int ksi = 0; ksi < 8; ksi++) {
                unsigned bb[2];
                bb[0] = *(const unsigned*)(vb + ksi * 16);
                bb[1] = *(const unsigned*)(vb + ksi * 16 + 8);
                mma_f16(o[nf], (const unsigned*)sc[2*ksi], bb);
            }
        }
    }

    float inv0 = 1.f / l0, inv1 = 1.f / l1;
    long orow0 = ((long)b * DD + qt * 128 + row) * SS + h * SK;
    long orow1 = orow0 + 8L * SS;
    #pragma unroll
    for (int nf = 0; nf < 4; nf++) {
        int c = nf * 8 + 2 * tig;
        *(__half2*)&xc[orow0 + c] = __floats2half2_rn(o[nf][0] * inv0, o[nf][1] * inv0);
        *(__half2*)&xc[orow1 + c] = __floats2half2_rn(o[nf][2] * inv1, o[nf][3] * inv1);
    }
}

// ---------------- launch ----------------
extern "C" void kernel_launch(void* const* d_in, const int* in_sizes, int n_in,
                              void* d_out, int out_size)
{
    const float* x   = (const float*)d_in[0];
    const float* Wp  = (const float*)d_in[1];
    const float* bp  = (const float*)d_in[2];
    const float* Wc  = (const float*)d_in[3];
    const float* bc  = (const float*)d_in[4];
    const float* ap  = (const float*)d_in[5];
    const float* bpp = (const float*)d_in[6];
    const float* ac  = (const float*)d_in[7];
    const float* bcc = (const float*)d_in[8];
    float* out = (float*)d_out;

    void *p_xp, *p_qkv, *p_xp2, *p_xt, *p_qkvc, *p_xc;
    void *p_wph, *p_wpl, *p_wch, *p_wcl;
    cudaGetSymbolAddress(&p_xp, g_xp);
    cudaGetSymbolAddress(&p_qkv, g_qkv);
    cudaGetSymbolAddress(&p_xp2, g_xp2);
    cudaGetSymbolAddress(&p_xt, g_xt);
    cudaGetSymbolAddress(&p_qkvc, g_qkvc);
    cudaGetSymbolAddress(&p_xc, g_xc);
    cudaGetSymbolAddress(&p_wph, g_WpT_hi);
    cudaGetSymbolAddress(&p_wpl, g_WpT_lo);
    cudaGetSymbolAddress(&p_wch, g_WcT_hi);
    cudaGetSymbolAddress(&p_wcl, g_WcT_lo);
    __half* xp   = (__half*)p_xp;
    __half* qkv  = (__half*)p_qkv;
    float* xp2   = (float*)p_xp2;
    __half* xt   = (__half*)p_xt;
    __half* qkvc = (__half*)p_qkvc;
    __half* xc   = (__half*)p_xc;
    __half* WpTh = (__half*)p_wph;
    __half* WpTl = (__half*)p_wpl;
    __half* WcTh = (__half*)p_wch;
    __half* WcTl = (__half*)p_wcl;

    cudaFuncSetAttribute((const void*)pos_attn_mma,  cudaFuncAttributeMaxDynamicSharedMemorySize, PA_SMEM_BYTES);
    cudaFuncSetAttribute((const void*)chan_attn_mma, cudaFuncAttributeMaxDynamicSharedMemorySize, CA_SMEM_BYTES);
    cudaFuncSetAttribute((const void*)gemm_f16,      cudaFuncAttributeMaxDynamicSharedMemorySize, GEMM_SMEM_BYTES);

    // 0. transpose + fp16 hi/lo split of weights
    split_transpose<<<dim3(DD/32, DD/32, 3), 256>>>(Wp, WpTh, WpTl, DD, DD);
    split_transpose<<<dim3(SS/32, SS/32, 4), 256>>>(Wc, WcTh, WcTl, SS, SS);

    // 1. LayerNorm over D -> fp16
    ln_p_kernel<<<BB*SS, 256>>>(x, ap, bpp, xp);

    // 2. positional qkv (fp16x2) -> fp16 qkv
    gemm_f16<<<dim3(DD/128, (BB*SS)/128, 3), 256, GEMM_SMEM_BYTES>>>(
        xp, WpTh, WpTl, bp, (float*)qkv, DD, DD,
        0L, (long)DD*DD, (long)DD, (long)BB*SS*DD, 2);

    // 3. positional attention (fp16 tensor cores)
    pos_attn_mma<<<dim3(2, BB*HP), 256, PA_SMEM_BYTES>>>(qkv, xp2);

    // 4. LayerNorm over S + transpose -> fp16 [B,D,S]
    ln_c_kernel<<<dim3(DD/32, BB), 256>>>(xp2, ac, bcc, xt);

    // 5. channel qkv (fp16x2) -> fp16 qkvc
    gemm_f16<<<dim3(SS/128, (BB*DD)/128, 3), 256, GEMM_SMEM_BYTES>>>(
        xt, WcTh, WcTl, bc, (float*)qkvc, SS, SS,
        0L, (long)SS*SS, (long)SS, (long)BB*DD*SS, 2);

    // 6. channel attention (fp16 tensor cores, flash) -> fp16
    chan_attn_mma<<<dim3(8, BB*HC), 256, CA_SMEM_BYTES>>>(qkvc, xc);

    // 7. output projection (fp16x2) with Wc[3], bc[3]; fused transpose -> out [B,S,D]
    gemm_f16<<<dim3(SS/128, (BB*DD)/128, 1), 256, GEMM_SMEM_BYTES>>>(
        xc, WcTh + 3L*SS*SS, WcTl + 3L*SS*SS, bc + 3L*SS, out, SS, SS,
        0L, 0L, 0L, 0L, 1);
}

// round 10
// speedup vs baseline: 6.0303x; 1.2393x over previous
#include <cuda_runtime.h>
#include <cuda_fp16.h>
#include <math.h>
#include <stdint.h>

// Problem constants
#define BB 16
#define SS 256
#define DD 1024
#define HP 16
#define DK 64
#define HC 8
#define SK 32
#define EPSV 1e-6f

// ---------------- scratch buffers (static device memory; no allocation) ----------------
__device__ __half g_xp[BB*SS*DD];        // LN_p output fp16 [B,S,D]
__device__ __half g_qkv[3*BB*SS*DD];     // pos qkv fp16      [3,B,S,D]
__device__ float  g_xp2[BB*SS*DD];       // pos attn out      [B,S,D]
__device__ __half g_xt[BB*DD*SS];        // LN_c out (transposed) fp16 [B,D,S]
__device__ __half g_qkvc[3*BB*DD*SS];    // channel qkv fp16  [3,B,D,S]
__device__ __half g_xc[BB*DD*SS];        // channel attn out fp16 [B,D,S]
__device__ __half g_WpT_hi[3*DD*DD];     // Wp transposed [N][K], fp16 hi
__device__ __half g_WpT_lo[3*DD*DD];     // fp16 lo (residual)
__device__ __half g_WcT_hi[4*SS*SS];
__device__ __half g_WcT_lo[4*SS*SS];

// ---------------- helpers ----------------
__device__ __forceinline__ void cp_async16(uint32_t smem, const void* g) {
    asm volatile("cp.async.cg.shared.global [%0], [%1], 16;" :: "r"(smem), "l"(g));
}

__device__ __forceinline__ void mma_f16(float* c, const unsigned* a, const unsigned* b) {
    asm volatile("mma.sync.aligned.m16n8k16.row.col.f32.f16.f16.f32 "
        "{%0,%1,%2,%3}, {%4,%5,%6,%7}, {%8,%9}, {%0,%1,%2,%3};"
        : "+f"(c[0]), "+f"(c[1]), "+f"(c[2]), "+f"(c[3])
        : "r"(a[0]), "r"(a[1]), "r"(a[2]), "r"(a[3]), "r"(b[0]), "r"(b[1]));
}

#define LDM4(r, addr) \
    asm volatile("ldmatrix.sync.aligned.m8n8.x4.shared.b16 {%0,%1,%2,%3}, [%4];" \
        : "=r"((r)[0]), "=r"((r)[1]), "=r"((r)[2]), "=r"((r)[3]) : "r"(addr))

__device__ __forceinline__ uint32_t smem_u32(const void* p) {
    uint32_t a;
    asm("{ .reg .u64 t; cvta.to.shared.u64 t, %1; cvt.u32.u64 %0, t; }" : "=r"(a) : "l"(p));
    return a;
}

__device__ __forceinline__ unsigned packh2(float x, float y) {
    __half2 h = __floats2half2_rn(x, y);
    return *(unsigned*)&h;
}

// ---------------- weight transpose + fp16 hi/lo split ----------------
__global__ void __launch_bounds__(256) split_transpose(const float* __restrict__ W,
                                                       __half* __restrict__ hi,
                                                       __half* __restrict__ lo,
                                                       int K, int N)
{
    __shared__ float t[32][33];
    int bz = blockIdx.z;
    W  += (long)bz * K * N;
    hi += (long)bz * K * N;
    lo += (long)bz * K * N;
    int n0 = blockIdx.x * 32, k0 = blockIdx.y * 32;
    int tx = threadIdx.x & 31, ty = threadIdx.x >> 5;
    #pragma unroll
    for (int j = 0; j < 32; j += 8)
        t[ty + j][tx] = W[(long)(k0 + ty + j) * N + n0 + tx];
    __syncthreads();
    #pragma unroll
    for (int j = 0; j < 32; j += 8) {
        float v = t[tx][ty + j];
        __half h = __float2half_rn(v);
        __half l = __float2half_rn(v - __half2float(h));
        long o = (long)(n0 + ty + j) * K + k0 + tx;
        hi[o] = h; lo[o] = l;
    }
}

// ---------------- LayerNorm over channels -> fp16 ----------------
__global__ void __launch_bounds__(256) ln_p_kernel(const float* __restrict__ x,
                                                   const float* __restrict__ ap,
                                                   const float* __restrict__ bp,
                                                   __half* __restrict__ xo)
{
    long row = blockIdx.x;
    const float* xr = x + row * DD;
    int tid = threadIdx.x;
    float s = 0.f, s2 = 0.f;
    #pragma unroll
    for (int i = tid; i < DD; i += 256) { float v = xr[i]; s += v; s2 += v*v; }
    __shared__ float rs[8], rs2[8];
    #pragma unroll
    for (int o = 16; o; o >>= 1) { s += __shfl_xor_sync(~0u, s, o); s2 += __shfl_xor_sync(~0u, s2, o); }
    if ((tid & 31) == 0) { rs[tid>>5] = s; rs2[tid>>5] = s2; }
    __syncthreads();
    s = 0.f; s2 = 0.f;
    #pragma unroll
    for (int w = 0; w < 8; w++) { s += rs[w]; s2 += rs2[w]; }
    float mean = s * (1.f / DD);
    float var  = (s2 - s * mean) * (1.f / (DD - 1));
    float inv  = 1.f / (sqrtf(var) + EPSV);
    #pragma unroll
    for (int i = tid; i < DD; i += 256) {
        float v = xr[i];
        xo[row * DD + i] = __float2half_rn(ap[i] * (v - mean) * inv + bp[i]);
    }
}

// ---------------- fp16 tensor GEMM: C = A * B^T (+ Blo^T optional) + bias ----------------
// 3-stage cp.async pipeline. A [M][K] fp16, Bh/Bl [N][K] fp16 (K-major).
// BM=128 BN=128 BK=32, 256 threads. Warp grid 2(M) x 4(N), warp tile 64x32.
// smem rows stride 40 halfs. outMode: 0=fp32 C, 1=fp32 fused transpose, 2=fp16 C.
// compLo: 1 = add A*Blo^T compensation term (2 MMAs/k16), 0 = hi only (1 MMA/k16).
#define GT_TILE 10240
#define GEMM_SMEM_BYTES (9 * GT_TILE)   // 92160; transpose buffer (66048) fits

__device__ __forceinline__ void gemm_load_chunk(
    uint32_t sbase,
    const __half* __restrict__ A,
    const __half* __restrict__ Bh, const __half* __restrict__ Bl,
    long row0, int col0, int K, int k0, int buf, int tid, int compLo)
{
    uint32_t base = sbase + buf * 3 * GT_TILE;
    #pragma unroll
    for (int i = 0; i < 2; i++) {
        int idx = tid + i * 256;
        int r = idx >> 2, sgi = idx & 3;
        uint32_t d = base + (uint32_t)(r * 80 + sgi * 16);
        long aoff = (row0 + r) * (long)K + k0 + sgi * 8;
        long boff = (long)(col0 + r) * K + k0 + sgi * 8;
        cp_async16(d,               &A[aoff]);
        cp_async16(d + GT_TILE,     &Bh[boff]);
        if (compLo) cp_async16(d + 2*GT_TILE, &Bl[boff]);
    }
    asm volatile("cp.async.commit_group;");
}

__global__ void __launch_bounds__(256, 2) gemm_f16(const __half* __restrict__ A,
                                                   const __half* __restrict__ Bh,
                                                   const __half* __restrict__ Bl,
                                                   const float* __restrict__ bias,
                                                   float* __restrict__ C,
                                                   int K, int Ntot,
                                                   long aB, long bB, long biasB, long cB,
                                                   int outMode, int compLo)
{
    extern __shared__ char smem[];
    uint32_t sbase = smem_u32(smem);
    int tid  = threadIdx.x;
    int warp = tid >> 5, lane = tid & 31;
    int wm = warp & 1, wn = warp >> 1;        // 2 x 4 warp grid, tile 64M x 32N
    int g = lane >> 2, t = lane & 3;
    int bz = blockIdx.z;
    A    += (long)bz * aB;
    Bh   += (long)bz * bB;
    Bl   += (long)bz * bB;
    bias += (long)bz * biasB;
    long row0 = (long)blockIdx.y * 128;
    int  col0 = blockIdx.x * 128;

    uint32_t aAddr = sbase +
        (uint32_t)(((wm * 64 + (lane & 7) + ((lane >> 3) & 1) * 8) * 40 + (lane >> 4) * 8) * 2);
    uint32_t bAddr = sbase + GT_TILE +
        (uint32_t)(((wn * 32 + (lane & 7) + ((lane >> 4) & 1) * 8) * 40 + ((lane >> 3) & 1) * 8) * 2);

    float acc[4][4][4];
    #pragma unroll
    for (int mi = 0; mi < 4; mi++)
        #pragma unroll
        for (int ni = 0; ni < 4; ni++)
            #pragma unroll
            for (int r = 0; r < 4; r++) acc[mi][ni][r] = 0.f;

    int NC = K >> 5;
    gemm_load_chunk(sbase, A, Bh, Bl, row0, col0, K, 0, 0, tid, compLo);
    if (NC > 1) gemm_load_chunk(sbase, A, Bh, Bl, row0, col0, K, 32, 1, tid, compLo);

    for (int c = 0; c < NC; c++) {
        int buf = c % 3;
        if (c + 1 < NC) {
            asm volatile("cp.async.wait_group 1;" ::: "memory");
        } else {
            asm volatile("cp.async.wait_group 0;" ::: "memory");
        }
        __syncthreads();
        if (c + 2 < NC)
            gemm_load_chunk(sbase, A, Bh, Bl, row0, col0, K, (c + 2) << 5, (c + 2) % 3, tid, compLo);

        uint32_t bo = buf * 3 * GT_TILE;
        #pragma unroll
        for (int ks = 0; ks < 2; ks++) {
            uint32_t ak = aAddr + bo + ks * 32;
            uint32_t bk = bAddr + bo + ks * 32;
            unsigned af[4][4];
            LDM4(af[0], ak);
            LDM4(af[1], ak + 1280);
            LDM4(af[2], ak + 2560);
            LDM4(af[3], ak + 3840);
            unsigned bhf[2][4];
            LDM4(bhf[0], bk);
            LDM4(bhf[1], bk + 1280);
            #pragma unroll
            for (int mi = 0; mi < 4; mi++)
                #pragma unroll
                for (int ni = 0; ni < 4; ni++)
                    mma_f16(acc[mi][ni], af[mi], &bhf[ni >> 1][(ni & 1) * 2]);
            if (compLo) {
                unsigned blf[2][4];
                LDM4(blf[0], bk + GT_TILE);
                LDM4(blf[1], bk + GT_TILE + 1280);
                #pragma unroll
                for (int mi = 0; mi < 4; mi++)
                    #pragma unroll
                    for (int ni = 0; ni < 4; ni++)
                        mma_f16(acc[mi][ni], af[mi], &blf[ni >> 1][(ni & 1) * 2]);
            }
        }
    }

    if (outMode == 0) {
        float* Cf = C + (long)bz * cB;
        #pragma unroll
        for (int mi = 0; mi < 4; mi++) {
            #pragma unroll
            for (int ni = 0; ni < 4; ni++) {
                long r = row0 + wm * 64 + mi * 16 + g;
                int  cc = col0 + wn * 32 + ni * 8 + 2 * t;
                float b0 = bias[cc], b1 = bias[cc + 1];
                *(float2*)&Cf[r * Ntot + cc]       = make_float2(acc[mi][ni][0] + b0, acc[mi][ni][1] + b1);
                *(float2*)&Cf[(r + 8) * Ntot + cc] = make_float2(acc[mi][ni][2] + b0, acc[mi][ni][3] + b1);
            }
        }
    } else if (outMode == 2) {
        __half* Ch = (__half*)C + (long)bz * cB;
        #pragma unroll
        for (int mi = 0; mi < 4; mi++) {
            #pragma unroll
            for (int ni = 0; ni < 4; ni++) {
                long r = row0 + wm * 64 + mi * 16 + g;
                int  cc = col0 + wn * 32 + ni * 8 + 2 * t;
                float b0 = bias[cc], b1 = bias[cc + 1];
                *(__half2*)&Ch[r * Ntot + cc]       = __floats2half2_rn(acc[mi][ni][0] + b0, acc[mi][ni][1] + b1);
                *(__half2*)&Ch[(r + 8) * Ntot + cc] = __floats2half2_rn(acc[mi][ni][2] + b0, acc[mi][ni][3] + b1);
            }
        }
    } else {
        // stage to smem [s][d] then write out[b][s][d] coalesced
        __syncthreads();
        float* Ts = (float*)smem;
        int b = (int)(row0 >> 10), d0 = (int)(row0 & 1023);
        #pragma unroll
        for (int mi = 0; mi < 4; mi++) {
            #pragma unroll
            for (int ni = 0; ni < 4; ni++) {
                int rl = wm * 64 + mi * 16 + g;
                int cl = wn * 32 + ni * 8 + 2 * t;
                float b0 = bias[col0 + cl], b1 = bias[col0 + cl + 1];
                Ts[cl * 129 + rl]           = acc[mi][ni][0] + b0;
                Ts[(cl + 1) * 129 + rl]     = acc[mi][ni][1] + b1;
                Ts[cl * 129 + rl + 8]       = acc[mi][ni][2] + b0;
                Ts[(cl + 1) * 129 + rl + 8] = acc[mi][ni][3] + b1;
            }
        }
        __syncthreads();
        #pragma unroll
        for (int j = 0; j < 16; j++) {
            int sl = j * 8 + (tid >> 5);
            int d4 = (tid & 31) * 4;
            float4 o = make_float4(Ts[sl * 129 + d4], Ts[sl * 129 + d4 + 1],
                                   Ts[sl * 129 + d4 + 2], Ts[sl * 129 + d4 + 3]);
            *(float4*)&C[((long)(b * SS + col0 + sl)) * DD + d0 + d4] = o;
        }
    }
}

// ---------------- positional attention via fp16 tensor cores ----------------
// Qs [128][72] fp16, Ks [256][72] fp16, Vt [64][264] fp16 (V transposed)
#define PA_SMEM_BYTES ((128*72 + 256*72 + 64*264) * 2)
__global__ void __launch_bounds__(256) pos_attn_mma(const __half* __restrict__ qkv,
                                                    float* __restrict__ out)
{
    extern __shared__ __half smh[];
    __half* Qs = smh;                 // [128][72]
    __half* Ks = Qs + 128 * 72;       // [256][72]
    __half* Vt = Ks + 256 * 72;       // [64][264]
    int tid = threadIdx.x, lane = tid & 31, w = tid >> 5;
    int qt = blockIdx.x, bh = blockIdx.y;
    int b = bh >> 4, h = bh & 15;

    const __half* Qg = qkv + ((long)b * SS + qt * 128) * DD + h * DK;
    const __half* Kg = qkv + (long)BB*SS*DD + (long)b * SS * DD + h * DK;
    const __half* Vg = Kg + (long)BB*SS*DD;

    for (int idx = tid; idx < 128 * 8; idx += 256) {
        int r = idx >> 3, c = (idx & 7) * 8;
        *(uint4*)&Qs[r * 72 + c] = *(const uint4*)&Qg[(long)r * DD + c];
    }
    for (int idx = tid; idx < 256 * 8; idx += 256) {
        int r = idx >> 3, c = (idx & 7) * 8;
        *(uint4*)&Ks[r * 72 + c] = *(const uint4*)&Kg[(long)r * DD + c];
        uint4 vv = *(const uint4*)&Vg[(long)r * DD + c];
        const __half* vh = (const __half*)&vv;
        #pragma unroll
        for (int j = 0; j < 8; j++) Vt[(c + j) * 264 + r] = vh[j];
    }
    __syncthreads();

    int g = lane >> 2, tig = lane & 3;
    int row = w * 16 + g;

    unsigned qa[4][4];
    #pragma unroll
    for (int ks = 0; ks < 4; ks++) {
        const __half* qb = Qs + row * 72 + ks * 16 + 2 * tig;
        qa[ks][0] = *(const unsigned*)qb;
        qa[ks][1] = *(const unsigned*)(qb + 8 * 72);
        qa[ks][2] = *(const unsigned*)(qb + 8);
        qa[ks][3] = *(const unsigned*)(qb + 8 * 72 + 8);
    }

    float sc[32][4];
    #pragma unroll
    for (int nf = 0; nf < 32; nf++) {
        sc[nf][0] = sc[nf][1] = sc[nf][2] = sc[nf][3] = 0.f;
        const __half* kb = Ks + (nf * 8 + g) * 72 + 2 * tig;
        #pragma unroll
        for (int ks = 0; ks < 4; ks++) {
            unsigned bb[2];
            bb[0] = *(const unsigned*)(kb + ks * 16);
            bb[1] = *(const unsigned*)(kb + ks * 16 + 8);
            mma_f16(sc[nf], qa[ks], bb);
        }
    }

    float mx0 = -1e30f, mx1 = -1e30f;
    #pragma unroll
    for (int nf = 0; nf < 32; nf++) {
        mx0 = fmaxf(mx0, fmaxf(sc[nf][0], sc[nf][1]));
        mx1 = fmaxf(mx1, fmaxf(sc[nf][2], sc[nf][3]));
    }
    mx0 = fmaxf(mx0, __shfl_xor_sync(~0u, mx0, 1));
    mx0 = fmaxf(mx0, __shfl_xor_sync(~0u, mx0, 2));
    mx1 = fmaxf(mx1, __shfl_xor_sync(~0u, mx1, 1));
    mx1 = fmaxf(mx1, __shfl_xor_sync(~0u, mx1, 2));
    float sum0 = 0.f, sum1 = 0.f;
    #pragma unroll
    for (int nf = 0; nf < 32; nf++) {
        float p0 = __expf((sc[nf][0] - mx0) * 0.125f), p1 = __expf((sc[nf][1] - mx0) * 0.125f);
        float p2 = __expf((sc[nf][2] - mx1) * 0.125f), p3 = __expf((sc[nf][3] - mx1) * 0.125f);
        sum0 += p0 + p1; sum1 += p2 + p3;
        sc[nf][0] = p0; sc[nf][1] = p1; sc[nf][2] = p2; sc[nf][3] = p3;
    }
    sum0 += __shfl_xor_sync(~0u, sum0, 1); sum0 += __shfl_xor_sync(~0u, sum0, 2);
    sum1 += __shfl_xor_sync(~0u, sum1, 1); sum1 += __shfl_xor_sync(~0u, sum1, 2);

    #pragma unroll
    for (int ksi = 0; ksi < 16; ksi++) {
        unsigned p0 = packh2(sc[2*ksi][0],   sc[2*ksi][1]);
        unsigned p1 = packh2(sc[2*ksi][2],   sc[2*ksi][3]);
        unsigned p2 = packh2(sc[2*ksi+1][0], sc[2*ksi+1][1]);
        unsigned p3 = packh2(sc[2*ksi+1][2], sc[2*ksi+1][3]);
        unsigned* d = (unsigned*)sc[2*ksi];
        d[0] = p0; d[1] = p1; d[2] = p2; d[3] = p3;
    }

    float o[8][4];
    #pragma unroll
    for (int nf = 0; nf < 8; nf++) { o[nf][0]=o[nf][1]=o[nf][2]=o[nf][3]=0.f; }
    #pragma unroll
    for (int nf = 0; nf < 8; nf++) {
        const __half* vb = Vt + (nf * 8 + g) * 264 + 2 * tig;
        #pragma unroll
        for (int ksi = 0; ksi < 16; ksi++) {
            unsigned bb[2];
            bb[0] = *(const unsigned*)(vb + ksi * 16);
            bb[1] = *(const unsigned*)(vb + ksi * 16 + 8);
            mma_f16(o[nf], (const unsigned*)sc[2*ksi], bb);
        }
    }

    float inv0 = 1.f / sum0, inv1 = 1.f / sum1;
    long orow0 = ((long)b * SS + qt * 128 + row) * DD + h * DK;
    long orow1 = orow0 + 8L * DD;
    #pragma unroll
    for (int nf = 0; nf < 8; nf++) {
        int c = nf * 8 + 2 * tig;
        *(float2*)&out[orow0 + c] = make_float2(o[nf][0] * inv0, o[nf][1] * inv0);
        *(float2*)&out[orow1 + c] = make_float2(o[nf][2] * inv1, o[nf][3] * inv1);
    }
}

// ---------------- LayerNorm over sequence + transpose -> fp16 [B,D,S] ----------------
__global__ void __launch_bounds__(256) ln_c_kernel(const float* __restrict__ xin,
                                                   const float* __restrict__ ac,
                                                   const float* __restrict__ bcv,
                                                   __half* __restrict__ xo)
{
    __shared__ float tile[32][257];
    __shared__ float red[8][32], red2[8][32];
    __shared__ float s_mean[32], s_inv[32];
    int b = blockIdx.y, d0 = blockIdx.x * 32;
    int tid = threadIdx.x, lane = tid & 31, w = tid >> 5;
    const float* base = xin + (long)b * SS * DD + d0;
    #pragma unroll 4
    for (int i = 0; i < 32; i++) {
        int s = w * 32 + i;
        tile[lane][s] = base[(long)s * DD + lane];
    }
    __syncthreads();
    {
        int d = tid & 31, ch = tid >> 5;
        float s1 = 0.f, s2 = 0.f;
        #pragma unroll
        for (int j = 0; j < 32; j++) {
            float v = tile[d][ch * 32 + j]; s1 += v; s2 += v * v;
        }
        red[ch][d] = s1; red2[ch][d] = s2;
    }
    __syncthreads();
    if (tid < 32) {
        float s1 = 0.f, s2 = 0.f;
        #pragma unroll
        for (int ch = 0; ch < 8; ch++) { s1 += red[ch][tid]; s2 += red2[ch][tid]; }
        float mean = s1 * (1.f / SS);
        float var  = (s2 - s1 * mean) * (1.f / (SS - 1));
        s_mean[tid] = mean;
        s_inv[tid]  = 1.f / (sqrtf(var) + EPSV);
    }
    __syncthreads();
    {
        int d = tid >> 3, s0 = (tid & 7) * 32;
        float mean = s_mean[d], inv = s_inv[d];
        long dstBase = ((long)b * DD + d0 + d) * SS;
        #pragma unroll
        for (int j = 0; j < 32; j += 2) {
            int s = s0 + j;
            float v0 = ac[s+0] * (tile[d][s+0] - mean) * inv + bcv[s+0];
            float v1 = ac[s+1] * (tile[d][s+1] - mean) * inv + bcv[s+1];
            *(__half2*)&xo[dstBase + s] = __floats2half2_rn(v0, v1);
        }
    }
}

// ---------------- channel attention via fp16 tensor cores (flash) ----------------
// Qs [128][40], Ks [128][40], Vt [32][136] fp16
#define CA_SMEM_BYTES ((128*40 + 128*40 + 32*136) * 2)
__global__ void __launch_bounds__(256) chan_attn_mma(const __half* __restrict__ qkvc,
                                                     __half* __restrict__ xc)
{
    extern __shared__ __half smh[];
    __half* Qs = smh;                // [128][40]
    __half* Ks = Qs + 128 * 40;
    __half* Vt = Ks + 128 * 40;      // [32][136]
    int tid = threadIdx.x, lane = tid & 31, w = tid >> 5;
    int qt = blockIdx.x, bh = blockIdx.y;
    int b = bh >> 3, h = bh & 7;
    const float scale = 0.1767766952966369f;   // 1/sqrt(32)

    const long qBase = (long)b * DD * SS + h * SK;
    const long nStride = (long)BB * DD * SS;

    for (int idx = tid; idx < 128 * 4; idx += 256) {
        int r = idx >> 2, c = (idx & 3) * 8;
        *(uint4*)&Qs[r * 40 + c] = *(const uint4*)&qkvc[qBase + (long)(qt * 128 + r) * SS + c];
    }
    __syncthreads();

    int g = lane >> 2, tig = lane & 3;
    int row = w * 16 + g;

    unsigned qa[2][4];
    #pragma unroll
    for (int ks = 0; ks < 2; ks++) {
        const __half* qb = Qs + row * 40 + ks * 16 + 2 * tig;
        qa[ks][0] = *(const unsigned*)qb;
        qa[ks][1] = *(const unsigned*)(qb + 8 * 40);
        qa[ks][2] = *(const unsigned*)(qb + 8);
        qa[ks][3] = *(const unsigned*)(qb + 8 * 40 + 8);
    }

    float m0 = -1e30f, m1 = -1e30f, l0 = 0.f, l1 = 0.f;
    float o[4][4];
    #pragma unroll
    for (int nf = 0; nf < 4; nf++) { o[nf][0]=o[nf][1]=o[nf][2]=o[nf][3]=0.f; }

    for (int st = 0; st < 8; st++) {
        __syncthreads();
        for (int idx = tid; idx < 128 * 4; idx += 256) {
            int r = idx >> 2, c = (idx & 3) * 8;
            *(uint4*)&Ks[r * 40 + c] = *(const uint4*)&qkvc[qBase + nStride + (long)(st * 128 + r) * SS + c];
            uint4 vv = *(const uint4*)&qkvc[qBase + 2 * nStride + (long)(st * 128 + r) * SS + c];
            const __half* vh = (const __half*)&vv;
            #pragma unroll
            for (int j = 0; j < 8; j++) Vt[(c + j) * 136 + r] = vh[j];
        }
        __syncthreads();

        float sc[16][4];
        #pragma unroll
        for (int nf = 0; nf < 16; nf++) {
            sc[nf][0] = sc[nf][1] = sc[nf][2] = sc[nf][3] = 0.f;
            const __half* kb = Ks + (nf * 8 + g) * 40 + 2 * tig;
            #pragma unroll
            for (int ks = 0; ks < 2; ks++) {
                unsigned bb[2];
                bb[0] = *(const unsigned*)(kb + ks * 16);
                bb[1] = *(const unsigned*)(kb + ks * 16 + 8);
                mma_f16(sc[nf], qa[ks], bb);
            }
        }
        float tm0 = -1e30f, tm1 = -1e30f;
        #pragma unroll
        for (int nf = 0; nf < 16; nf++) {
            tm0 = fmaxf(tm0, fmaxf(sc[nf][0], sc[nf][1]));
            tm1 = fmaxf(tm1, fmaxf(sc[nf][2], sc[nf][3]));
        }
        tm0 = fmaxf(tm0, __shfl_xor_sync(~0u, tm0, 1));
        tm0 = fmaxf(tm0, __shfl_xor_sync(~0u, tm0, 2));
        tm1 = fmaxf(tm1, __shfl_xor_sync(~0u, tm1, 1));
        tm1 = fmaxf(tm1, __shfl_xor_sync(~0u, tm1, 2));
        float nm0 = fmaxf(m0, tm0), nm1 = fmaxf(m1, tm1);
        float al0 = __expf((m0 - nm0) * scale), al1 = __expf((m1 - nm1) * scale);
        m0 = nm0; m1 = nm1;
        float ts0 = 0.f, ts1 = 0.f;
        #pragma unroll
        for (int nf = 0; nf < 16; nf++) {
            float p0 = __expf((sc[nf][0] - nm0) * scale), p1 = __expf((sc[nf][1] - nm0) * scale);
            float p2 = __expf((sc[nf][2] - nm1) * scale), p3 = __expf((sc[nf][3] - nm1) * scale);
            ts0 += p0 + p1; ts1 += p2 + p3;
            sc[nf][0] = p0; sc[nf][1] = p1; sc[nf][2] = p2; sc[nf][3] = p3;
        }
        ts0 += __shfl_xor_sync(~0u, ts0, 1); ts0 += __shfl_xor_sync(~0u, ts0, 2);
        ts1 += __shfl_xor_sync(~0u, ts1, 1); ts1 += __shfl_xor_sync(~0u, ts1, 2);
        l0 = l0 * al0 + ts0; l1 = l1 * al1 + ts1;
        #pragma unroll
        for (int nf = 0; nf < 4; nf++) {
            o[nf][0] *= al0; o[nf][1] *= al0;
            o[nf][2] *= al1; o[nf][3] *= al1;
        }
        #pragma unroll
        for (int ksi = 0; ksi < 8; ksi++) {
            unsigned p0 = packh2(sc[2*ksi][0],   sc[2*ksi][1]);
            unsigned p1 = packh2(sc[2*ksi][2],   sc[2*ksi][3]);
            unsigned p2 = packh2(sc[2*ksi+1][0], sc[2*ksi+1][1]);
            unsigned p3 = packh2(sc[2*ksi+1][2], sc[2*ksi+1][3]);
            unsigned* d = (unsigned*)sc[2*ksi];
            d[0] = p0; d[1] = p1; d[2] = p2; d[3] = p3;
        }
        #pragma unroll
        for (int nf = 0; nf < 4; nf++) {
            const __half* vb = Vt + (nf * 8 + g) * 136 + 2 * tig;
            #pragma unroll
            for (int ksi = 0; ksi < 8; ksi++) {
                unsigned bb[2];
                bb[0] = *(const unsigned*)(vb + ksi * 16);
                bb[1] = *(const unsigned*)(vb + ksi * 16 + 8);
                mma_f16(o[nf], (const unsigned*)sc[2*ksi], bb);
            }
        }
    }

    float inv0 = 1.f / l0, inv1 = 1.f / l1;
    long orow0 = ((long)b * DD + qt * 128 + row) * SS + h * SK;
    long orow1 = orow0 + 8L * SS;
    #pragma unroll
    for (int nf = 0; nf < 4; nf++) {
        int c = nf * 8 + 2 * tig;
        *(__half2*)&xc[orow0 + c] = __floats2half2_rn(o[nf][0] * inv0, o[nf][1] * inv0);
        *(__half2*)&xc[orow1 + c] = __floats2half2_rn(o[nf][2] * inv1, o[nf][3] * inv1);
    }
}

// ---------------- launch ----------------
extern "C" void kernel_launch(void* const* d_in, const int* in_sizes, int n_in,
                              void* d_out, int out_size)
{
    const float* x   = (const float*)d_in[0];
    const float* Wp  = (const float*)d_in[1];
    const float* bp  = (const float*)d_in[2];
    const float* Wc  = (const float*)d_in[3];
    const float* bc  = (const float*)d_in[4];
    const float* ap  = (const float*)d_in[5];
    const float* bpp = (const float*)d_in[6];
    const float* ac  = (const float*)d_in[7];
    const float* bcc = (const float*)d_in[8];
    float* out = (float*)d_out;

    void *p_xp, *p_qkv, *p_xp2, *p_xt, *p_qkvc, *p_xc;
    void *p_wph, *p_wpl, *p_wch, *p_wcl;
    cudaGetSymbolAddress(&p_xp, g_xp);
    cudaGetSymbolAddress(&p_qkv, g_qkv);
    cudaGetSymbolAddress(&p_xp2, g_xp2);
    cudaGetSymbolAddress(&p_xt, g_xt);
    cudaGetSymbolAddress(&p_qkvc, g_qkvc);
    cudaGetSymbolAddress(&p_xc, g_xc);
    cudaGetSymbolAddress(&p_wph, g_WpT_hi);
    cudaGetSymbolAddress(&p_wpl, g_WpT_lo);
    cudaGetSymbolAddress(&p_wch, g_WcT_hi);
    cudaGetSymbolAddress(&p_wcl, g_WcT_lo);
    __half* xp   = (__half*)p_xp;
    __half* qkv  = (__half*)p_qkv;
    float* xp2   = (float*)p_xp2;
    __half* xt   = (__half*)p_xt;
    __half* qkvc = (__half*)p_qkvc;
    __half* xc   = (__half*)p_xc;
    __half* WpTh = (__half*)p_wph;
    __half* WpTl = (__half*)p_wpl;
    __half* WcTh = (__half*)p_wch;
    __half* WcTl = (__half*)p_wcl;

    cudaFuncSetAttribute((const void*)pos_attn_mma,  cudaFuncAttributeMaxDynamicSharedMemorySize, PA_SMEM_BYTES);
    cudaFuncSetAttribute((const void*)chan_attn_mma, cudaFuncAttributeMaxDynamicSharedMemorySize, CA_SMEM_BYTES);
    cudaFuncSetAttribute((const void*)gemm_f16,      cudaFuncAttributeMaxDynamicSharedMemorySize, GEMM_SMEM_BYTES);

    // 0. transpose + fp16 hi/lo split of weights
    split_transpose<<<dim3(DD/32, DD/32, 3), 256>>>(Wp, WpTh, WpTl, DD, DD);
    split_transpose<<<dim3(SS/32, SS/32, 4), 256>>>(Wc, WcTh, WcTl, SS, SS);

    // 1. LayerNorm over D -> fp16
    ln_p_kernel<<<BB*SS, 256>>>(x, ap, bpp, xp);

    // 2. positional qkv (fp16, hi-only weights) -> fp16 qkv
    gemm_f16<<<dim3(DD/128, (BB*SS)/128, 3), 256, GEMM_SMEM_BYTES>>>(
        xp, WpTh, WpTl, bp, (float*)qkv, DD, DD,
        0L, (long)DD*DD, (long)DD, (long)BB*SS*DD, 2, 0);

    // 3. positional attention (fp16 tensor cores)
    pos_attn_mma<<<dim3(2, BB*HP), 256, PA_SMEM_BYTES>>>(qkv, xp2);

    // 4. LayerNorm over S + transpose -> fp16 [B,D,S]
    ln_c_kernel<<<dim3(DD/32, BB), 256>>>(xp2, ac, bcc, xt);

    // 5. channel qkv (fp16, hi-only weights) -> fp16 qkvc
    gemm_f16<<<dim3(SS/128, (BB*DD)/128, 3), 256, GEMM_SMEM_BYTES>>>(
        xt, WcTh, WcTl, bc, (float*)qkvc, SS, SS,
        0L, (long)SS*SS, (long)SS, (long)BB*DD*SS, 2, 0);

    // 6. channel attention (fp16 tensor cores, flash) -> fp16
    chan_attn_mma<<<dim3(8, BB*HC), 256, CA_SMEM_BYTES>>>(qkvc, xc);

    // 7. output projection (fp16 hi+lo compensated) with Wc[3], bc[3]; fused transpose -> out
    gemm_f16<<<dim3(SS/128, (BB*DD)/128, 1), 256, GEMM_SMEM_BYTES>>>(
        xc, WcTh + 3L*SS*SS, WcTl + 3L*SS*SS, bc + 3L*SS, out, SS, SS,
        0L, 0L, 0L, 0L, 1, 1);
}